// round 10
// baseline (speedup 1.0000x reference)
#include <cuda_runtime.h>
#include <cuda_bf16.h>
#include <math.h>
#include <stdint.h>

// ---------------------------------------------------------------------------
// HGT forward. GEMMs via mma.sync bf16 (hi/lo 3-term = fp32-class accuracy).
// R10: fused fp32->bf16 hi/lo A-loader in GEMM (split_hilo kernels removed).
// ---------------------------------------------------------------------------
#define NA     20000
#define NP     40000
#define D      256
#define DOUT   64
#define LL     2
#define E_WB   150000
#define E_W    150000
#define E_C    300000
#define NSLOT  23
// paper proj row: [0,256)=q | [256,512)=k_wb | [512,768)=k_c | [768,1024)=m_wb | [1024,1280)=m_c
#define PSTR   1280
// author proj row: [0,256)=q | [256,512)=k_w | [512,768)=m_w
#define ASTR   768

// ------------------------- device scratch ----------------------------------
__device__ float g_feats_a[2][NA * D];
__device__ float g_feats_p[2][NP * D];
__device__ float g_proj_a[NA * ASTR];
__device__ float g_proj_p[NP * PSTR];
__device__ float g_agg_a[NA * D];
__device__ float g_agg_p[NP * D];
__device__ float g_tr_a[NA * D];
__device__ float g_tr_p[NP * D];
__device__ float g_Wk[LL * 3 * D * D];
__device__ float g_bk[LL * 3 * D];
__device__ float g_Wm[LL * 3 * D * D];
__device__ float g_bm[LL * 3 * D];
__device__ float g_bias_p[LL * PSTR];
__device__ float g_bias_a[LL * ASTR];
// bf16 hi/lo operands (feats only; inputs/agg consumed fp32 by A32 GEMMs)
__device__ __nv_bfloat16 g_fa_hi[NA * D], g_fa_lo[NA * D];
__device__ __nv_bfloat16 g_fp_hi[NP * D], g_fp_lo[NP * D];
__device__ __nv_bfloat16 g_Whi[NSLOT * D * D], g_Wlo[NSLOT * D * D];

// ------------------------- small helpers -----------------------------------
__device__ __forceinline__ uint32_t smem_u32(const void* p) {
    uint32_t a;
    asm("{ .reg .u64 t; cvta.to.shared.u64 t, %1; cvt.u32.u64 %0, t; }" : "=r"(a) : "l"(p));
    return a;
}
#define SWZ(off) ((off) ^ (((off) >> 3) & 0x70))

#define CPASYNC16(dst, src) \
    asm volatile("cp.async.cg.shared.global [%0], [%1], 16;" :: "r"(dst), "l"(src) : "memory")

#define LDSM_X4(r0, r1, r2, r3, addr)                                         \
    asm volatile("ldmatrix.sync.aligned.m8n8.x4.shared.b16 {%0,%1,%2,%3}, [%4];" \
                 : "=r"(r0), "=r"(r1), "=r"(r2), "=r"(r3) : "r"(addr))

#define MMA16816(d, a, b0, b1)                                                \
    asm volatile("mma.sync.aligned.m16n8k16.row.col.f32.bf16.bf16.f32 "       \
                 "{%0,%1,%2,%3}, {%4,%5,%6,%7}, {%8,%9}, {%0,%1,%2,%3};"      \
                 : "+f"((d)[0]), "+f"((d)[1]), "+f"((d)[2]), "+f"((d)[3])     \
                 : "r"((a)[0]), "r"((a)[1]), "r"((a)[2]), "r"((a)[3]),        \
                   "r"(b0), "r"(b1))

#define STS64(addr, lo32, hi32) \
    asm volatile("st.shared.v2.u32 [%0], {%1,%2};" :: "r"(addr), "r"(lo32), "r"(hi32) : "memory")

__device__ __forceinline__ float gelu_exact(float x) {
    return 0.5f * x * (1.0f + erff(x * 0.70710678118654752f));
}

// ---------------------------------------------------------------------------
// combine per-head w_att/w_msg into dense K/M projection weights (fp32).
// ---------------------------------------------------------------------------
__global__ void combine_weights(const float* __restrict__ kW, const float* __restrict__ kb,
                                const float* __restrict__ mW, const float* __restrict__ mb,
                                const float* __restrict__ w_att, const float* __restrict__ w_msg,
                                float* __restrict__ Wk, float* __restrict__ bk,
                                float* __restrict__ Wm, float* __restrict__ bm)
{
    int mat = blockIdx.x;
    int l = mat / 6;
    int r6 = mat % 6;
    int e = r6 / 2;
    int which = r6 % 2;
    int d = blockIdx.y;        // 0..256 (256 == bias row)
    int j = threadIdx.x;
    int h = j >> 6;
    int jj = j & 63;
    int st = (e == 1) ? 0 : 1;

    const float* W   = which ? mW : kW;
    const float* B   = which ? mb : kb;
    const float* att = which ? w_msg : w_att;

    const float* wrow;
    if (d < 256) wrow = W + (((size_t)(l * 2 + st) * 256 + d) * 256);
    else         wrow = B + ((size_t)(l * 2 + st) * 256);
    const float* a = att + ((size_t)((l * 3 + e) * 4 + h)) * 64 * 64;

    float s = 0.f;
#pragma unroll 8
    for (int c = 0; c < 64; c++)
        s += wrow[h * 64 + c] * a[c * 64 + jj];

    float* out  = which ? Wm : Wk;
    float* outb = which ? bm : bk;
    if (d < 256) out[((size_t)(l * 3 + e) * 256 + d) * 256 + j] = s;
    else         outb[(size_t)(l * 3 + e) * 256 + j] = s;
}

// ---------------------------------------------------------------------------
// Transpose + split all weight matrices into bf16 hi/lo, K-major [n][k].
// Slot order: 0,1 adapt | 2+l*8+{0..7}: q_p,k_wb,k_c,m_wb,m_c,q_a,k_w,m_w
//             | 18+l*2+nt aW | 22 out_W
// ---------------------------------------------------------------------------
__global__ void transpose_split(const float* __restrict__ adapt_W, const float* __restrict__ qW,
                                const float* __restrict__ Wk, const float* __restrict__ Wm,
                                const float* __restrict__ aW, const float* __restrict__ outW,
                                __nv_bfloat16* __restrict__ Whi, __nv_bfloat16* __restrict__ Wlo)
{
    int slot = blockIdx.z;
    const float* src; int NC = 256;
    if (slot < 2)        src = adapt_W + (size_t)slot * 65536;
    else if (slot < 18) {
        int l = (slot - 2) / 8, o = (slot - 2) % 8;
        switch (o) {
            case 0: src = qW + (size_t)(l * 2 + 1) * 65536; break;
            case 1: src = Wk + (size_t)(l * 3 + 2) * 65536; break;
            case 2: src = Wk + (size_t)(l * 3 + 0) * 65536; break;
            case 3: src = Wm + (size_t)(l * 3 + 2) * 65536; break;
            case 4: src = Wm + (size_t)(l * 3 + 0) * 65536; break;
            case 5: src = qW + (size_t)(l * 2 + 0) * 65536; break;
            case 6: src = Wk + (size_t)(l * 3 + 1) * 65536; break;
            default: src = Wm + (size_t)(l * 3 + 1) * 65536; break;
        }
    }
    else if (slot < 22)  src = aW + (size_t)(slot - 18) * 65536;
    else               { src = outW; NC = 64; }

    int k0 = blockIdx.x * 32, n0 = blockIdx.y * 32;
    if (n0 >= NC) return;
    int tx = threadIdx.x, ty = threadIdx.y;

    __shared__ float t[32][33];
#pragma unroll
    for (int i = 0; i < 4; i++) {
        int k = k0 + ty + i * 8;
        t[ty + i * 8][tx] = src[(size_t)k * NC + n0 + tx];
    }
    __syncthreads();
#pragma unroll
    for (int i = 0; i < 4; i++) {
        int n = n0 + ty + i * 8, k = k0 + tx;
        float v = t[tx][ty + i * 8];
        __nv_bfloat16 h = __float2bfloat16(v);
        float r = v - __bfloat162float(h);
        size_t o = (size_t)slot * 65536 + (size_t)n * 256 + k;
        Whi[o] = h;
        Wlo[o] = __float2bfloat16(r);
    }
}

// ---------------------------------------------------------------------------
// Pack per-layer projection biases into the batched column layout.
// ---------------------------------------------------------------------------
__global__ void pack_bias(const float* __restrict__ qb, const float* __restrict__ bk,
                          const float* __restrict__ bm,
                          float* __restrict__ bp, float* __restrict__ ba)
{
    int idx = blockIdx.x * 256 + threadIdx.x;    // 2 * 2048
    if (idx >= LL * 2048) return;
    int l = idx / 2048, r = idx % 2048;
    int seg = r >> 8, c = r & 255;
    float v;
    switch (seg) {
        case 0: v = qb[(l * 2 + 1) * 256 + c]; break;
        case 1: v = bk[(l * 3 + 2) * 256 + c]; break;
        case 2: v = bk[(l * 3 + 0) * 256 + c]; break;
        case 3: v = bm[(l * 3 + 2) * 256 + c]; break;
        case 4: v = bm[(l * 3 + 0) * 256 + c]; break;
        case 5: v = qb[(l * 2 + 0) * 256 + c]; break;
        case 6: v = bk[(l * 3 + 1) * 256 + c]; break;
        default: v = bm[(l * 3 + 1) * 256 + c]; break;
    }
    if (seg < 5) bp[l * PSTR + seg * 256 + c] = v;
    else         ba[l * ASTR + (seg - 5) * 256 + c] = v;
}

// ---------------------------------------------------------------------------
// HMMA GEMM: C[M, grid.y*BN] (row stride Ntot) = epi( scale*(A @ W^T) + bias )
// A either bf16 hi/lo [M][256] (A32=false) or fp32 [M][256] (A32=true:
// converted to hi/lo in the loader). W bf16 hi/lo [rows][256] k-contig.
// 3-term: Ahi*Whi + Ahi*Wlo + Alo*Whi, fp32 register accumulation.
// 512 threads = 16 warps (4M x 4N), CTA tile 128 x BN, warp tile 32 x BN/4,
// K chunks of 64, 2-stage pipeline, SW128 swizzle + ldmatrix.
// ---------------------------------------------------------------------------
#define A_HI_OFF  0
#define A_LO_OFF  16384

template <int BN, bool GELU, bool HILO, bool A32>
__global__ void __launch_bounds__(512, 1)
hmma_gemm(const __nv_bfloat16* __restrict__ Ahi, const __nv_bfloat16* __restrict__ Alo,
          const float* __restrict__ Af,
          const __nv_bfloat16* __restrict__ Whi, const __nv_bfloat16* __restrict__ Wlo,
          const float* __restrict__ bias, float* __restrict__ C,
          __nv_bfloat16* __restrict__ Chi, __nv_bfloat16* __restrict__ Clo,
          int M, int Ntot, float scale)
{
    constexpr int WN = BN / 4;          // warp n extent (32 for BN=128, 16 for BN=64)
    constexpr int NT = WN / 16;         // n16 tiles per warp (2 / 1)
    constexpr int B_HI_OFF = 32768;
    constexpr int B_LO_OFF = 32768 + BN * 128;
    constexpr int STG = 32768 + 2 * BN * 128;
    constexpr int A_OPS = 2048;                 // 128 rows * 8 sixteens * (hi+lo)
    constexpr int TOT_OPS = A_OPS + BN * 16;    // bf16 path op count
    constexpr int B_OPS = BN * 16;              // A32 path: B only

    extern __shared__ __align__(1024) char sm[];
    const uint32_t sb = smem_u32(sm);

    const int tid = threadIdx.x;
    const int lane = tid & 31, wid = tid >> 5;
    const int wm = wid & 3, wn = wid >> 2;          // warp grid 4 x 4
    const int m0 = blockIdx.x * 128, n0 = blockIdx.y * BN;

    // bf16-A loader (cp.async everything)
    auto load_chunk_bf16 = [&](int kc, int stg) {
        uint32_t base = sb + stg * STG;
        int kb = kc * 64;
#pragma unroll
        for (int it = tid; it < TOT_OPS; it += 512) {
            bool isA = it < A_OPS;
            int i = isA ? (it & 1023) : ((it - A_OPS) % (BN * 8));
            bool isHi = isA ? (it < 1024) : ((it - A_OPS) < BN * 8);
            int r = i >> 3, s = i & 7;
            uint32_t o = SWZ((uint32_t)(r * 128 + s * 16));
            if (isA) {
                if (m0 + r < M) {
                    const __nv_bfloat16* gp = (isHi ? Ahi : Alo) + (size_t)(m0 + r) * 256 + kb + s * 8;
                    CPASYNC16(base + (isHi ? A_HI_OFF : A_LO_OFF) + o, gp);
                }
            } else {
                const __nv_bfloat16* gp = (isHi ? Whi : Wlo) + (size_t)(n0 + r) * 256 + kb + s * 8;
                CPASYNC16(base + (isHi ? B_HI_OFF : B_LO_OFF) + o, gp);
            }
        }
        asm volatile("cp.async.commit_group;" ::: "memory");
    };

    // A32 path helpers: B via cp.async, A via LDG(regs) + convert + STS.
    auto load_B = [&](int kc, int stg) {
        uint32_t base = sb + stg * STG;
        int kb = kc * 64;
#pragma unroll
        for (int it = tid; it < B_OPS; it += 512) {
            int i = it % (BN * 8);
            bool isHi = it < BN * 8;
            int r = i >> 3, s = i & 7;
            uint32_t o = SWZ((uint32_t)(r * 128 + s * 16));
            const __nv_bfloat16* gp = (isHi ? Whi : Wlo) + (size_t)(n0 + r) * 256 + kb + s * 8;
            CPASYNC16(base + (isHi ? B_HI_OFF : B_LO_OFF) + o, gp);
        }
        asm volatile("cp.async.commit_group;" ::: "memory");
    };
    // thread -> (row, quad): 4 threads per row, each 4 float4 (16 fp32 = 32B bf16)
    const int a_row = tid >> 2, a_q = tid & 3;
    auto ldg_A = [&](int kc, float4* buf) {
        int kb = kc * 64;
        if (m0 + a_row < M) {
            const float4* src = (const float4*)(Af + (size_t)(m0 + a_row) * 256 + kb + a_q * 16);
#pragma unroll
            for (int i = 0; i < 4; i++) buf[i] = src[i];
        } else {
#pragma unroll
            for (int i = 0; i < 4; i++) buf[i] = make_float4(0.f, 0.f, 0.f, 0.f);
        }
    };
    auto sts_A = [&](const float4* buf, int stg) {
        uint32_t base = sb + stg * STG;
#pragma unroll
        for (int i = 0; i < 4; i++) {
            float4 v = buf[i];
            uint32_t o = SWZ((uint32_t)(a_row * 128 + a_q * 32 + i * 8));
            union { __nv_bfloat16 b[4]; uint2 u; } uh, ul;
            uh.b[0] = __float2bfloat16(v.x); uh.b[1] = __float2bfloat16(v.y);
            uh.b[2] = __float2bfloat16(v.z); uh.b[3] = __float2bfloat16(v.w);
            ul.b[0] = __float2bfloat16(v.x - __bfloat162float(uh.b[0]));
            ul.b[1] = __float2bfloat16(v.y - __bfloat162float(uh.b[1]));
            ul.b[2] = __float2bfloat16(v.z - __bfloat162float(uh.b[2]));
            ul.b[3] = __float2bfloat16(v.w - __bfloat162float(uh.b[3]));
            STS64(base + A_HI_OFF + o, uh.u.x, uh.u.y);
            STS64(base + A_LO_OFF + o, ul.u.x, ul.u.y);
        }
    };

    float d[2][2 * NT][4];
#pragma unroll
    for (int i = 0; i < 2; i++)
#pragma unroll
        for (int j = 0; j < 2 * NT; j++)
#pragma unroll
            for (int r = 0; r < 4; r++) d[i][j][r] = 0.f;

    const int g = lane >> 3, l7 = lane & 7;
    const int a_row_off = (g & 1) ? 8 : 0;
    const int a_byte_off = (g & 2) ? 16 : 0;
    const int b_row_off = (g & 2) ? 8 : 0;
    const int b_byte_off = (g & 1) ? 16 : 0;

    float4 abuf[4];
    if (A32) { ldg_A(0, abuf); load_B(0, 0); }
    else     { load_chunk_bf16(0, 0); }

    for (int kc = 0; kc < 4; kc++) {
        if (A32) {
            sts_A(abuf, kc & 1);                 // consume chunk kc regs
            if (kc < 3) ldg_A(kc + 1, abuf);     // issue next LDGs early (hidden by mma)
            if (kc < 3) load_B(kc + 1, (kc + 1) & 1);
            if (kc < 3) asm volatile("cp.async.wait_group 1;" ::: "memory");
            else        asm volatile("cp.async.wait_group 0;" ::: "memory");
        } else {
            if (kc < 3) load_chunk_bf16(kc + 1, (kc + 1) & 1);
            if (kc < 3) asm volatile("cp.async.wait_group 1;" ::: "memory");
            else        asm volatile("cp.async.wait_group 0;" ::: "memory");
        }
        __syncthreads();

        uint32_t base = sb + (kc & 1) * STG;
#pragma unroll
        for (int kk = 0; kk < 4; kk++) {
            int kb2 = kk * 32;
            uint32_t a_hi[2][4], a_lo[2][4], b_hi[NT][4], b_lo[NT][4];
#pragma unroll
            for (int i = 0; i < 2; i++) {
                uint32_t o = SWZ((uint32_t)((wm * 32 + i * 16 + l7 + a_row_off) * 128 + kb2 + a_byte_off));
                LDSM_X4(a_hi[i][0], a_hi[i][1], a_hi[i][2], a_hi[i][3], base + A_HI_OFF + o);
                LDSM_X4(a_lo[i][0], a_lo[i][1], a_lo[i][2], a_lo[i][3], base + A_LO_OFF + o);
            }
#pragma unroll
            for (int jt = 0; jt < NT; jt++) {
                uint32_t o = SWZ((uint32_t)((wn * WN + jt * 16 + l7 + b_row_off) * 128 + kb2 + b_byte_off));
                LDSM_X4(b_hi[jt][0], b_hi[jt][1], b_hi[jt][2], b_hi[jt][3], base + B_HI_OFF + o);
                LDSM_X4(b_lo[jt][0], b_lo[jt][1], b_lo[jt][2], b_lo[jt][3], base + B_LO_OFF + o);
            }
#pragma unroll
            for (int i = 0; i < 2; i++)
#pragma unroll
                for (int jt = 0; jt < NT; jt++)
#pragma unroll
                    for (int half = 0; half < 2; half++) {
                        int j = jt * 2 + half, sel = half * 2;
                        MMA16816(d[i][j], a_hi[i], b_hi[jt][sel], b_hi[jt][sel + 1]);
                        MMA16816(d[i][j], a_hi[i], b_lo[jt][sel], b_lo[jt][sel + 1]);
                        MMA16816(d[i][j], a_lo[i], b_hi[jt][sel], b_hi[jt][sel + 1]);
                    }
        }
        __syncthreads();
    }

    // ---- epilogue ----
    const int r_base = m0 + wm * 32;
    const int c_base = n0 + wn * WN;
#pragma unroll
    for (int i = 0; i < 2; i++)
#pragma unroll
        for (int j = 0; j < 2 * NT; j++) {
            int col = c_base + j * 8 + (lane & 3) * 2;
            float2 b2 = *(const float2*)(bias + col);
#pragma unroll
            for (int half = 0; half < 2; half++) {
                int row = r_base + i * 16 + (lane >> 2) + half * 8;
                if (row >= M) continue;
                float vx = d[i][j][half * 2 + 0] * scale + b2.x;
                float vy = d[i][j][half * 2 + 1] * scale + b2.y;
                if (GELU) { vx = gelu_exact(vx); vy = gelu_exact(vy); }
                *(float2*)(C + (size_t)row * Ntot + col) = make_float2(vx, vy);
                if (HILO) {
                    union { __nv_bfloat16 b[2]; uint32_t u; } uh, ul;
                    uh.b[0] = __float2bfloat16(vx);
                    uh.b[1] = __float2bfloat16(vy);
                    ul.b[0] = __float2bfloat16(vx - __bfloat162float(uh.b[0]));
                    ul.b[1] = __float2bfloat16(vy - __bfloat162float(uh.b[1]));
                    *(uint32_t*)(Chi + (size_t)row * Ntot + col) = uh.u;
                    *(uint32_t*)(Clo + (size_t)row * Ntot + col) = ul.u;
                }
            }
        }
}

// ---------------------------------------------------------------------------
// Edge kernel: one warp per edge; q/k/m read from strided projection buffers.
// ---------------------------------------------------------------------------
__global__ void edge_kernel(const float* __restrict__ q, int qs,
                            const float* __restrict__ khat, const float* __restrict__ mhat, int kms,
                            const int* __restrict__ src, const int* __restrict__ dst,
                            const float* __restrict__ ew, const float* __restrict__ pri,
                            float* __restrict__ agg, int E)
{
    int gw = (int)((blockIdx.x * (size_t)blockDim.x + threadIdx.x) >> 5);
    int lane = threadIdx.x & 31;
    if (gw >= E) return;

    int s = src[gw];
    int d = dst[gw];

    const float4* qr = (const float4*)(q    + (size_t)d * qs) + lane * 2;
    const float4* kr = (const float4*)(khat + (size_t)s * kms) + lane * 2;
    float4 q0 = qr[0], q1 = qr[1];
    float4 k0 = kr[0], k1 = kr[1];
    float p = q0.x * k0.x + q0.y * k0.y + q0.z * k0.z + q0.w * k0.w
            + q1.x * k1.x + q1.y * k1.y + q1.z * k1.z + q1.w * k1.w;
    p += __shfl_xor_sync(0xffffffffu, p, 1);
    p += __shfl_xor_sync(0xffffffffu, p, 2);
    p += __shfl_xor_sync(0xffffffffu, p, 4);

    int h = lane >> 3;
    float score = p * pri[h] * 0.125f;
    float attn = ew[gw] / (1.f + __expf(-score));

    const float4* mr = (const float4*)(mhat + (size_t)s * kms) + lane * 2;
    float4 m0 = mr[0], m1 = mr[1];

    float* out = agg + (size_t)d * 256 + lane * 8;
    asm volatile("red.global.add.v4.f32 [%0], {%1,%2,%3,%4};" ::
                 "l"(out), "f"(m0.x * attn), "f"(m0.y * attn),
                 "f"(m0.z * attn), "f"(m0.w * attn) : "memory");
    asm volatile("red.global.add.v4.f32 [%0], {%1,%2,%3,%4};" ::
                 "l"(out + 4), "f"(m1.x * attn), "f"(m1.y * attn),
                 "f"(m1.z * attn), "f"(m1.w * attn) : "memory");
}

// ---------------------------------------------------------------------------
// Skip-blend + LayerNorm; also emits bf16 hi/lo of the output.
// ---------------------------------------------------------------------------
__global__ void ln_blend_kernel(const float* __restrict__ tr, const float* __restrict__ feats,
                                const float* __restrict__ g, const float* __restrict__ b,
                                const float* __restrict__ skip, int skip_idx,
                                float* __restrict__ out,
                                __nv_bfloat16* __restrict__ ohi, __nv_bfloat16* __restrict__ olo,
                                int N)
{
    int row = (int)((blockIdx.x * (size_t)blockDim.x + threadIdx.x) >> 5);
    int lane = threadIdx.x & 31;
    if (row >= N) return;

    float alpha = 1.f / (1.f + __expf(-skip[skip_idx]));
    float beta = 1.f - alpha;

    const float4* t4 = (const float4*)(tr    + (size_t)row * 256) + lane * 2;
    const float4* f4 = (const float4*)(feats + (size_t)row * 256) + lane * 2;
    float4 ta = t4[0], tb = t4[1], fa = f4[0], fb = f4[1];

    float v[8];
    v[0] = ta.x * alpha + fa.x * beta;  v[1] = ta.y * alpha + fa.y * beta;
    v[2] = ta.z * alpha + fa.z * beta;  v[3] = ta.w * alpha + fa.w * beta;
    v[4] = tb.x * alpha + fb.x * beta;  v[5] = tb.y * alpha + fb.y * beta;
    v[6] = tb.z * alpha + fb.z * beta;  v[7] = tb.w * alpha + fb.w * beta;

    float s = 0.f;
#pragma unroll
    for (int i = 0; i < 8; i++) s += v[i];
#pragma unroll
    for (int o = 16; o > 0; o >>= 1) s += __shfl_xor_sync(0xffffffffu, s, o);
    float mean = s * (1.f / 256.f);

    float sq = 0.f;
#pragma unroll
    for (int i = 0; i < 8; i++) { float dv = v[i] - mean; sq += dv * dv; }
#pragma unroll
    for (int o = 16; o > 0; o >>= 1) sq += __shfl_xor_sync(0xffffffffu, sq, o);
    float rstd = rsqrtf(sq * (1.f / 256.f) + 1e-5f);

    const float4* g4 = (const float4*)(g) + lane * 2;
    const float4* b4 = (const float4*)(b) + lane * 2;
    float4 ga = g4[0], gb = g4[1], ba = b4[0], bb = b4[1];
    float gg[8] = {ga.x, ga.y, ga.z, ga.w, gb.x, gb.y, gb.z, gb.w};
    float bbv[8] = {ba.x, ba.y, ba.z, ba.w, bb.x, bb.y, bb.z, bb.w};

    float o8[8];
    union { __nv_bfloat16 b[8]; uint4 u; } uh, ul;
#pragma unroll
    for (int i = 0; i < 8; i++) {
        o8[i] = (v[i] - mean) * rstd * gg[i] + bbv[i];
        uh.b[i] = __float2bfloat16(o8[i]);
        ul.b[i] = __float2bfloat16(o8[i] - __bfloat162float(uh.b[i]));
    }

    float4* outp = (float4*)(out + (size_t)row * 256) + lane * 2;
    outp[0] = make_float4(o8[0], o8[1], o8[2], o8[3]);
    outp[1] = make_float4(o8[4], o8[5], o8[6], o8[7]);
    *(uint4*)(ohi + (size_t)row * 256 + lane * 8) = uh.u;
    *(uint4*)(olo + (size_t)row * 256 + lane * 8) = ul.u;
}

// ---------------------------------------------------------------------------
// Host orchestration.
// ---------------------------------------------------------------------------
static const int SMEM128 = 2 * (32768 + 2 * 128 * 128);   // 131072
static const int SMEM64  = 2 * (32768 + 2 * 64 * 128);    // 98304

extern "C" void kernel_launch(void* const* d_in, const int* in_sizes, int n_in,
                              void* d_out, int out_size)
{
    const float* x_author = (const float*)d_in[0];
    const float* x_paper  = (const float*)d_in[1];
    const float* ew_wb    = (const float*)d_in[2];
    const float* ew_w     = (const float*)d_in[3];
    const float* ew_c     = (const float*)d_in[4];
    const float* adapt_W  = (const float*)d_in[5];
    const float* adapt_b  = (const float*)d_in[6];
    const float* kW       = (const float*)d_in[7];
    const float* kb       = (const float*)d_in[8];
    const float* qW       = (const float*)d_in[9];
    const float* qb       = (const float*)d_in[10];
    const float* mW       = (const float*)d_in[11];
    const float* mb       = (const float*)d_in[12];
    const float* aW       = (const float*)d_in[13];
    const float* ab       = (const float*)d_in[14];
    const float* w_pri    = (const float*)d_in[15];
    const float* w_att    = (const float*)d_in[16];
    const float* w_msg    = (const float*)d_in[17];
    const float* skip     = (const float*)d_in[18];
    const float* ln_g     = (const float*)d_in[19];
    const float* ln_b     = (const float*)d_in[20];
    const float* out_W    = (const float*)d_in[21];
    const float* out_b    = (const float*)d_in[22];
    const int* src_wb     = (const int*)d_in[23];
    const int* dst_wb     = (const int*)d_in[24];
    const int* src_w      = (const int*)d_in[25];
    const int* dst_w      = (const int*)d_in[26];
    const int* src_c      = (const int*)d_in[27];
    const int* dst_c      = (const int*)d_in[28];
    (void)in_sizes; (void)n_in; (void)out_size;

    cudaFuncSetAttribute(hmma_gemm<128, false, false, false>, cudaFuncAttributeMaxDynamicSharedMemorySize, SMEM128);
    cudaFuncSetAttribute(hmma_gemm<128, false, false, true>,  cudaFuncAttributeMaxDynamicSharedMemorySize, SMEM128);
    cudaFuncSetAttribute(hmma_gemm<128, true, true, true>,    cudaFuncAttributeMaxDynamicSharedMemorySize, SMEM128);
    cudaFuncSetAttribute(hmma_gemm<64, false, false, false>,  cudaFuncAttributeMaxDynamicSharedMemorySize, SMEM64);

    float *feats_a, *feats_p, *proj_a, *proj_p;
    float *agg_a, *agg_p, *tr_a, *tr_p, *Wkp, *bkp, *Wmp, *bmp, *bias_p, *bias_a;
    __nv_bfloat16 *fa_hi, *fa_lo, *fp_hi, *fp_lo, *Whi, *Wlo;
#define SYM(var, sym) cudaGetSymbolAddress((void**)&var, sym)
    SYM(feats_a, g_feats_a); SYM(feats_p, g_feats_p);
    SYM(proj_a, g_proj_a); SYM(proj_p, g_proj_p);
    SYM(agg_a, g_agg_a); SYM(agg_p, g_agg_p);
    SYM(tr_a, g_tr_a); SYM(tr_p, g_tr_p);
    SYM(Wkp, g_Wk); SYM(bkp, g_bk); SYM(Wmp, g_Wm); SYM(bmp, g_bm);
    SYM(bias_p, g_bias_p); SYM(bias_a, g_bias_a);
    SYM(fa_hi, g_fa_hi); SYM(fa_lo, g_fa_lo); SYM(fp_hi, g_fp_hi); SYM(fp_lo, g_fp_lo);
    SYM(Whi, g_Whi); SYM(Wlo, g_Wlo);
#undef SYM

    float* fa[2] = {feats_a, feats_a + (size_t)NA * D};
    float* fp[2] = {feats_p, feats_p + (size_t)NP * D};

    const int GA = (NA + 127) / 128;   // 157
    const int GP = (NP + 127) / 128;   // 313

    // 0) weight prep
    combine_weights<<<dim3(12, 257), 256>>>(kW, kb, mW, mb, w_att, w_msg, Wkp, bkp, Wmp, bmp);
    transpose_split<<<dim3(8, 8, NSLOT), dim3(32, 8)>>>(adapt_W, qW, Wkp, Wmp, aW, out_W, Whi, Wlo);
    pack_bias<<<(LL * 2048 + 255) / 256, 256>>>(qb, bkp, bmp, bias_p, bias_a);

    // 1) adapt + GELU straight from fp32 inputs (A32 loader), emits feats + hi/lo
    hmma_gemm<128, true, true, true><<<dim3(GA, 2), 512, SMEM128>>>(nullptr, nullptr, x_author,
        Whi, Wlo, adapt_b, fa[0], fa_hi, fa_lo, NA, 256, 1.f);
    hmma_gemm<128, true, true, true><<<dim3(GP, 2), 512, SMEM128>>>(nullptr, nullptr, x_paper,
        Whi + 65536, Wlo + 65536, adapt_b + 256, fp[0], fp_hi, fp_lo, NP, 256, 1.f);

    for (int l = 0; l < LL; l++) {
        int cur = l & 1, nxt = 1 - cur;

        // batched projections: paper 5 mats (q, k_wb, k_c, m_wb, m_c), author 3 (q, k_w, m_w)
        const size_t psl = (size_t)(2 + l * 8) * 65536;
        const size_t asl = (size_t)(2 + l * 8 + 5) * 65536;
        hmma_gemm<128, false, false, false><<<dim3(GP, PSTR / 128), 512, SMEM128>>>(fp_hi, fp_lo, nullptr,
            Whi + psl, Wlo + psl, bias_p + l * PSTR, proj_p, nullptr, nullptr, NP, PSTR, 1.f);
        hmma_gemm<128, false, false, false><<<dim3(GA, ASTR / 128), 512, SMEM128>>>(fa_hi, fa_lo, nullptr,
            Whi + asl, Wlo + asl, bias_a + l * ASTR, proj_a, nullptr, nullptr, NA, ASTR, 1.f);

        cudaMemsetAsync(agg_a, 0, (size_t)NA * D * sizeof(float), 0);
        cudaMemsetAsync(agg_p, 0, (size_t)NP * D * sizeof(float), 0);

        // WRITTEN_BY: dst author (q in proj_a), src paper (k/m in proj_p)
        edge_kernel<<<(E_WB + 7) / 8, 256>>>(proj_a, ASTR, proj_p + 256, proj_p + 768, PSTR,
            src_wb, dst_wb, ew_wb, w_pri + (l * 3 + 2) * 4, agg_a, E_WB);
        // WRITES: dst paper, src author
        edge_kernel<<<(E_W + 7) / 8, 256>>>(proj_p, PSTR, proj_a + 256, proj_a + 512, ASTR,
            src_w, dst_w, ew_w, w_pri + (l * 3 + 1) * 4, agg_p, E_W);
        // CITES: dst paper, src paper
        edge_kernel<<<(E_C + 7) / 8, 256>>>(proj_p, PSTR, proj_p + 512, proj_p + 1024, PSTR,
            src_c, dst_c, ew_c, w_pri + (l * 3 + 0) * 4, agg_p, E_C);

        // a-projection straight from fp32 agg (A32 loader); 0.5 paper mean via scale
        const size_t aa = (size_t)(18 + l * 2 + 0) * 65536;
        const size_t ap = (size_t)(18 + l * 2 + 1) * 65536;
        hmma_gemm<128, false, false, true><<<dim3(GA, 2), 512, SMEM128>>>(nullptr, nullptr, agg_a,
            Whi + aa, Wlo + aa, ab + (l * 2 + 0) * 256, tr_a, nullptr, nullptr, NA, 256, 1.0f);
        hmma_gemm<128, false, false, true><<<dim3(GP, 2), 512, SMEM128>>>(nullptr, nullptr, agg_p,
            Whi + ap, Wlo + ap, ab + (l * 2 + 1) * 256, tr_p, nullptr, nullptr, NP, 256, 0.5f);

        // skip blend + LN (emits fp32 feats + hi/lo for next layer / out proj)
        ln_blend_kernel<<<(NA + 7) / 8, 256>>>(tr_a, fa[cur], ln_g + (l * 2 + 0) * 256,
            ln_b + (l * 2 + 0) * 256, skip, l * 3 + 0, fa[nxt], fa_hi, fa_lo, NA);
        ln_blend_kernel<<<(NP + 7) / 8, 256>>>(tr_p, fp[cur], ln_g + (l * 2 + 1) * 256,
            ln_b + (l * 2 + 1) * 256, skip, l * 3 + 1, fp[nxt], fp_hi, fp_lo, NP);
    }

    // output projection: paper feats (hi/lo from last LN) @ out_W + out_b
    hmma_gemm<64, false, false, false><<<dim3(GP, 1), 512, SMEM64>>>(fp_hi, fp_lo, nullptr,
        Whi + (size_t)22 * 65536, Wlo + (size_t)22 * 65536,
        out_b, (float*)d_out, nullptr, nullptr, NP, 64, 1.f);
}

// round 12
// speedup vs baseline: 1.5696x; 1.5696x over previous
#include <cuda_runtime.h>
#include <cuda_bf16.h>
#include <cuda_fp16.h>
#include <math.h>
#include <stdint.h>

// ---------------------------------------------------------------------------
// HGT forward. GEMMs via mma.sync bf16 (hi/lo 3-term = fp32-class accuracy).
// R12: fp16 (not bf16) projection outputs + fp16 edge gather. fp16's 11
// mantissa bits keep quantization error ~2e-4 (bf16's 8 bits gave 1.5e-3).
// ---------------------------------------------------------------------------
#define NA     20000
#define NP     40000
#define D      256
#define DOUT   64
#define LL     2
#define E_WB   150000
#define E_W    150000
#define E_C    300000
#define NSLOT  23
// paper proj row: [0,256)=q | [256,512)=k_wb | [512,768)=k_c | [768,1024)=m_wb | [1024,1280)=m_c
#define PSTR   1280
// author proj row: [0,256)=q | [256,512)=k_w | [512,768)=m_w
#define ASTR   768

// ------------------------- device scratch ----------------------------------
__device__ float g_feats_a[2][NA * D];
__device__ float g_feats_p[2][NP * D];
__device__ __half g_proj_a[NA * ASTR];
__device__ __half g_proj_p[NP * PSTR];
__device__ float g_agg_a[NA * D];
__device__ float g_agg_p[NP * D];
__device__ float g_tr_a[NA * D];
__device__ float g_tr_p[NP * D];
__device__ float g_Wk[LL * 3 * D * D];
__device__ float g_bk[LL * 3 * D];
__device__ float g_Wm[LL * 3 * D * D];
__device__ float g_bm[LL * 3 * D];
__device__ float g_bias_p[LL * PSTR];
__device__ float g_bias_a[LL * ASTR];
// bf16 hi/lo operands
__device__ __nv_bfloat16 g_xa_hi[NA * D], g_xa_lo[NA * D];
__device__ __nv_bfloat16 g_xp_hi[NP * D], g_xp_lo[NP * D];
__device__ __nv_bfloat16 g_fa_hi[NA * D], g_fa_lo[NA * D];
__device__ __nv_bfloat16 g_fp_hi[NP * D], g_fp_lo[NP * D];
__device__ __nv_bfloat16 g_ga_hi[NA * D], g_ga_lo[NA * D];
__device__ __nv_bfloat16 g_gp_hi[NP * D], g_gp_lo[NP * D];
__device__ __nv_bfloat16 g_Whi[NSLOT * D * D], g_Wlo[NSLOT * D * D];

// ------------------------- small helpers -----------------------------------
__device__ __forceinline__ uint32_t smem_u32(const void* p) {
    uint32_t a;
    asm("{ .reg .u64 t; cvta.to.shared.u64 t, %1; cvt.u32.u64 %0, t; }" : "=r"(a) : "l"(p));
    return a;
}
#define SWZ(off) ((off) ^ (((off) >> 3) & 0x70))

#define CPASYNC16(dst, src) \
    asm volatile("cp.async.cg.shared.global [%0], [%1], 16;" :: "r"(dst), "l"(src) : "memory")

#define LDSM_X4(r0, r1, r2, r3, addr)                                         \
    asm volatile("ldmatrix.sync.aligned.m8n8.x4.shared.b16 {%0,%1,%2,%3}, [%4];" \
                 : "=r"(r0), "=r"(r1), "=r"(r2), "=r"(r3) : "r"(addr))

#define MMA16816(d, a, b0, b1)                                                \
    asm volatile("mma.sync.aligned.m16n8k16.row.col.f32.bf16.bf16.f32 "       \
                 "{%0,%1,%2,%3}, {%4,%5,%6,%7}, {%8,%9}, {%0,%1,%2,%3};"      \
                 : "+f"((d)[0]), "+f"((d)[1]), "+f"((d)[2]), "+f"((d)[3])     \
                 : "r"((a)[0]), "r"((a)[1]), "r"((a)[2]), "r"((a)[3]),        \
                   "r"(b0), "r"(b1))

__device__ __forceinline__ float gelu_exact(float x) {
    return 0.5f * x * (1.0f + erff(x * 0.70710678118654752f));
}

// ---------------------------------------------------------------------------
// combine per-head w_att/w_msg into dense K/M projection weights (fp32).
// ---------------------------------------------------------------------------
__global__ void combine_weights(const float* __restrict__ kW, const float* __restrict__ kb,
                                const float* __restrict__ mW, const float* __restrict__ mb,
                                const float* __restrict__ w_att, const float* __restrict__ w_msg,
                                float* __restrict__ Wk, float* __restrict__ bk,
                                float* __restrict__ Wm, float* __restrict__ bm)
{
    int mat = blockIdx.x;
    int l = mat / 6;
    int r6 = mat % 6;
    int e = r6 / 2;
    int which = r6 % 2;
    int d = blockIdx.y;        // 0..256 (256 == bias row)
    int j = threadIdx.x;
    int h = j >> 6;
    int jj = j & 63;
    int st = (e == 1) ? 0 : 1;

    const float* W   = which ? mW : kW;
    const float* B   = which ? mb : kb;
    const float* att = which ? w_msg : w_att;

    const float* wrow;
    if (d < 256) wrow = W + (((size_t)(l * 2 + st) * 256 + d) * 256);
    else         wrow = B + ((size_t)(l * 2 + st) * 256);
    const float* a = att + ((size_t)((l * 3 + e) * 4 + h)) * 64 * 64;

    float s = 0.f;
#pragma unroll 8
    for (int c = 0; c < 64; c++)
        s += wrow[h * 64 + c] * a[c * 64 + jj];

    float* out  = which ? Wm : Wk;
    float* outb = which ? bm : bk;
    if (d < 256) out[((size_t)(l * 3 + e) * 256 + d) * 256 + j] = s;
    else         outb[(size_t)(l * 3 + e) * 256 + j] = s;
}

// ---------------------------------------------------------------------------
// Transpose + split all weight matrices into bf16 hi/lo, K-major [n][k].
// Slot order: 0,1 adapt | 2+l*8+{0..7}: q_p,k_wb,k_c,m_wb,m_c,q_a,k_w,m_w
//             | 18+l*2+nt aW | 22 out_W
// ---------------------------------------------------------------------------
__global__ void transpose_split(const float* __restrict__ adapt_W, const float* __restrict__ qW,
                                const float* __restrict__ Wk, const float* __restrict__ Wm,
                                const float* __restrict__ aW, const float* __restrict__ outW,
                                __nv_bfloat16* __restrict__ Whi, __nv_bfloat16* __restrict__ Wlo)
{
    int slot = blockIdx.z;
    const float* src; int NC = 256;
    if (slot < 2)        src = adapt_W + (size_t)slot * 65536;
    else if (slot < 18) {
        int l = (slot - 2) / 8, o = (slot - 2) % 8;
        switch (o) {
            case 0: src = qW + (size_t)(l * 2 + 1) * 65536; break;
            case 1: src = Wk + (size_t)(l * 3 + 2) * 65536; break;
            case 2: src = Wk + (size_t)(l * 3 + 0) * 65536; break;
            case 3: src = Wm + (size_t)(l * 3 + 2) * 65536; break;
            case 4: src = Wm + (size_t)(l * 3 + 0) * 65536; break;
            case 5: src = qW + (size_t)(l * 2 + 0) * 65536; break;
            case 6: src = Wk + (size_t)(l * 3 + 1) * 65536; break;
            default: src = Wm + (size_t)(l * 3 + 1) * 65536; break;
        }
    }
    else if (slot < 22)  src = aW + (size_t)(slot - 18) * 65536;
    else               { src = outW; NC = 64; }

    int k0 = blockIdx.x * 32, n0 = blockIdx.y * 32;
    if (n0 >= NC) return;
    int tx = threadIdx.x, ty = threadIdx.y;

    __shared__ float t[32][33];
#pragma unroll
    for (int i = 0; i < 4; i++) {
        int k = k0 + ty + i * 8;
        t[ty + i * 8][tx] = src[(size_t)k * NC + n0 + tx];
    }
    __syncthreads();
#pragma unroll
    for (int i = 0; i < 4; i++) {
        int n = n0 + ty + i * 8, k = k0 + tx;
        float v = t[tx][ty + i * 8];
        __nv_bfloat16 h = __float2bfloat16(v);
        float r = v - __bfloat162float(h);
        size_t o = (size_t)slot * 65536 + (size_t)n * 256 + k;
        Whi[o] = h;
        Wlo[o] = __float2bfloat16(r);
    }
}

// ---------------------------------------------------------------------------
// Pack per-layer projection biases into the batched column layout.
// ---------------------------------------------------------------------------
__global__ void pack_bias(const float* __restrict__ qb, const float* __restrict__ bk,
                          const float* __restrict__ bm,
                          float* __restrict__ bp, float* __restrict__ ba)
{
    int idx = blockIdx.x * 256 + threadIdx.x;    // 2 * 2048
    if (idx >= LL * 2048) return;
    int l = idx / 2048, r = idx % 2048;
    int seg = r >> 8, c = r & 255;
    float v;
    switch (seg) {
        case 0: v = qb[(l * 2 + 1) * 256 + c]; break;
        case 1: v = bk[(l * 3 + 2) * 256 + c]; break;
        case 2: v = bk[(l * 3 + 0) * 256 + c]; break;
        case 3: v = bm[(l * 3 + 2) * 256 + c]; break;
        case 4: v = bm[(l * 3 + 0) * 256 + c]; break;
        case 5: v = qb[(l * 2 + 0) * 256 + c]; break;
        case 6: v = bk[(l * 3 + 1) * 256 + c]; break;
        default: v = bm[(l * 3 + 1) * 256 + c]; break;
    }
    if (seg < 5) bp[l * PSTR + seg * 256 + c] = v;
    else         ba[l * ASTR + (seg - 5) * 256 + c] = v;
}

// ---------------------------------------------------------------------------
// fp32 -> bf16 hi/lo split (vectorized).
// ---------------------------------------------------------------------------
__global__ void split_hilo(const float* __restrict__ s, __nv_bfloat16* __restrict__ hi,
                           __nv_bfloat16* __restrict__ lo, int n4)
{
    int i = blockIdx.x * blockDim.x + threadIdx.x;
    if (i >= n4) return;
    float4 v = ((const float4*)s)[i];
    __nv_bfloat16 h[4], l[4];
    float vv[4] = {v.x, v.y, v.z, v.w};
#pragma unroll
    for (int j = 0; j < 4; j++) {
        h[j] = __float2bfloat16(vv[j]);
        l[j] = __float2bfloat16(vv[j] - __bfloat162float(h[j]));
    }
    ((uint2*)hi)[i] = *(uint2*)h;
    ((uint2*)lo)[i] = *(uint2*)l;
}

// ---------------------------------------------------------------------------
// HMMA GEMM: epi( scale*(A @ W^T) + bias ), A bf16 hi/lo [M][256] k-contig,
// W bf16 hi/lo [rows][256] k-contig. 3-term fp32 accumulation.
// Output: OUTH ? fp16 into Ch : fp32 into C (HILO additionally emits hi/lo).
// 512 threads = 16 warps (4M x 4N), CTA tile 128 x BN, warp tile 32 x BN/4,
// K chunks of 64, 2-stage cp.async pipeline, SW128 swizzle + ldmatrix.
// ---------------------------------------------------------------------------
#define A_HI_OFF  0
#define A_LO_OFF  16384

template <int BN, bool GELU, bool HILO, bool OUTH>
__global__ void __launch_bounds__(512, 1)
hmma_gemm(const __nv_bfloat16* __restrict__ Ahi, const __nv_bfloat16* __restrict__ Alo,
          const __nv_bfloat16* __restrict__ Whi, const __nv_bfloat16* __restrict__ Wlo,
          const float* __restrict__ bias, float* __restrict__ C,
          __half* __restrict__ Ch,
          __nv_bfloat16* __restrict__ Chi, __nv_bfloat16* __restrict__ Clo,
          int M, int Ntot, float scale)
{
    constexpr int WN = BN / 4;          // warp n extent (32 for BN=128, 16 for BN=64)
    constexpr int NT = WN / 16;         // n16 tiles per warp (2 / 1)
    constexpr int B_HI_OFF = 32768;
    constexpr int B_LO_OFF = 32768 + BN * 128;
    constexpr int STG = 32768 + 2 * BN * 128;
    constexpr int A_OPS = 2048;                 // 128 rows * 8 sixteens * (hi+lo)
    constexpr int TOT_OPS = A_OPS + BN * 16;    // + B rows * 8 * (hi+lo)

    extern __shared__ __align__(1024) char sm[];
    const uint32_t sb = smem_u32(sm);

    const int tid = threadIdx.x;
    const int lane = tid & 31, wid = tid >> 5;
    const int wm = wid & 3, wn = wid >> 2;          // warp grid 4 x 4
    const int m0 = blockIdx.x * 128, n0 = blockIdx.y * BN;

    auto load_chunk = [&](int kc, int stg) {
        uint32_t base = sb + stg * STG;
        int kb = kc * 64;
#pragma unroll
        for (int it = tid; it < TOT_OPS; it += 512) {
            bool isA = it < A_OPS;
            int i = isA ? (it & 1023) : ((it - A_OPS) % (BN * 8));
            bool isHi = isA ? (it < 1024) : ((it - A_OPS) < BN * 8);
            int r = i >> 3, s = i & 7;
            uint32_t o = SWZ((uint32_t)(r * 128 + s * 16));
            if (isA) {
                if (m0 + r < M) {
                    const __nv_bfloat16* gp = (isHi ? Ahi : Alo) + (size_t)(m0 + r) * 256 + kb + s * 8;
                    CPASYNC16(base + (isHi ? A_HI_OFF : A_LO_OFF) + o, gp);
                }
            } else {
                const __nv_bfloat16* gp = (isHi ? Whi : Wlo) + (size_t)(n0 + r) * 256 + kb + s * 8;
                CPASYNC16(base + (isHi ? B_HI_OFF : B_LO_OFF) + o, gp);
            }
        }
        asm volatile("cp.async.commit_group;" ::: "memory");
    };

    float d[2][2 * NT][4];
#pragma unroll
    for (int i = 0; i < 2; i++)
#pragma unroll
        for (int j = 0; j < 2 * NT; j++)
#pragma unroll
            for (int r = 0; r < 4; r++) d[i][j][r] = 0.f;

    const int g = lane >> 3, l7 = lane & 7;
    const int a_row_off = (g & 1) ? 8 : 0;
    const int a_byte_off = (g & 2) ? 16 : 0;
    const int b_row_off = (g & 2) ? 8 : 0;
    const int b_byte_off = (g & 1) ? 16 : 0;

    load_chunk(0, 0);

    for (int kc = 0; kc < 4; kc++) {
        if (kc < 3) load_chunk(kc + 1, (kc + 1) & 1);
        if (kc < 3) asm volatile("cp.async.wait_group 1;" ::: "memory");
        else        asm volatile("cp.async.wait_group 0;" ::: "memory");
        __syncthreads();

        uint32_t base = sb + (kc & 1) * STG;
#pragma unroll
        for (int kk = 0; kk < 4; kk++) {
            int kb2 = kk * 32;
            uint32_t a_hi[2][4], a_lo[2][4], b_hi[NT][4], b_lo[NT][4];
#pragma unroll
            for (int i = 0; i < 2; i++) {
                uint32_t o = SWZ((uint32_t)((wm * 32 + i * 16 + l7 + a_row_off) * 128 + kb2 + a_byte_off));
                LDSM_X4(a_hi[i][0], a_hi[i][1], a_hi[i][2], a_hi[i][3], base + A_HI_OFF + o);
                LDSM_X4(a_lo[i][0], a_lo[i][1], a_lo[i][2], a_lo[i][3], base + A_LO_OFF + o);
            }
#pragma unroll
            for (int jt = 0; jt < NT; jt++) {
                uint32_t o = SWZ((uint32_t)((wn * WN + jt * 16 + l7 + b_row_off) * 128 + kb2 + b_byte_off));
                LDSM_X4(b_hi[jt][0], b_hi[jt][1], b_hi[jt][2], b_hi[jt][3], base + B_HI_OFF + o);
                LDSM_X4(b_lo[jt][0], b_lo[jt][1], b_lo[jt][2], b_lo[jt][3], base + B_LO_OFF + o);
            }
#pragma unroll
            for (int i = 0; i < 2; i++)
#pragma unroll
                for (int jt = 0; jt < NT; jt++)
#pragma unroll
                    for (int half = 0; half < 2; half++) {
                        int j = jt * 2 + half, sel = half * 2;
                        MMA16816(d[i][j], a_hi[i], b_hi[jt][sel], b_hi[jt][sel + 1]);
                        MMA16816(d[i][j], a_hi[i], b_lo[jt][sel], b_lo[jt][sel + 1]);
                        MMA16816(d[i][j], a_lo[i], b_hi[jt][sel], b_hi[jt][sel + 1]);
                    }
        }
        __syncthreads();
    }

    // ---- epilogue ----
    const int r_base = m0 + wm * 32;
    const int c_base = n0 + wn * WN;
#pragma unroll
    for (int i = 0; i < 2; i++)
#pragma unroll
        for (int j = 0; j < 2 * NT; j++) {
            int col = c_base + j * 8 + (lane & 3) * 2;
            float2 b2 = *(const float2*)(bias + col);
#pragma unroll
            for (int half = 0; half < 2; half++) {
                int row = r_base + i * 16 + (lane >> 2) + half * 8;
                if (row >= M) continue;
                float vx = d[i][j][half * 2 + 0] * scale + b2.x;
                float vy = d[i][j][half * 2 + 1] * scale + b2.y;
                if (GELU) { vx = gelu_exact(vx); vy = gelu_exact(vy); }
                if (OUTH) {
                    union { __half b[2]; uint32_t u; } ub;
                    ub.b[0] = __float2half_rn(vx);
                    ub.b[1] = __float2half_rn(vy);
                    *(uint32_t*)(Ch + (size_t)row * Ntot + col) = ub.u;
                } else {
                    *(float2*)(C + (size_t)row * Ntot + col) = make_float2(vx, vy);
                }
                if (HILO) {
                    union { __nv_bfloat16 b[2]; uint32_t u; } uh, ul;
                    uh.b[0] = __float2bfloat16(vx);
                    uh.b[1] = __float2bfloat16(vy);
                    ul.b[0] = __float2bfloat16(vx - __bfloat162float(uh.b[0]));
                    ul.b[1] = __float2bfloat16(vy - __bfloat162float(uh.b[1]));
                    *(uint32_t*)(Chi + (size_t)row * Ntot + col) = uh.u;
                    *(uint32_t*)(Clo + (size_t)row * Ntot + col) = ul.u;
                }
            }
        }
}

// ---------------------------------------------------------------------------
// Edge kernel: one warp per edge; q/k/m are fp16 rows in strided proj buffers.
// Scores and aggregation math in fp32; agg stays fp32 (red.global.add.v4).
// ---------------------------------------------------------------------------
__global__ void edge_kernel(const __half* __restrict__ q, int qs,
                            const __half* __restrict__ khat,
                            const __half* __restrict__ mhat, int kms,
                            const int* __restrict__ src, const int* __restrict__ dst,
                            const float* __restrict__ ew, const float* __restrict__ pri,
                            float* __restrict__ agg, int E)
{
    int gw = (int)((blockIdx.x * (size_t)blockDim.x + threadIdx.x) >> 5);
    int lane = threadIdx.x & 31;
    if (gw >= E) return;

    int s = src[gw];
    int d = dst[gw];

    // 8 fp16 per lane = one uint4 load each for q and k
    union { uint4 u; __half2 h2[4]; } qv, kv, mv;
    qv.u = *(const uint4*)(q    + (size_t)d * qs  + lane * 8);
    kv.u = *(const uint4*)(khat + (size_t)s * kms + lane * 8);

    float p = 0.f;
#pragma unroll
    for (int i = 0; i < 4; i++) {
        float2 qf = __half22float2(qv.h2[i]);
        float2 kf = __half22float2(kv.h2[i]);
        p += qf.x * kf.x + qf.y * kf.y;
    }
    // reduce within each 8-lane head group
    p += __shfl_xor_sync(0xffffffffu, p, 1);
    p += __shfl_xor_sync(0xffffffffu, p, 2);
    p += __shfl_xor_sync(0xffffffffu, p, 4);

    int h = lane >> 3;
    float score = p * pri[h] * 0.125f;
    float attn = ew[gw] / (1.f + __expf(-score));

    mv.u = *(const uint4*)(mhat + (size_t)s * kms + lane * 8);
    float2 m0 = __half22float2(mv.h2[0]);
    float2 m1 = __half22float2(mv.h2[1]);
    float2 m2 = __half22float2(mv.h2[2]);
    float2 m3 = __half22float2(mv.h2[3]);

    float* out = agg + (size_t)d * 256 + lane * 8;
    asm volatile("red.global.add.v4.f32 [%0], {%1,%2,%3,%4};" ::
                 "l"(out), "f"(m0.x * attn), "f"(m0.y * attn),
                 "f"(m1.x * attn), "f"(m1.y * attn) : "memory");
    asm volatile("red.global.add.v4.f32 [%0], {%1,%2,%3,%4};" ::
                 "l"(out + 4), "f"(m2.x * attn), "f"(m2.y * attn),
                 "f"(m3.x * attn), "f"(m3.y * attn) : "memory");
}

// ---------------------------------------------------------------------------
// Skip-blend + LayerNorm; also emits bf16 hi/lo of the output.
// ---------------------------------------------------------------------------
__global__ void ln_blend_kernel(const float* __restrict__ tr, const float* __restrict__ feats,
                                const float* __restrict__ g, const float* __restrict__ b,
                                const float* __restrict__ skip, int skip_idx,
                                float* __restrict__ out,
                                __nv_bfloat16* __restrict__ ohi, __nv_bfloat16* __restrict__ olo,
                                int N)
{
    int row = (int)((blockIdx.x * (size_t)blockDim.x + threadIdx.x) >> 5);
    int lane = threadIdx.x & 31;
    if (row >= N) return;

    float alpha = 1.f / (1.f + __expf(-skip[skip_idx]));
    float beta = 1.f - alpha;

    const float4* t4 = (const float4*)(tr    + (size_t)row * 256) + lane * 2;
    const float4* f4 = (const float4*)(feats + (size_t)row * 256) + lane * 2;
    float4 ta = t4[0], tb = t4[1], fa = f4[0], fb = f4[1];

    float v[8];
    v[0] = ta.x * alpha + fa.x * beta;  v[1] = ta.y * alpha + fa.y * beta;
    v[2] = ta.z * alpha + fa.z * beta;  v[3] = ta.w * alpha + fa.w * beta;
    v[4] = tb.x * alpha + fb.x * beta;  v[5] = tb.y * alpha + fb.y * beta;
    v[6] = tb.z * alpha + fb.z * beta;  v[7] = tb.w * alpha + fb.w * beta;

    float s = 0.f;
#pragma unroll
    for (int i = 0; i < 8; i++) s += v[i];
#pragma unroll
    for (int o = 16; o > 0; o >>= 1) s += __shfl_xor_sync(0xffffffffu, s, o);
    float mean = s * (1.f / 256.f);

    float sq = 0.f;
#pragma unroll
    for (int i = 0; i < 8; i++) { float dv = v[i] - mean; sq += dv * dv; }
#pragma unroll
    for (int o = 16; o > 0; o >>= 1) sq += __shfl_xor_sync(0xffffffffu, sq, o);
    float rstd = rsqrtf(sq * (1.f / 256.f) + 1e-5f);

    const float4* g4 = (const float4*)(g) + lane * 2;
    const float4* b4 = (const float4*)(b) + lane * 2;
    float4 ga = g4[0], gb = g4[1], ba = b4[0], bb = b4[1];
    float gg[8] = {ga.x, ga.y, ga.z, ga.w, gb.x, gb.y, gb.z, gb.w};
    float bbv[8] = {ba.x, ba.y, ba.z, ba.w, bb.x, bb.y, bb.z, bb.w};

    float o8[8];
    union { __nv_bfloat16 b[8]; uint4 u; } uh, ul;
#pragma unroll
    for (int i = 0; i < 8; i++) {
        o8[i] = (v[i] - mean) * rstd * gg[i] + bbv[i];
        uh.b[i] = __float2bfloat16(o8[i]);
        ul.b[i] = __float2bfloat16(o8[i] - __bfloat162float(uh.b[i]));
    }

    float4* outp = (float4*)(out + (size_t)row * 256) + lane * 2;
    outp[0] = make_float4(o8[0], o8[1], o8[2], o8[3]);
    outp[1] = make_float4(o8[4], o8[5], o8[6], o8[7]);
    *(uint4*)(ohi + (size_t)row * 256 + lane * 8) = uh.u;
    *(uint4*)(olo + (size_t)row * 256 + lane * 8) = ul.u;
}

// ---------------------------------------------------------------------------
// Host orchestration.
// ---------------------------------------------------------------------------
static const int SMEM128 = 2 * (32768 + 2 * 128 * 128);   // 131072
static const int SMEM64  = 2 * (32768 + 2 * 64 * 128);    // 98304

extern "C" void kernel_launch(void* const* d_in, const int* in_sizes, int n_in,
                              void* d_out, int out_size)
{
    const float* x_author = (const float*)d_in[0];
    const float* x_paper  = (const float*)d_in[1];
    const float* ew_wb    = (const float*)d_in[2];
    const float* ew_w     = (const float*)d_in[3];
    const float* ew_c     = (const float*)d_in[4];
    const float* adapt_W  = (const float*)d_in[5];
    const float* adapt_b  = (const float*)d_in[6];
    const float* kW       = (const float*)d_in[7];
    const float* kb       = (const float*)d_in[8];
    const float* qW       = (const float*)d_in[9];
    const float* qb       = (const float*)d_in[10];
    const float* mW       = (const float*)d_in[11];
    const float* mb       = (const float*)d_in[12];
    const float* aW       = (const float*)d_in[13];
    const float* ab       = (const float*)d_in[14];
    const float* w_pri    = (const float*)d_in[15];
    const float* w_att    = (const float*)d_in[16];
    const float* w_msg    = (const float*)d_in[17];
    const float* skip     = (const float*)d_in[18];
    const float* ln_g     = (const float*)d_in[19];
    const float* ln_b     = (const float*)d_in[20];
    const float* out_W    = (const float*)d_in[21];
    const float* out_b    = (const float*)d_in[22];
    const int* src_wb     = (const int*)d_in[23];
    const int* dst_wb     = (const int*)d_in[24];
    const int* src_w      = (const int*)d_in[25];
    const int* dst_w      = (const int*)d_in[26];
    const int* src_c      = (const int*)d_in[27];
    const int* dst_c      = (const int*)d_in[28];
    (void)in_sizes; (void)n_in; (void)out_size;

    cudaFuncSetAttribute(hmma_gemm<128, false, false, false>, cudaFuncAttributeMaxDynamicSharedMemorySize, SMEM128);
    cudaFuncSetAttribute(hmma_gemm<128, false, false, true>,  cudaFuncAttributeMaxDynamicSharedMemorySize, SMEM128);
    cudaFuncSetAttribute(hmma_gemm<128, true, true, false>,   cudaFuncAttributeMaxDynamicSharedMemorySize, SMEM128);
    cudaFuncSetAttribute(hmma_gemm<64, false, false, false>,  cudaFuncAttributeMaxDynamicSharedMemorySize, SMEM64);

    float *feats_a, *feats_p;
    __half *proj_a, *proj_p;
    float *agg_a, *agg_p, *tr_a, *tr_p, *Wkp, *bkp, *Wmp, *bmp, *bias_p, *bias_a;
    __nv_bfloat16 *xa_hi, *xa_lo, *xp_hi, *xp_lo, *fa_hi, *fa_lo, *fp_hi, *fp_lo;
    __nv_bfloat16 *ga_hi, *ga_lo, *gp_hi, *gp_lo, *Whi, *Wlo;
#define SYM(var, sym) cudaGetSymbolAddress((void**)&var, sym)
    SYM(feats_a, g_feats_a); SYM(feats_p, g_feats_p);
    SYM(proj_a, g_proj_a); SYM(proj_p, g_proj_p);
    SYM(agg_a, g_agg_a); SYM(agg_p, g_agg_p);
    SYM(tr_a, g_tr_a); SYM(tr_p, g_tr_p);
    SYM(Wkp, g_Wk); SYM(bkp, g_bk); SYM(Wmp, g_Wm); SYM(bmp, g_bm);
    SYM(bias_p, g_bias_p); SYM(bias_a, g_bias_a);
    SYM(xa_hi, g_xa_hi); SYM(xa_lo, g_xa_lo); SYM(xp_hi, g_xp_hi); SYM(xp_lo, g_xp_lo);
    SYM(fa_hi, g_fa_hi); SYM(fa_lo, g_fa_lo); SYM(fp_hi, g_fp_hi); SYM(fp_lo, g_fp_lo);
    SYM(ga_hi, g_ga_hi); SYM(ga_lo, g_ga_lo); SYM(gp_hi, g_gp_hi); SYM(gp_lo, g_gp_lo);
    SYM(Whi, g_Whi); SYM(Wlo, g_Wlo);
#undef SYM

    float* fa[2] = {feats_a, feats_a + (size_t)NA * D};
    float* fp[2] = {feats_p, feats_p + (size_t)NP * D};

    const int GA = (NA + 127) / 128;   // 157
    const int GP = (NP + 127) / 128;   // 313

    // 0) weight prep
    combine_weights<<<dim3(12, 257), 256>>>(kW, kb, mW, mb, w_att, w_msg, Wkp, bkp, Wmp, bmp);
    transpose_split<<<dim3(8, 8, NSLOT), dim3(32, 8)>>>(adapt_W, qW, Wkp, Wmp, aW, out_W, Whi, Wlo);
    pack_bias<<<(LL * 2048 + 255) / 256, 256>>>(qb, bkp, bmp, bias_p, bias_a);

    // 1) split inputs, adapt + GELU (emits feats fp32 + hi/lo)
    split_hilo<<<(NA * D / 4 + 255) / 256, 256>>>(x_author, xa_hi, xa_lo, NA * D / 4);
    split_hilo<<<(NP * D / 4 + 255) / 256, 256>>>(x_paper, xp_hi, xp_lo, NP * D / 4);
    hmma_gemm<128, true, true, false><<<dim3(GA, 2), 512, SMEM128>>>(xa_hi, xa_lo, Whi, Wlo,
        adapt_b, fa[0], nullptr, fa_hi, fa_lo, NA, 256, 1.f);
    hmma_gemm<128, true, true, false><<<dim3(GP, 2), 512, SMEM128>>>(xp_hi, xp_lo, Whi + 65536, Wlo + 65536,
        adapt_b + 256, fp[0], nullptr, fp_hi, fp_lo, NP, 256, 1.f);

    for (int l = 0; l < LL; l++) {
        int cur = l & 1, nxt = 1 - cur;

        // batched projections -> fp16 proj buffers (OUTH epilogue)
        const size_t psl = (size_t)(2 + l * 8) * 65536;
        const size_t asl = (size_t)(2 + l * 8 + 5) * 65536;
        hmma_gemm<128, false, false, true><<<dim3(GP, PSTR / 128), 512, SMEM128>>>(fp_hi, fp_lo,
            Whi + psl, Wlo + psl, bias_p + l * PSTR, nullptr, proj_p, nullptr, nullptr, NP, PSTR, 1.f);
        hmma_gemm<128, false, false, true><<<dim3(GA, ASTR / 128), 512, SMEM128>>>(fa_hi, fa_lo,
            Whi + asl, Wlo + asl, bias_a + l * ASTR, nullptr, proj_a, nullptr, nullptr, NA, ASTR, 1.f);

        cudaMemsetAsync(agg_a, 0, (size_t)NA * D * sizeof(float), 0);
        cudaMemsetAsync(agg_p, 0, (size_t)NP * D * sizeof(float), 0);

        // WRITTEN_BY: dst author (q in proj_a), src paper (k/m in proj_p)
        edge_kernel<<<(E_WB + 7) / 8, 256>>>(proj_a, ASTR, proj_p + 256, proj_p + 768, PSTR,
            src_wb, dst_wb, ew_wb, w_pri + (l * 3 + 2) * 4, agg_a, E_WB);
        // WRITES: dst paper, src author
        edge_kernel<<<(E_W + 7) / 8, 256>>>(proj_p, PSTR, proj_a + 256, proj_a + 512, ASTR,
            src_w, dst_w, ew_w, w_pri + (l * 3 + 1) * 4, agg_p, E_W);
        // CITES: dst paper, src paper
        edge_kernel<<<(E_C + 7) / 8, 256>>>(proj_p, PSTR, proj_p + 512, proj_p + 1024, PSTR,
            src_c, dst_c, ew_c, w_pri + (l * 3 + 0) * 4, agg_p, E_C);

        // agg -> hi/lo, then a-projection (0.5 cross-relation mean via scale)
        split_hilo<<<(NA * D / 4 + 255) / 256, 256>>>(agg_a, ga_hi, ga_lo, NA * D / 4);
        split_hilo<<<(NP * D / 4 + 255) / 256, 256>>>(agg_p, gp_hi, gp_lo, NP * D / 4);
        const size_t aa = (size_t)(18 + l * 2 + 0) * 65536;
        const size_t ap = (size_t)(18 + l * 2 + 1) * 65536;
        hmma_gemm<128, false, false, false><<<dim3(GA, 2), 512, SMEM128>>>(ga_hi, ga_lo,
            Whi + aa, Wlo + aa, ab + (l * 2 + 0) * 256, tr_a, nullptr, nullptr, nullptr, NA, 256, 1.0f);
        hmma_gemm<128, false, false, false><<<dim3(GP, 2), 512, SMEM128>>>(gp_hi, gp_lo,
            Whi + ap, Wlo + ap, ab + (l * 2 + 1) * 256, tr_p, nullptr, nullptr, nullptr, NP, 256, 0.5f);

        // skip blend + LN (emits fp32 feats + hi/lo for next layer / out proj)
        ln_blend_kernel<<<(NA + 7) / 8, 256>>>(tr_a, fa[cur], ln_g + (l * 2 + 0) * 256,
            ln_b + (l * 2 + 0) * 256, skip, l * 3 + 0, fa[nxt], fa_hi, fa_lo, NA);
        ln_blend_kernel<<<(NP + 7) / 8, 256>>>(tr_p, fp[cur], ln_g + (l * 2 + 1) * 256,
            ln_b + (l * 2 + 1) * 256, skip, l * 3 + 1, fp[nxt], fp_hi, fp_lo, NP);
    }

    // output projection: paper feats (hi/lo from last LN) @ out_W + out_b
    hmma_gemm<64, false, false, false><<<dim3(GP, 1), 512, SMEM64>>>(fp_hi, fp_lo,
        Whi + (size_t)22 * 65536, Wlo + (size_t)22 * 65536,
        out_b, (float*)d_out, nullptr, nullptr, nullptr, NP, 64, 1.f);
}

// round 13
// speedup vs baseline: 1.6316x; 1.0395x over previous
#include <cuda_runtime.h>
#include <cuda_bf16.h>
#include <cuda_fp16.h>
#include <math.h>
#include <stdint.h>

// ---------------------------------------------------------------------------
// HGT forward. GEMMs: mma.sync bf16 hi/lo 3-term. Projections/edge data fp16.
// R13: CSR-based edge aggregation (warp per dst node, no atomics).
// ---------------------------------------------------------------------------
#define NA     20000
#define NP     40000
#define D      256
#define DOUT   64
#define LL     2
#define E_WB   150000
#define E_W    150000
#define E_C    300000
#define NSLOT  23
#define PSTR   1280   // paper proj row: q | k_wb | k_c | m_wb | m_c
#define ASTR   768    // author proj row: q | k_w | m_w

// ------------------------- device scratch ----------------------------------
__device__ float g_feats_a[2][NA * D];
__device__ float g_feats_p[2][NP * D];
__device__ __half g_proj_a[NA * ASTR];
__device__ __half g_proj_p[NP * PSTR];
__device__ float g_agg_a[NA * D];
__device__ float g_agg_p[NP * D];
__device__ float g_tr_a[NA * D];
__device__ float g_tr_p[NP * D];
__device__ float g_Wk[LL * 3 * D * D];
__device__ float g_bk[LL * 3 * D];
__device__ float g_Wm[LL * 3 * D * D];
__device__ float g_bm[LL * 3 * D];
__device__ float g_bias_p[LL * PSTR];
__device__ float g_bias_a[LL * ASTR];
// CSR scratch
__device__ int g_rp_wb[NA + 1], g_rp_w[NP + 1], g_rp_c[NP + 1];
__device__ int g_ei_wb[E_WB], g_ei_w[E_W], g_ei_c[E_C];
__device__ int g_cnt[NP + 1];
__device__ int g_bsum[64];
// bf16 hi/lo operands
__device__ __nv_bfloat16 g_xa_hi[NA * D], g_xa_lo[NA * D];
__device__ __nv_bfloat16 g_xp_hi[NP * D], g_xp_lo[NP * D];
__device__ __nv_bfloat16 g_fa_hi[NA * D], g_fa_lo[NA * D];
__device__ __nv_bfloat16 g_fp_hi[NP * D], g_fp_lo[NP * D];
__device__ __nv_bfloat16 g_ga_hi[NA * D], g_ga_lo[NA * D];
__device__ __nv_bfloat16 g_gp_hi[NP * D], g_gp_lo[NP * D];
__device__ __nv_bfloat16 g_Whi[NSLOT * D * D], g_Wlo[NSLOT * D * D];

// ------------------------- small helpers -----------------------------------
__device__ __forceinline__ uint32_t smem_u32(const void* p) {
    uint32_t a;
    asm("{ .reg .u64 t; cvta.to.shared.u64 t, %1; cvt.u32.u64 %0, t; }" : "=r"(a) : "l"(p));
    return a;
}
#define SWZ(off) ((off) ^ (((off) >> 3) & 0x70))

#define CPASYNC16(dst, src) \
    asm volatile("cp.async.cg.shared.global [%0], [%1], 16;" :: "r"(dst), "l"(src) : "memory")

#define LDSM_X4(r0, r1, r2, r3, addr)                                         \
    asm volatile("ldmatrix.sync.aligned.m8n8.x4.shared.b16 {%0,%1,%2,%3}, [%4];" \
                 : "=r"(r0), "=r"(r1), "=r"(r2), "=r"(r3) : "r"(addr))

#define MMA16816(d, a, b0, b1)                                                \
    asm volatile("mma.sync.aligned.m16n8k16.row.col.f32.bf16.bf16.f32 "       \
                 "{%0,%1,%2,%3}, {%4,%5,%6,%7}, {%8,%9}, {%0,%1,%2,%3};"      \
                 : "+f"((d)[0]), "+f"((d)[1]), "+f"((d)[2]), "+f"((d)[3])     \
                 : "r"((a)[0]), "r"((a)[1]), "r"((a)[2]), "r"((a)[3]),        \
                   "r"(b0), "r"(b1))

__device__ __forceinline__ float gelu_exact(float x) {
    return 0.5f * x * (1.0f + erff(x * 0.70710678118654752f));
}

// ---------------------------------------------------------------------------
// combine per-head w_att/w_msg into dense K/M projection weights (fp32).
// ---------------------------------------------------------------------------
__global__ void combine_weights(const float* __restrict__ kW, const float* __restrict__ kb,
                                const float* __restrict__ mW, const float* __restrict__ mb,
                                const float* __restrict__ w_att, const float* __restrict__ w_msg,
                                float* __restrict__ Wk, float* __restrict__ bk,
                                float* __restrict__ Wm, float* __restrict__ bm)
{
    int mat = blockIdx.x;
    int l = mat / 6;
    int r6 = mat % 6;
    int e = r6 / 2;
    int which = r6 % 2;
    int d = blockIdx.y;        // 0..256 (256 == bias row)
    int j = threadIdx.x;
    int h = j >> 6;
    int jj = j & 63;
    int st = (e == 1) ? 0 : 1;

    const float* W   = which ? mW : kW;
    const float* B   = which ? mb : kb;
    const float* att = which ? w_msg : w_att;

    const float* wrow;
    if (d < 256) wrow = W + (((size_t)(l * 2 + st) * 256 + d) * 256);
    else         wrow = B + ((size_t)(l * 2 + st) * 256);
    const float* a = att + ((size_t)((l * 3 + e) * 4 + h)) * 64 * 64;

    float s = 0.f;
#pragma unroll 8
    for (int c = 0; c < 64; c++)
        s += wrow[h * 64 + c] * a[c * 64 + jj];

    float* out  = which ? Wm : Wk;
    float* outb = which ? bm : bk;
    if (d < 256) out[((size_t)(l * 3 + e) * 256 + d) * 256 + j] = s;
    else         outb[(size_t)(l * 3 + e) * 256 + j] = s;
}

// ---------------------------------------------------------------------------
// Transpose + split weights into bf16 hi/lo, K-major [n][k].
// ---------------------------------------------------------------------------
__global__ void transpose_split(const float* __restrict__ adapt_W, const float* __restrict__ qW,
                                const float* __restrict__ Wk, const float* __restrict__ Wm,
                                const float* __restrict__ aW, const float* __restrict__ outW,
                                __nv_bfloat16* __restrict__ Whi, __nv_bfloat16* __restrict__ Wlo)
{
    int slot = blockIdx.z;
    const float* src; int NC = 256;
    if (slot < 2)        src = adapt_W + (size_t)slot * 65536;
    else if (slot < 18) {
        int l = (slot - 2) / 8, o = (slot - 2) % 8;
        switch (o) {
            case 0: src = qW + (size_t)(l * 2 + 1) * 65536; break;
            case 1: src = Wk + (size_t)(l * 3 + 2) * 65536; break;
            case 2: src = Wk + (size_t)(l * 3 + 0) * 65536; break;
            case 3: src = Wm + (size_t)(l * 3 + 2) * 65536; break;
            case 4: src = Wm + (size_t)(l * 3 + 0) * 65536; break;
            case 5: src = qW + (size_t)(l * 2 + 0) * 65536; break;
            case 6: src = Wk + (size_t)(l * 3 + 1) * 65536; break;
            default: src = Wm + (size_t)(l * 3 + 1) * 65536; break;
        }
    }
    else if (slot < 22)  src = aW + (size_t)(slot - 18) * 65536;
    else               { src = outW; NC = 64; }

    int k0 = blockIdx.x * 32, n0 = blockIdx.y * 32;
    if (n0 >= NC) return;
    int tx = threadIdx.x, ty = threadIdx.y;

    __shared__ float t[32][33];
#pragma unroll
    for (int i = 0; i < 4; i++) {
        int k = k0 + ty + i * 8;
        t[ty + i * 8][tx] = src[(size_t)k * NC + n0 + tx];
    }
    __syncthreads();
#pragma unroll
    for (int i = 0; i < 4; i++) {
        int n = n0 + ty + i * 8, k = k0 + tx;
        float v = t[tx][ty + i * 8];
        __nv_bfloat16 h = __float2bfloat16(v);
        float r = v - __bfloat162float(h);
        size_t o = (size_t)slot * 65536 + (size_t)n * 256 + k;
        Whi[o] = h;
        Wlo[o] = __float2bfloat16(r);
    }
}

// ---------------------------------------------------------------------------
// Pack per-layer projection biases into the batched column layout.
// ---------------------------------------------------------------------------
__global__ void pack_bias(const float* __restrict__ qb, const float* __restrict__ bk,
                          const float* __restrict__ bm,
                          float* __restrict__ bp, float* __restrict__ ba)
{
    int idx = blockIdx.x * 256 + threadIdx.x;
    if (idx >= LL * 2048) return;
    int l = idx / 2048, r = idx % 2048;
    int seg = r >> 8, c = r & 255;
    float v;
    switch (seg) {
        case 0: v = qb[(l * 2 + 1) * 256 + c]; break;
        case 1: v = bk[(l * 3 + 2) * 256 + c]; break;
        case 2: v = bk[(l * 3 + 0) * 256 + c]; break;
        case 3: v = bm[(l * 3 + 2) * 256 + c]; break;
        case 4: v = bm[(l * 3 + 0) * 256 + c]; break;
        case 5: v = qb[(l * 2 + 0) * 256 + c]; break;
        case 6: v = bk[(l * 3 + 1) * 256 + c]; break;
        default: v = bm[(l * 3 + 1) * 256 + c]; break;
    }
    if (seg < 5) bp[l * PSTR + seg * 256 + c] = v;
    else         ba[l * ASTR + (seg - 5) * 256 + c] = v;
}

// ---------------------------------------------------------------------------
// fp32 -> bf16 hi/lo split (vectorized).
// ---------------------------------------------------------------------------
__global__ void split_hilo(const float* __restrict__ s, __nv_bfloat16* __restrict__ hi,
                           __nv_bfloat16* __restrict__ lo, int n4)
{
    int i = blockIdx.x * blockDim.x + threadIdx.x;
    if (i >= n4) return;
    float4 v = ((const float4*)s)[i];
    __nv_bfloat16 h[4], l[4];
    float vv[4] = {v.x, v.y, v.z, v.w};
#pragma unroll
    for (int j = 0; j < 4; j++) {
        h[j] = __float2bfloat16(vv[j]);
        l[j] = __float2bfloat16(vv[j] - __bfloat162float(h[j]));
    }
    ((uint2*)hi)[i] = *(uint2*)h;
    ((uint2*)lo)[i] = *(uint2*)l;
}

// ---------------------------------------------------------------------------
// CSR build: count -> two-level exclusive scan -> fill (dst-sorted edge ids).
// ---------------------------------------------------------------------------
__global__ void count_edges(const int* __restrict__ dst, int* __restrict__ cnt, int E)
{
    int i = blockIdx.x * blockDim.x + threadIdx.x;
    if (i < E) atomicAdd(&cnt[dst[i]], 1);
}
__global__ void scan_block(const int* __restrict__ cnt, int* __restrict__ rp,
                           int* __restrict__ bsum, int n)
{
    __shared__ int sh[1024];
    int i = blockIdx.x * 1024 + threadIdx.x;
    sh[threadIdx.x] = (i < n) ? cnt[i] : 0;
    __syncthreads();
#pragma unroll
    for (int off = 1; off < 1024; off <<= 1) {
        int t = (threadIdx.x >= off) ? sh[threadIdx.x - off] : 0;
        __syncthreads();
        sh[threadIdx.x] += t;
        __syncthreads();
    }
    if (i < n) rp[i + 1] = sh[threadIdx.x];
    if (threadIdx.x == 1023) bsum[blockIdx.x] = sh[1023];
}
__global__ void scan_bsum(int* __restrict__ bsum, int nb)
{
    if (threadIdx.x == 0) {
        int run = 0;
        for (int i = 0; i < nb; i++) { int v = bsum[i]; bsum[i] = run; run += v; }
    }
}
__global__ void scan_add(int* __restrict__ rp, const int* __restrict__ bsum, int n)
{
    int i = blockIdx.x * 1024 + threadIdx.x;
    if (i < n) rp[i + 1] += bsum[blockIdx.x];
    if (blockIdx.x == 0 && threadIdx.x == 0) rp[0] = 0;
}
__global__ void copy_int(const int* __restrict__ a, int* __restrict__ b, int n)
{
    int i = blockIdx.x * blockDim.x + threadIdx.x;
    if (i < n) b[i] = a[i];
}
__global__ void fill_edges(const int* __restrict__ dst, int* __restrict__ cur,
                           int* __restrict__ ei, int E)
{
    int i = blockIdx.x * blockDim.x + threadIdx.x;
    if (i < E) ei[atomicAdd(&cur[dst[i]], 1)] = i;
}

// ---------------------------------------------------------------------------
// HMMA GEMM: epi( scale*(A @ W^T) + bias ). 512 threads, tile 128 x BN,
// warp tile 32 x BN/4, K chunks of 64, 2-stage cp.async, SW128 + ldmatrix.
// OUTH: fp16 output into Ch. HILO: bf16 hi/lo aux outputs.
// ---------------------------------------------------------------------------
#define A_HI_OFF  0
#define A_LO_OFF  16384

template <int BN, bool GELU, bool HILO, bool OUTH>
__global__ void __launch_bounds__(512, 1)
hmma_gemm(const __nv_bfloat16* __restrict__ Ahi, const __nv_bfloat16* __restrict__ Alo,
          const __nv_bfloat16* __restrict__ Whi, const __nv_bfloat16* __restrict__ Wlo,
          const float* __restrict__ bias, float* __restrict__ C,
          __half* __restrict__ Ch,
          __nv_bfloat16* __restrict__ Chi, __nv_bfloat16* __restrict__ Clo,
          int M, int Ntot, float scale)
{
    constexpr int WN = BN / 4;
    constexpr int NT = WN / 16;
    constexpr int B_HI_OFF = 32768;
    constexpr int B_LO_OFF = 32768 + BN * 128;
    constexpr int STG = 32768 + 2 * BN * 128;
    constexpr int A_OPS = 2048;
    constexpr int TOT_OPS = A_OPS + BN * 16;

    extern __shared__ __align__(1024) char sm[];
    const uint32_t sb = smem_u32(sm);

    const int tid = threadIdx.x;
    const int lane = tid & 31, wid = tid >> 5;
    const int wm = wid & 3, wn = wid >> 2;
    const int m0 = blockIdx.x * 128, n0 = blockIdx.y * BN;

    auto load_chunk = [&](int kc, int stg) {
        uint32_t base = sb + stg * STG;
        int kb = kc * 64;
#pragma unroll
        for (int it = tid; it < TOT_OPS; it += 512) {
            bool isA = it < A_OPS;
            int i = isA ? (it & 1023) : ((it - A_OPS) % (BN * 8));
            bool isHi = isA ? (it < 1024) : ((it - A_OPS) < BN * 8);
            int r = i >> 3, s = i & 7;
            uint32_t o = SWZ((uint32_t)(r * 128 + s * 16));
            if (isA) {
                if (m0 + r < M) {
                    const __nv_bfloat16* gp = (isHi ? Ahi : Alo) + (size_t)(m0 + r) * 256 + kb + s * 8;
                    CPASYNC16(base + (isHi ? A_HI_OFF : A_LO_OFF) + o, gp);
                }
            } else {
                const __nv_bfloat16* gp = (isHi ? Whi : Wlo) + (size_t)(n0 + r) * 256 + kb + s * 8;
                CPASYNC16(base + (isHi ? B_HI_OFF : B_LO_OFF) + o, gp);
            }
        }
        asm volatile("cp.async.commit_group;" ::: "memory");
    };

    float d[2][2 * NT][4];
#pragma unroll
    for (int i = 0; i < 2; i++)
#pragma unroll
        for (int j = 0; j < 2 * NT; j++)
#pragma unroll
            for (int r = 0; r < 4; r++) d[i][j][r] = 0.f;

    const int g = lane >> 3, l7 = lane & 7;
    const int a_row_off = (g & 1) ? 8 : 0;
    const int a_byte_off = (g & 2) ? 16 : 0;
    const int b_row_off = (g & 2) ? 8 : 0;
    const int b_byte_off = (g & 1) ? 16 : 0;

    load_chunk(0, 0);

    for (int kc = 0; kc < 4; kc++) {
        if (kc < 3) load_chunk(kc + 1, (kc + 1) & 1);
        if (kc < 3) asm volatile("cp.async.wait_group 1;" ::: "memory");
        else        asm volatile("cp.async.wait_group 0;" ::: "memory");
        __syncthreads();

        uint32_t base = sb + (kc & 1) * STG;
#pragma unroll
        for (int kk = 0; kk < 4; kk++) {
            int kb2 = kk * 32;
            uint32_t a_hi[2][4], a_lo[2][4], b_hi[NT][4], b_lo[NT][4];
#pragma unroll
            for (int i = 0; i < 2; i++) {
                uint32_t o = SWZ((uint32_t)((wm * 32 + i * 16 + l7 + a_row_off) * 128 + kb2 + a_byte_off));
                LDSM_X4(a_hi[i][0], a_hi[i][1], a_hi[i][2], a_hi[i][3], base + A_HI_OFF + o);
                LDSM_X4(a_lo[i][0], a_lo[i][1], a_lo[i][2], a_lo[i][3], base + A_LO_OFF + o);
            }
#pragma unroll
            for (int jt = 0; jt < NT; jt++) {
                uint32_t o = SWZ((uint32_t)((wn * WN + jt * 16 + l7 + b_row_off) * 128 + kb2 + b_byte_off));
                LDSM_X4(b_hi[jt][0], b_hi[jt][1], b_hi[jt][2], b_hi[jt][3], base + B_HI_OFF + o);
                LDSM_X4(b_lo[jt][0], b_lo[jt][1], b_lo[jt][2], b_lo[jt][3], base + B_LO_OFF + o);
            }
#pragma unroll
            for (int i = 0; i < 2; i++)
#pragma unroll
                for (int jt = 0; jt < NT; jt++)
#pragma unroll
                    for (int half = 0; half < 2; half++) {
                        int j = jt * 2 + half, sel = half * 2;
                        MMA16816(d[i][j], a_hi[i], b_hi[jt][sel], b_hi[jt][sel + 1]);
                        MMA16816(d[i][j], a_hi[i], b_lo[jt][sel], b_lo[jt][sel + 1]);
                        MMA16816(d[i][j], a_lo[i], b_hi[jt][sel], b_hi[jt][sel + 1]);
                    }
        }
        __syncthreads();
    }

    const int r_base = m0 + wm * 32;
    const int c_base = n0 + wn * WN;
#pragma unroll
    for (int i = 0; i < 2; i++)
#pragma unroll
        for (int j = 0; j < 2 * NT; j++) {
            int col = c_base + j * 8 + (lane & 3) * 2;
            float2 b2 = *(const float2*)(bias + col);
#pragma unroll
            for (int half = 0; half < 2; half++) {
                int row = r_base + i * 16 + (lane >> 2) + half * 8;
                if (row >= M) continue;
                float vx = d[i][j][half * 2 + 0] * scale + b2.x;
                float vy = d[i][j][half * 2 + 1] * scale + b2.y;
                if (GELU) { vx = gelu_exact(vx); vy = gelu_exact(vy); }
                if (OUTH) {
                    union { __half b[2]; uint32_t u; } ub;
                    ub.b[0] = __float2half_rn(vx);
                    ub.b[1] = __float2half_rn(vy);
                    *(uint32_t*)(Ch + (size_t)row * Ntot + col) = ub.u;
                } else {
                    *(float2*)(C + (size_t)row * Ntot + col) = make_float2(vx, vy);
                }
                if (HILO) {
                    union { __nv_bfloat16 b[2]; uint32_t u; } uh, ul;
                    uh.b[0] = __float2bfloat16(vx);
                    uh.b[1] = __float2bfloat16(vy);
                    ul.b[0] = __float2bfloat16(vx - __bfloat162float(uh.b[0]));
                    ul.b[1] = __float2bfloat16(vy - __bfloat162float(uh.b[1]));
                    *(uint32_t*)(Chi + (size_t)row * Ntot + col) = uh.u;
                    *(uint32_t*)(Clo + (size_t)row * Ntot + col) = ul.u;
                }
            }
        }
}

// ---------------------------------------------------------------------------
// CSR aggregation: one warp per dst node. q row held in registers; in-edges
// gathered (k, m fp16 rows), fp32 score/attn/accumulate; single fp32 store.
// ACC=true adds to existing agg (second relation targeting same dst type).
// ---------------------------------------------------------------------------
template <bool ACC>
__global__ void csr_agg(const int* __restrict__ rp, const int* __restrict__ ei,
                        const int* __restrict__ src, const float* __restrict__ ew,
                        const float* __restrict__ pri,
                        const __half* __restrict__ q, int qs,
                        const __half* __restrict__ khat, const __half* __restrict__ mhat, int kms,
                        float* __restrict__ agg, int N)
{
    int node = (int)((blockIdx.x * (size_t)blockDim.x + threadIdx.x) >> 5);
    int lane = threadIdx.x & 31;
    if (node >= N) return;

    int beg = rp[node], end = rp[node + 1];
    float prih = pri[lane >> 3] * 0.125f;

    union { uint4 u; __half2 h2[4]; } qv;
    qv.u = *(const uint4*)(q + (size_t)node * qs + lane * 8);
    float qf[8];
#pragma unroll
    for (int i = 0; i < 4; i++) {
        float2 f = __half22float2(qv.h2[i]);
        qf[2 * i] = f.x; qf[2 * i + 1] = f.y;
    }

    float acc[8];
    float* out = agg + (size_t)node * 256 + lane * 8;
    if (ACC) {
        float4 a0 = *(float4*)out, a1 = *(float4*)(out + 4);
        acc[0] = a0.x; acc[1] = a0.y; acc[2] = a0.z; acc[3] = a0.w;
        acc[4] = a1.x; acc[5] = a1.y; acc[6] = a1.z; acc[7] = a1.w;
    } else {
#pragma unroll
        for (int i = 0; i < 8; i++) acc[i] = 0.f;
    }

    for (int j = beg; j < end; j++) {
        int eid = ei[j];
        int s = src[eid];
        union { uint4 u; __half2 h2[4]; } kv, mv;
        kv.u = *(const uint4*)(khat + (size_t)s * kms + lane * 8);
        mv.u = *(const uint4*)(mhat + (size_t)s * kms + lane * 8);

        float p = 0.f;
#pragma unroll
        for (int i = 0; i < 4; i++) {
            float2 kf = __half22float2(kv.h2[i]);
            p += qf[2 * i] * kf.x + qf[2 * i + 1] * kf.y;
        }
        p += __shfl_xor_sync(0xffffffffu, p, 1);
        p += __shfl_xor_sync(0xffffffffu, p, 2);
        p += __shfl_xor_sync(0xffffffffu, p, 4);

        float attn = ew[eid] / (1.f + __expf(-p * prih));
#pragma unroll
        for (int i = 0; i < 4; i++) {
            float2 mf = __half22float2(mv.h2[i]);
            acc[2 * i]     += mf.x * attn;
            acc[2 * i + 1] += mf.y * attn;
        }
    }

    *(float4*)out       = make_float4(acc[0], acc[1], acc[2], acc[3]);
    *(float4*)(out + 4) = make_float4(acc[4], acc[5], acc[6], acc[7]);
}

// ---------------------------------------------------------------------------
// Skip-blend + LayerNorm; also emits bf16 hi/lo of the output.
// ---------------------------------------------------------------------------
__global__ void ln_blend_kernel(const float* __restrict__ tr, const float* __restrict__ feats,
                                const float* __restrict__ g, const float* __restrict__ b,
                                const float* __restrict__ skip, int skip_idx,
                                float* __restrict__ out,
                                __nv_bfloat16* __restrict__ ohi, __nv_bfloat16* __restrict__ olo,
                                int N)
{
    int row = (int)((blockIdx.x * (size_t)blockDim.x + threadIdx.x) >> 5);
    int lane = threadIdx.x & 31;
    if (row >= N) return;

    float alpha = 1.f / (1.f + __expf(-skip[skip_idx]));
    float beta = 1.f - alpha;

    const float4* t4 = (const float4*)(tr    + (size_t)row * 256) + lane * 2;
    const float4* f4 = (const float4*)(feats + (size_t)row * 256) + lane * 2;
    float4 ta = t4[0], tb = t4[1], fa = f4[0], fb = f4[1];

    float v[8];
    v[0] = ta.x * alpha + fa.x * beta;  v[1] = ta.y * alpha + fa.y * beta;
    v[2] = ta.z * alpha + fa.z * beta;  v[3] = ta.w * alpha + fa.w * beta;
    v[4] = tb.x * alpha + fb.x * beta;  v[5] = tb.y * alpha + fb.y * beta;
    v[6] = tb.z * alpha + fb.z * beta;  v[7] = tb.w * alpha + fb.w * beta;

    float s = 0.f;
#pragma unroll
    for (int i = 0; i < 8; i++) s += v[i];
#pragma unroll
    for (int o = 16; o > 0; o >>= 1) s += __shfl_xor_sync(0xffffffffu, s, o);
    float mean = s * (1.f / 256.f);

    float sq = 0.f;
#pragma unroll
    for (int i = 0; i < 8; i++) { float dv = v[i] - mean; sq += dv * dv; }
#pragma unroll
    for (int o = 16; o > 0; o >>= 1) sq += __shfl_xor_sync(0xffffffffu, sq, o);
    float rstd = rsqrtf(sq * (1.f / 256.f) + 1e-5f);

    const float4* g4 = (const float4*)(g) + lane * 2;
    const float4* b4 = (const float4*)(b) + lane * 2;
    float4 ga = g4[0], gb = g4[1], ba = b4[0], bb = b4[1];
    float gg[8] = {ga.x, ga.y, ga.z, ga.w, gb.x, gb.y, gb.z, gb.w};
    float bbv[8] = {ba.x, ba.y, ba.z, ba.w, bb.x, bb.y, bb.z, bb.w};

    float o8[8];
    union { __nv_bfloat16 b[8]; uint4 u; } uh, ul;
#pragma unroll
    for (int i = 0; i < 8; i++) {
        o8[i] = (v[i] - mean) * rstd * gg[i] + bbv[i];
        uh.b[i] = __float2bfloat16(o8[i]);
        ul.b[i] = __float2bfloat16(o8[i] - __bfloat162float(uh.b[i]));
    }

    float4* outp = (float4*)(out + (size_t)row * 256) + lane * 2;
    outp[0] = make_float4(o8[0], o8[1], o8[2], o8[3]);
    outp[1] = make_float4(o8[4], o8[5], o8[6], o8[7]);
    *(uint4*)(ohi + (size_t)row * 256 + lane * 8) = uh.u;
    *(uint4*)(olo + (size_t)row * 256 + lane * 8) = ul.u;
}

// ---------------------------------------------------------------------------
// Host orchestration.
// ---------------------------------------------------------------------------
static const int SMEM128 = 2 * (32768 + 2 * 128 * 128);   // 131072
static const int SMEM64  = 2 * (32768 + 2 * 64 * 128);    // 98304

static void build_csr(const int* dst, int* cnt, int* rp, int* ei, int* bsum, int N, int E)
{
    cudaMemsetAsync(cnt, 0, (size_t)(N + 1) * sizeof(int), 0);
    count_edges<<<(E + 255) / 256, 256>>>(dst, cnt, E);
    int nb = (N + 1023) / 1024;
    scan_block<<<nb, 1024>>>(cnt, rp, bsum, N);
    scan_bsum<<<1, 32>>>(bsum, nb);
    scan_add<<<nb, 1024>>>(rp, bsum, N);
    copy_int<<<(N + 255) / 256, 256>>>(rp, cnt, N);
    fill_edges<<<(E + 255) / 256, 256>>>(dst, cnt, ei, E);
}

extern "C" void kernel_launch(void* const* d_in, const int* in_sizes, int n_in,
                              void* d_out, int out_size)
{
    const float* x_author = (const float*)d_in[0];
    const float* x_paper  = (const float*)d_in[1];
    const float* ew_wb    = (const float*)d_in[2];
    const float* ew_w     = (const float*)d_in[3];
    const float* ew_c     = (const float*)d_in[4];
    const float* adapt_W  = (const float*)d_in[5];
    const float* adapt_b  = (const float*)d_in[6];
    const float* kW       = (const float*)d_in[7];
    const float* kb       = (const float*)d_in[8];
    const float* qW       = (const float*)d_in[9];
    const float* qb       = (const float*)d_in[10];
    const float* mW       = (const float*)d_in[11];
    const float* mb       = (const float*)d_in[12];
    const float* aW       = (const float*)d_in[13];
    const float* ab       = (const float*)d_in[14];
    const float* w_pri    = (const float*)d_in[15];
    const float* w_att    = (const float*)d_in[16];
    const float* w_msg    = (const float*)d_in[17];
    const float* skip     = (const float*)d_in[18];
    const float* ln_g     = (const float*)d_in[19];
    const float* ln_b     = (const float*)d_in[20];
    const float* out_W    = (const float*)d_in[21];
    const float* out_b    = (const float*)d_in[22];
    const int* src_wb     = (const int*)d_in[23];
    const int* dst_wb     = (const int*)d_in[24];
    const int* src_w      = (const int*)d_in[25];
    const int* dst_w      = (const int*)d_in[26];
    const int* src_c      = (const int*)d_in[27];
    const int* dst_c      = (const int*)d_in[28];
    (void)in_sizes; (void)n_in; (void)out_size;

    cudaFuncSetAttribute(hmma_gemm<128, false, false, false>, cudaFuncAttributeMaxDynamicSharedMemorySize, SMEM128);
    cudaFuncSetAttribute(hmma_gemm<128, false, false, true>,  cudaFuncAttributeMaxDynamicSharedMemorySize, SMEM128);
    cudaFuncSetAttribute(hmma_gemm<128, true, true, false>,   cudaFuncAttributeMaxDynamicSharedMemorySize, SMEM128);
    cudaFuncSetAttribute(hmma_gemm<64, false, false, false>,  cudaFuncAttributeMaxDynamicSharedMemorySize, SMEM64);

    float *feats_a, *feats_p;
    __half *proj_a, *proj_p;
    float *agg_a, *agg_p, *tr_a, *tr_p, *Wkp, *bkp, *Wmp, *bmp, *bias_p, *bias_a;
    int *rp_wb, *rp_w, *rp_c, *ei_wb, *ei_w, *ei_c, *cnt, *bsum;
    __nv_bfloat16 *xa_hi, *xa_lo, *xp_hi, *xp_lo, *fa_hi, *fa_lo, *fp_hi, *fp_lo;
    __nv_bfloat16 *ga_hi, *ga_lo, *gp_hi, *gp_lo, *Whi, *Wlo;
#define SYM(var, sym) cudaGetSymbolAddress((void**)&var, sym)
    SYM(feats_a, g_feats_a); SYM(feats_p, g_feats_p);
    SYM(proj_a, g_proj_a); SYM(proj_p, g_proj_p);
    SYM(agg_a, g_agg_a); SYM(agg_p, g_agg_p);
    SYM(tr_a, g_tr_a); SYM(tr_p, g_tr_p);
    SYM(Wkp, g_Wk); SYM(bkp, g_bk); SYM(Wmp, g_Wm); SYM(bmp, g_bm);
    SYM(bias_p, g_bias_p); SYM(bias_a, g_bias_a);
    SYM(rp_wb, g_rp_wb); SYM(rp_w, g_rp_w); SYM(rp_c, g_rp_c);
    SYM(ei_wb, g_ei_wb); SYM(ei_w, g_ei_w); SYM(ei_c, g_ei_c);
    SYM(cnt, g_cnt); SYM(bsum, g_bsum);
    SYM(xa_hi, g_xa_hi); SYM(xa_lo, g_xa_lo); SYM(xp_hi, g_xp_hi); SYM(xp_lo, g_xp_lo);
    SYM(fa_hi, g_fa_hi); SYM(fa_lo, g_fa_lo); SYM(fp_hi, g_fp_hi); SYM(fp_lo, g_fp_lo);
    SYM(ga_hi, g_ga_hi); SYM(ga_lo, g_ga_lo); SYM(gp_hi, g_gp_hi); SYM(gp_lo, g_gp_lo);
    SYM(Whi, g_Whi); SYM(Wlo, g_Wlo);
#undef SYM

    float* fa[2] = {feats_a, feats_a + (size_t)NA * D};
    float* fp[2] = {feats_p, feats_p + (size_t)NP * D};

    const int GA = (NA + 127) / 128;   // 157
    const int GP = (NP + 127) / 128;   // 313

    // 0) weight prep + CSR build (graph static; once per launch)
    combine_weights<<<dim3(12, 257), 256>>>(kW, kb, mW, mb, w_att, w_msg, Wkp, bkp, Wmp, bmp);
    transpose_split<<<dim3(8, 8, NSLOT), dim3(32, 8)>>>(adapt_W, qW, Wkp, Wmp, aW, out_W, Whi, Wlo);
    pack_bias<<<(LL * 2048 + 255) / 256, 256>>>(qb, bkp, bmp, bias_p, bias_a);
    build_csr(dst_wb, cnt, rp_wb, ei_wb, bsum, NA, E_WB);
    build_csr(dst_w,  cnt, rp_w,  ei_w,  bsum, NP, E_W);
    build_csr(dst_c,  cnt, rp_c,  ei_c,  bsum, NP, E_C);

    // 1) split inputs, adapt + GELU (emits feats fp32 + hi/lo)
    split_hilo<<<(NA * D / 4 + 255) / 256, 256>>>(x_author, xa_hi, xa_lo, NA * D / 4);
    split_hilo<<<(NP * D / 4 + 255) / 256, 256>>>(x_paper, xp_hi, xp_lo, NP * D / 4);
    hmma_gemm<128, true, true, false><<<dim3(GA, 2), 512, SMEM128>>>(xa_hi, xa_lo, Whi, Wlo,
        adapt_b, fa[0], nullptr, fa_hi, fa_lo, NA, 256, 1.f);
    hmma_gemm<128, true, true, false><<<dim3(GP, 2), 512, SMEM128>>>(xp_hi, xp_lo, Whi + 65536, Wlo + 65536,
        adapt_b + 256, fp[0], nullptr, fp_hi, fp_lo, NP, 256, 1.f);

    for (int l = 0; l < LL; l++) {
        int cur = l & 1, nxt = 1 - cur;

        // batched projections -> fp16 proj buffers
        const size_t psl = (size_t)(2 + l * 8) * 65536;
        const size_t asl = (size_t)(2 + l * 8 + 5) * 65536;
        hmma_gemm<128, false, false, true><<<dim3(GP, PSTR / 128), 512, SMEM128>>>(fp_hi, fp_lo,
            Whi + psl, Wlo + psl, bias_p + l * PSTR, nullptr, proj_p, nullptr, nullptr, NP, PSTR, 1.f);
        hmma_gemm<128, false, false, true><<<dim3(GA, ASTR / 128), 512, SMEM128>>>(fa_hi, fa_lo,
            Whi + asl, Wlo + asl, bias_a + l * ASTR, nullptr, proj_a, nullptr, nullptr, NA, ASTR, 1.f);

        // CSR aggregation, warp per dst (no atomics, no memsets)
        // WRITTEN_BY: dst author, src paper
        csr_agg<false><<<(NA * 32 + 255) / 256, 256>>>(rp_wb, ei_wb, src_wb, ew_wb,
            w_pri + (l * 3 + 2) * 4, proj_a, ASTR, proj_p + 256, proj_p + 768, PSTR, agg_a, NA);
        // WRITES: dst paper, src author
        csr_agg<false><<<(NP * 32 + 255) / 256, 256>>>(rp_w, ei_w, src_w, ew_w,
            w_pri + (l * 3 + 1) * 4, proj_p, PSTR, proj_a + 256, proj_a + 512, ASTR, agg_p, NP);
        // CITES: dst paper, src paper (accumulate)
        csr_agg<true><<<(NP * 32 + 255) / 256, 256>>>(rp_c, ei_c, src_c, ew_c,
            w_pri + (l * 3 + 0) * 4, proj_p, PSTR, proj_p + 512, proj_p + 1024, PSTR, agg_p, NP);

        // agg -> hi/lo, then a-projection (0.5 cross-relation mean via scale)
        split_hilo<<<(NA * D / 4 + 255) / 256, 256>>>(agg_a, ga_hi, ga_lo, NA * D / 4);
        split_hilo<<<(NP * D / 4 + 255) / 256, 256>>>(agg_p, gp_hi, gp_lo, NP * D / 4);
        const size_t aa = (size_t)(18 + l * 2 + 0) * 65536;
        const size_t ap = (size_t)(18 + l * 2 + 1) * 65536;
        hmma_gemm<128, false, false, false><<<dim3(GA, 2), 512, SMEM128>>>(ga_hi, ga_lo,
            Whi + aa, Wlo + aa, ab + (l * 2 + 0) * 256, tr_a, nullptr, nullptr, nullptr, NA, 256, 1.0f);
        hmma_gemm<128, false, false, false><<<dim3(GP, 2), 512, SMEM128>>>(gp_hi, gp_lo,
            Whi + ap, Wlo + ap, ab + (l * 2 + 1) * 256, tr_p, nullptr, nullptr, nullptr, NP, 256, 0.5f);

        // skip blend + LN (emits fp32 feats + hi/lo for next layer / out proj)
        ln_blend_kernel<<<(NA + 7) / 8, 256>>>(tr_a, fa[cur], ln_g + (l * 2 + 0) * 256,
            ln_b + (l * 2 + 0) * 256, skip, l * 3 + 0, fa[nxt], fa_hi, fa_lo, NA);
        ln_blend_kernel<<<(NP + 7) / 8, 256>>>(tr_p, fp[cur], ln_g + (l * 2 + 1) * 256,
            ln_b + (l * 2 + 1) * 256, skip, l * 3 + 1, fp[nxt], fp_hi, fp_lo, NP);
    }

    // output projection: paper feats (hi/lo from last LN) @ out_W + out_b
    hmma_gemm<64, false, false, false><<<dim3(GP, 1), 512, SMEM64>>>(fp_hi, fp_lo,
        Whi + (size_t)22 * 65536, Wlo + (size_t)22 * 65536,
        out_b, (float*)d_out, nullptr, nullptr, nullptr, NP, 64, 1.f);
}

// round 14
// speedup vs baseline: 1.6727x; 1.0252x over previous
#include <cuda_runtime.h>
#include <cuda_bf16.h>
#include <cuda_fp16.h>
#include <math.h>
#include <stdint.h>

// ---------------------------------------------------------------------------
// HGT forward. GEMMs: mma.sync bf16 hi/lo 3-term. Projections/edge data fp16.
// R14: csr_agg emits bf16 hi/lo directly (agg fp32 round trip removed).
// ---------------------------------------------------------------------------
#define NA     20000
#define NP     40000
#define D      256
#define DOUT   64
#define LL     2
#define E_WB   150000
#define E_W    150000
#define E_C    300000
#define NSLOT  23
#define PSTR   1280   // paper proj row: q | k_wb | k_c | m_wb | m_c
#define ASTR   768    // author proj row: q | k_w | m_w

// ------------------------- device scratch ----------------------------------
__device__ float g_feats_a[2][NA * D];
__device__ float g_feats_p[2][NP * D];
__device__ __half g_proj_a[NA * ASTR];
__device__ __half g_proj_p[NP * PSTR];
__device__ float g_agg_p[NP * D];
__device__ float g_tr_a[NA * D];
__device__ float g_tr_p[NP * D];
__device__ float g_Wk[LL * 3 * D * D];
__device__ float g_bk[LL * 3 * D];
__device__ float g_Wm[LL * 3 * D * D];
__device__ float g_bm[LL * 3 * D];
__device__ float g_bias_p[LL * PSTR];
__device__ float g_bias_a[LL * ASTR];
// CSR scratch
__device__ int g_rp_wb[NA + 1], g_rp_w[NP + 1], g_rp_c[NP + 1];
__device__ int g_ei_wb[E_WB], g_ei_w[E_W], g_ei_c[E_C];
__device__ int g_cnt[NP + 1];
__device__ int g_bsum[64];
// bf16 hi/lo operands
__device__ __nv_bfloat16 g_xa_hi[NA * D], g_xa_lo[NA * D];
__device__ __nv_bfloat16 g_xp_hi[NP * D], g_xp_lo[NP * D];
__device__ __nv_bfloat16 g_fa_hi[NA * D], g_fa_lo[NA * D];
__device__ __nv_bfloat16 g_fp_hi[NP * D], g_fp_lo[NP * D];
__device__ __nv_bfloat16 g_ga_hi[NA * D], g_ga_lo[NA * D];
__device__ __nv_bfloat16 g_gp_hi[NP * D], g_gp_lo[NP * D];
__device__ __nv_bfloat16 g_Whi[NSLOT * D * D], g_Wlo[NSLOT * D * D];

// ------------------------- small helpers -----------------------------------
__device__ __forceinline__ uint32_t smem_u32(const void* p) {
    uint32_t a;
    asm("{ .reg .u64 t; cvta.to.shared.u64 t, %1; cvt.u32.u64 %0, t; }" : "=r"(a) : "l"(p));
    return a;
}
#define SWZ(off) ((off) ^ (((off) >> 3) & 0x70))

#define CPASYNC16(dst, src) \
    asm volatile("cp.async.cg.shared.global [%0], [%1], 16;" :: "r"(dst), "l"(src) : "memory")

#define LDSM_X4(r0, r1, r2, r3, addr)                                         \
    asm volatile("ldmatrix.sync.aligned.m8n8.x4.shared.b16 {%0,%1,%2,%3}, [%4];" \
                 : "=r"(r0), "=r"(r1), "=r"(r2), "=r"(r3) : "r"(addr))

#define MMA16816(d, a, b0, b1)                                                \
    asm volatile("mma.sync.aligned.m16n8k16.row.col.f32.bf16.bf16.f32 "       \
                 "{%0,%1,%2,%3}, {%4,%5,%6,%7}, {%8,%9}, {%0,%1,%2,%3};"      \
                 : "+f"((d)[0]), "+f"((d)[1]), "+f"((d)[2]), "+f"((d)[3])     \
                 : "r"((a)[0]), "r"((a)[1]), "r"((a)[2]), "r"((a)[3]),        \
                   "r"(b0), "r"(b1))

__device__ __forceinline__ float gelu_exact(float x) {
    return 0.5f * x * (1.0f + erff(x * 0.70710678118654752f));
}

// ---------------------------------------------------------------------------
// combine per-head w_att/w_msg into dense K/M projection weights (fp32).
// ---------------------------------------------------------------------------
__global__ void combine_weights(const float* __restrict__ kW, const float* __restrict__ kb,
                                const float* __restrict__ mW, const float* __restrict__ mb,
                                const float* __restrict__ w_att, const float* __restrict__ w_msg,
                                float* __restrict__ Wk, float* __restrict__ bk,
                                float* __restrict__ Wm, float* __restrict__ bm)
{
    int mat = blockIdx.x;
    int l = mat / 6;
    int r6 = mat % 6;
    int e = r6 / 2;
    int which = r6 % 2;
    int d = blockIdx.y;        // 0..256 (256 == bias row)
    int j = threadIdx.x;
    int h = j >> 6;
    int jj = j & 63;
    int st = (e == 1) ? 0 : 1;

    const float* W   = which ? mW : kW;
    const float* B   = which ? mb : kb;
    const float* att = which ? w_msg : w_att;

    const float* wrow;
    if (d < 256) wrow = W + (((size_t)(l * 2 + st) * 256 + d) * 256);
    else         wrow = B + ((size_t)(l * 2 + st) * 256);
    const float* a = att + ((size_t)((l * 3 + e) * 4 + h)) * 64 * 64;

    float s = 0.f;
#pragma unroll 8
    for (int c = 0; c < 64; c++)
        s += wrow[h * 64 + c] * a[c * 64 + jj];

    float* out  = which ? Wm : Wk;
    float* outb = which ? bm : bk;
    if (d < 256) out[((size_t)(l * 3 + e) * 256 + d) * 256 + j] = s;
    else         outb[(size_t)(l * 3 + e) * 256 + j] = s;
}

// ---------------------------------------------------------------------------
// Transpose + split weights into bf16 hi/lo, K-major [n][k].
// ---------------------------------------------------------------------------
__global__ void transpose_split(const float* __restrict__ adapt_W, const float* __restrict__ qW,
                                const float* __restrict__ Wk, const float* __restrict__ Wm,
                                const float* __restrict__ aW, const float* __restrict__ outW,
                                __nv_bfloat16* __restrict__ Whi, __nv_bfloat16* __restrict__ Wlo)
{
    int slot = blockIdx.z;
    const float* src; int NC = 256;
    if (slot < 2)        src = adapt_W + (size_t)slot * 65536;
    else if (slot < 18) {
        int l = (slot - 2) / 8, o = (slot - 2) % 8;
        switch (o) {
            case 0: src = qW + (size_t)(l * 2 + 1) * 65536; break;
            case 1: src = Wk + (size_t)(l * 3 + 2) * 65536; break;
            case 2: src = Wk + (size_t)(l * 3 + 0) * 65536; break;
            case 3: src = Wm + (size_t)(l * 3 + 2) * 65536; break;
            case 4: src = Wm + (size_t)(l * 3 + 0) * 65536; break;
            case 5: src = qW + (size_t)(l * 2 + 0) * 65536; break;
            case 6: src = Wk + (size_t)(l * 3 + 1) * 65536; break;
            default: src = Wm + (size_t)(l * 3 + 1) * 65536; break;
        }
    }
    else if (slot < 22)  src = aW + (size_t)(slot - 18) * 65536;
    else               { src = outW; NC = 64; }

    int k0 = blockIdx.x * 32, n0 = blockIdx.y * 32;
    if (n0 >= NC) return;
    int tx = threadIdx.x, ty = threadIdx.y;

    __shared__ float t[32][33];
#pragma unroll
    for (int i = 0; i < 4; i++) {
        int k = k0 + ty + i * 8;
        t[ty + i * 8][tx] = src[(size_t)k * NC + n0 + tx];
    }
    __syncthreads();
#pragma unroll
    for (int i = 0; i < 4; i++) {
        int n = n0 + ty + i * 8, k = k0 + tx;
        float v = t[tx][ty + i * 8];
        __nv_bfloat16 h = __float2bfloat16(v);
        float r = v - __bfloat162float(h);
        size_t o = (size_t)slot * 65536 + (size_t)n * 256 + k;
        Whi[o] = h;
        Wlo[o] = __float2bfloat16(r);
    }
}

// ---------------------------------------------------------------------------
// Pack per-layer projection biases into the batched column layout.
// ---------------------------------------------------------------------------
__global__ void pack_bias(const float* __restrict__ qb, const float* __restrict__ bk,
                          const float* __restrict__ bm,
                          float* __restrict__ bp, float* __restrict__ ba)
{
    int idx = blockIdx.x * 256 + threadIdx.x;
    if (idx >= LL * 2048) return;
    int l = idx / 2048, r = idx % 2048;
    int seg = r >> 8, c = r & 255;
    float v;
    switch (seg) {
        case 0: v = qb[(l * 2 + 1) * 256 + c]; break;
        case 1: v = bk[(l * 3 + 2) * 256 + c]; break;
        case 2: v = bk[(l * 3 + 0) * 256 + c]; break;
        case 3: v = bm[(l * 3 + 2) * 256 + c]; break;
        case 4: v = bm[(l * 3 + 0) * 256 + c]; break;
        case 5: v = qb[(l * 2 + 0) * 256 + c]; break;
        case 6: v = bk[(l * 3 + 1) * 256 + c]; break;
        default: v = bm[(l * 3 + 1) * 256 + c]; break;
    }
    if (seg < 5) bp[l * PSTR + seg * 256 + c] = v;
    else         ba[l * ASTR + (seg - 5) * 256 + c] = v;
}

// ---------------------------------------------------------------------------
// fp32 -> bf16 hi/lo split (vectorized) — inputs only.
// ---------------------------------------------------------------------------
__global__ void split_hilo(const float* __restrict__ s, __nv_bfloat16* __restrict__ hi,
                           __nv_bfloat16* __restrict__ lo, int n4)
{
    int i = blockIdx.x * blockDim.x + threadIdx.x;
    if (i >= n4) return;
    float4 v = ((const float4*)s)[i];
    __nv_bfloat16 h[4], l[4];
    float vv[4] = {v.x, v.y, v.z, v.w};
#pragma unroll
    for (int j = 0; j < 4; j++) {
        h[j] = __float2bfloat16(vv[j]);
        l[j] = __float2bfloat16(vv[j] - __bfloat162float(h[j]));
    }
    ((uint2*)hi)[i] = *(uint2*)h;
    ((uint2*)lo)[i] = *(uint2*)l;
}

// ---------------------------------------------------------------------------
// CSR build: count -> two-level exclusive scan -> fill (dst-sorted edge ids).
// ---------------------------------------------------------------------------
__global__ void count_edges(const int* __restrict__ dst, int* __restrict__ cnt, int E)
{
    int i = blockIdx.x * blockDim.x + threadIdx.x;
    if (i < E) atomicAdd(&cnt[dst[i]], 1);
}
__global__ void scan_block(const int* __restrict__ cnt, int* __restrict__ rp,
                           int* __restrict__ bsum, int n)
{
    __shared__ int sh[1024];
    int i = blockIdx.x * 1024 + threadIdx.x;
    sh[threadIdx.x] = (i < n) ? cnt[i] : 0;
    __syncthreads();
#pragma unroll
    for (int off = 1; off < 1024; off <<= 1) {
        int t = (threadIdx.x >= off) ? sh[threadIdx.x - off] : 0;
        __syncthreads();
        sh[threadIdx.x] += t;
        __syncthreads();
    }
    if (i < n) rp[i + 1] = sh[threadIdx.x];
    if (threadIdx.x == 1023) bsum[blockIdx.x] = sh[1023];
}
__global__ void scan_bsum(int* __restrict__ bsum, int nb)
{
    if (threadIdx.x == 0) {
        int run = 0;
        for (int i = 0; i < nb; i++) { int v = bsum[i]; bsum[i] = run; run += v; }
    }
}
__global__ void scan_add(int* __restrict__ rp, const int* __restrict__ bsum, int n)
{
    int i = blockIdx.x * 1024 + threadIdx.x;
    if (i < n) rp[i + 1] += bsum[blockIdx.x];
    if (blockIdx.x == 0 && threadIdx.x == 0) rp[0] = 0;
}
__global__ void copy_int(const int* __restrict__ a, int* __restrict__ b, int n)
{
    int i = blockIdx.x * blockDim.x + threadIdx.x;
    if (i < n) b[i] = a[i];
}
__global__ void fill_edges(const int* __restrict__ dst, int* __restrict__ cur,
                           int* __restrict__ ei, int E)
{
    int i = blockIdx.x * blockDim.x + threadIdx.x;
    if (i < E) ei[atomicAdd(&cur[dst[i]], 1)] = i;
}

// ---------------------------------------------------------------------------
// HMMA GEMM: epi( scale*(A @ W^T) + bias ). 512 threads, tile 128 x BN,
// warp tile 32 x BN/4, K chunks of 64, 2-stage cp.async, SW128 + ldmatrix.
// OUTH: fp16 output into Ch. HILO: bf16 hi/lo aux outputs.
// ---------------------------------------------------------------------------
#define A_HI_OFF  0
#define A_LO_OFF  16384

template <int BN, bool GELU, bool HILO, bool OUTH>
__global__ void __launch_bounds__(512, 1)
hmma_gemm(const __nv_bfloat16* __restrict__ Ahi, const __nv_bfloat16* __restrict__ Alo,
          const __nv_bfloat16* __restrict__ Whi, const __nv_bfloat16* __restrict__ Wlo,
          const float* __restrict__ bias, float* __restrict__ C,
          __half* __restrict__ Ch,
          __nv_bfloat16* __restrict__ Chi, __nv_bfloat16* __restrict__ Clo,
          int M, int Ntot, float scale)
{
    constexpr int WN = BN / 4;
    constexpr int NT = WN / 16;
    constexpr int B_HI_OFF = 32768;
    constexpr int B_LO_OFF = 32768 + BN * 128;
    constexpr int STG = 32768 + 2 * BN * 128;
    constexpr int A_OPS = 2048;
    constexpr int TOT_OPS = A_OPS + BN * 16;

    extern __shared__ __align__(1024) char sm[];
    const uint32_t sb = smem_u32(sm);

    const int tid = threadIdx.x;
    const int lane = tid & 31, wid = tid >> 5;
    const int wm = wid & 3, wn = wid >> 2;
    const int m0 = blockIdx.x * 128, n0 = blockIdx.y * BN;

    auto load_chunk = [&](int kc, int stg) {
        uint32_t base = sb + stg * STG;
        int kb = kc * 64;
#pragma unroll
        for (int it = tid; it < TOT_OPS; it += 512) {
            bool isA = it < A_OPS;
            int i = isA ? (it & 1023) : ((it - A_OPS) % (BN * 8));
            bool isHi = isA ? (it < 1024) : ((it - A_OPS) < BN * 8);
            int r = i >> 3, s = i & 7;
            uint32_t o = SWZ((uint32_t)(r * 128 + s * 16));
            if (isA) {
                if (m0 + r < M) {
                    const __nv_bfloat16* gp = (isHi ? Ahi : Alo) + (size_t)(m0 + r) * 256 + kb + s * 8;
                    CPASYNC16(base + (isHi ? A_HI_OFF : A_LO_OFF) + o, gp);
                }
            } else {
                const __nv_bfloat16* gp = (isHi ? Whi : Wlo) + (size_t)(n0 + r) * 256 + kb + s * 8;
                CPASYNC16(base + (isHi ? B_HI_OFF : B_LO_OFF) + o, gp);
            }
        }
        asm volatile("cp.async.commit_group;" ::: "memory");
    };

    float d[2][2 * NT][4];
#pragma unroll
    for (int i = 0; i < 2; i++)
#pragma unroll
        for (int j = 0; j < 2 * NT; j++)
#pragma unroll
            for (int r = 0; r < 4; r++) d[i][j][r] = 0.f;

    const int g = lane >> 3, l7 = lane & 7;
    const int a_row_off = (g & 1) ? 8 : 0;
    const int a_byte_off = (g & 2) ? 16 : 0;
    const int b_row_off = (g & 2) ? 8 : 0;
    const int b_byte_off = (g & 1) ? 16 : 0;

    load_chunk(0, 0);

    for (int kc = 0; kc < 4; kc++) {
        if (kc < 3) load_chunk(kc + 1, (kc + 1) & 1);
        if (kc < 3) asm volatile("cp.async.wait_group 1;" ::: "memory");
        else        asm volatile("cp.async.wait_group 0;" ::: "memory");
        __syncthreads();

        uint32_t base = sb + (kc & 1) * STG;
#pragma unroll
        for (int kk = 0; kk < 4; kk++) {
            int kb2 = kk * 32;
            uint32_t a_hi[2][4], a_lo[2][4], b_hi[NT][4], b_lo[NT][4];
#pragma unroll
            for (int i = 0; i < 2; i++) {
                uint32_t o = SWZ((uint32_t)((wm * 32 + i * 16 + l7 + a_row_off) * 128 + kb2 + a_byte_off));
                LDSM_X4(a_hi[i][0], a_hi[i][1], a_hi[i][2], a_hi[i][3], base + A_HI_OFF + o);
                LDSM_X4(a_lo[i][0], a_lo[i][1], a_lo[i][2], a_lo[i][3], base + A_LO_OFF + o);
            }
#pragma unroll
            for (int jt = 0; jt < NT; jt++) {
                uint32_t o = SWZ((uint32_t)((wn * WN + jt * 16 + l7 + b_row_off) * 128 + kb2 + b_byte_off));
                LDSM_X4(b_hi[jt][0], b_hi[jt][1], b_hi[jt][2], b_hi[jt][3], base + B_HI_OFF + o);
                LDSM_X4(b_lo[jt][0], b_lo[jt][1], b_lo[jt][2], b_lo[jt][3], base + B_LO_OFF + o);
            }
#pragma unroll
            for (int i = 0; i < 2; i++)
#pragma unroll
                for (int jt = 0; jt < NT; jt++)
#pragma unroll
                    for (int half = 0; half < 2; half++) {
                        int j = jt * 2 + half, sel = half * 2;
                        MMA16816(d[i][j], a_hi[i], b_hi[jt][sel], b_hi[jt][sel + 1]);
                        MMA16816(d[i][j], a_hi[i], b_lo[jt][sel], b_lo[jt][sel + 1]);
                        MMA16816(d[i][j], a_lo[i], b_hi[jt][sel], b_hi[jt][sel + 1]);
                    }
        }
        __syncthreads();
    }

    const int r_base = m0 + wm * 32;
    const int c_base = n0 + wn * WN;
#pragma unroll
    for (int i = 0; i < 2; i++)
#pragma unroll
        for (int j = 0; j < 2 * NT; j++) {
            int col = c_base + j * 8 + (lane & 3) * 2;
            float2 b2 = *(const float2*)(bias + col);
#pragma unroll
            for (int half = 0; half < 2; half++) {
                int row = r_base + i * 16 + (lane >> 2) + half * 8;
                if (row >= M) continue;
                float vx = d[i][j][half * 2 + 0] * scale + b2.x;
                float vy = d[i][j][half * 2 + 1] * scale + b2.y;
                if (GELU) { vx = gelu_exact(vx); vy = gelu_exact(vy); }
                if (OUTH) {
                    union { __half b[2]; uint32_t u; } ub;
                    ub.b[0] = __float2half_rn(vx);
                    ub.b[1] = __float2half_rn(vy);
                    *(uint32_t*)(Ch + (size_t)row * Ntot + col) = ub.u;
                } else {
                    *(float2*)(C + (size_t)row * Ntot + col) = make_float2(vx, vy);
                }
                if (HILO) {
                    union { __nv_bfloat16 b[2]; uint32_t u; } uh, ul;
                    uh.b[0] = __float2bfloat16(vx);
                    uh.b[1] = __float2bfloat16(vy);
                    ul.b[0] = __float2bfloat16(vx - __bfloat162float(uh.b[0]));
                    ul.b[1] = __float2bfloat16(vy - __bfloat162float(uh.b[1]));
                    *(uint32_t*)(Chi + (size_t)row * Ntot + col) = uh.u;
                    *(uint32_t*)(Clo + (size_t)row * Ntot + col) = ul.u;
                }
            }
        }
}

// ---------------------------------------------------------------------------
// CSR aggregation: one warp per dst node. q row in registers, k/m fp16 gather,
// fp32 score/attn/accumulate.
// ACC: initialize from fp32 agg buffer (prior relation), else zero.
// HILO_OUT: write bf16 hi/lo (for a-proj GEMM); else write fp32 agg.
// ---------------------------------------------------------------------------
template <bool ACC, bool HILO_OUT>
__global__ void csr_agg(const int* __restrict__ rp, const int* __restrict__ ei,
                        const int* __restrict__ src, const float* __restrict__ ew,
                        const float* __restrict__ pri,
                        const __half* __restrict__ q, int qs,
                        const __half* __restrict__ khat, const __half* __restrict__ mhat, int kms,
                        float* __restrict__ agg,
                        __nv_bfloat16* __restrict__ ohi, __nv_bfloat16* __restrict__ olo,
                        int N)
{
    int node = (int)((blockIdx.x * (size_t)blockDim.x + threadIdx.x) >> 5);
    int lane = threadIdx.x & 31;
    if (node >= N) return;

    int beg = rp[node], end = rp[node + 1];
    float prih = pri[lane >> 3] * 0.125f;

    union { uint4 u; __half2 h2[4]; } qv;
    qv.u = *(const uint4*)(q + (size_t)node * qs + lane * 8);
    float qf[8];
#pragma unroll
    for (int i = 0; i < 4; i++) {
        float2 f = __half22float2(qv.h2[i]);
        qf[2 * i] = f.x; qf[2 * i + 1] = f.y;
    }

    float acc[8];
    if (ACC) {
        const float* in = agg + (size_t)node * 256 + lane * 8;
        float4 a0 = *(const float4*)in, a1 = *(const float4*)(in + 4);
        acc[0] = a0.x; acc[1] = a0.y; acc[2] = a0.z; acc[3] = a0.w;
        acc[4] = a1.x; acc[5] = a1.y; acc[6] = a1.z; acc[7] = a1.w;
    } else {
#pragma unroll
        for (int i = 0; i < 8; i++) acc[i] = 0.f;
    }

    for (int j = beg; j < end; j++) {
        int eid = ei[j];
        int s = src[eid];
        union { uint4 u; __half2 h2[4]; } kv, mv;
        kv.u = *(const uint4*)(khat + (size_t)s * kms + lane * 8);
        mv.u = *(const uint4*)(mhat + (size_t)s * kms + lane * 8);

        float p = 0.f;
#pragma unroll
        for (int i = 0; i < 4; i++) {
            float2 kf = __half22float2(kv.h2[i]);
            p += qf[2 * i] * kf.x + qf[2 * i + 1] * kf.y;
        }
        p += __shfl_xor_sync(0xffffffffu, p, 1);
        p += __shfl_xor_sync(0xffffffffu, p, 2);
        p += __shfl_xor_sync(0xffffffffu, p, 4);

        float attn = ew[eid] / (1.f + __expf(-p * prih));
#pragma unroll
        for (int i = 0; i < 4; i++) {
            float2 mf = __half22float2(mv.h2[i]);
            acc[2 * i]     += mf.x * attn;
            acc[2 * i + 1] += mf.y * attn;
        }
    }

    if (HILO_OUT) {
        union { __nv_bfloat16 b[8]; uint4 u; } uh, ul;
#pragma unroll
        for (int i = 0; i < 8; i++) {
            uh.b[i] = __float2bfloat16(acc[i]);
            ul.b[i] = __float2bfloat16(acc[i] - __bfloat162float(uh.b[i]));
        }
        *(uint4*)(ohi + (size_t)node * 256 + lane * 8) = uh.u;
        *(uint4*)(olo + (size_t)node * 256 + lane * 8) = ul.u;
    } else {
        float* out = agg + (size_t)node * 256 + lane * 8;
        *(float4*)out       = make_float4(acc[0], acc[1], acc[2], acc[3]);
        *(float4*)(out + 4) = make_float4(acc[4], acc[5], acc[6], acc[7]);
    }
}

// ---------------------------------------------------------------------------
// Skip-blend + LayerNorm; also emits bf16 hi/lo of the output.
// ---------------------------------------------------------------------------
__global__ void ln_blend_kernel(const float* __restrict__ tr, const float* __restrict__ feats,
                                const float* __restrict__ g, const float* __restrict__ b,
                                const float* __restrict__ skip, int skip_idx,
                                float* __restrict__ out,
                                __nv_bfloat16* __restrict__ ohi, __nv_bfloat16* __restrict__ olo,
                                int N)
{
    int row = (int)((blockIdx.x * (size_t)blockDim.x + threadIdx.x) >> 5);
    int lane = threadIdx.x & 31;
    if (row >= N) return;

    float alpha = 1.f / (1.f + __expf(-skip[skip_idx]));
    float beta = 1.f - alpha;

    const float4* t4 = (const float4*)(tr    + (size_t)row * 256) + lane * 2;
    const float4* f4 = (const float4*)(feats + (size_t)row * 256) + lane * 2;
    float4 ta = t4[0], tb = t4[1], fa = f4[0], fb = f4[1];

    float v[8];
    v[0] = ta.x * alpha + fa.x * beta;  v[1] = ta.y * alpha + fa.y * beta;
    v[2] = ta.z * alpha + fa.z * beta;  v[3] = ta.w * alpha + fa.w * beta;
    v[4] = tb.x * alpha + fb.x * beta;  v[5] = tb.y * alpha + fb.y * beta;
    v[6] = tb.z * alpha + fb.z * beta;  v[7] = tb.w * alpha + fb.w * beta;

    float s = 0.f;
#pragma unroll
    for (int i = 0; i < 8; i++) s += v[i];
#pragma unroll
    for (int o = 16; o > 0; o >>= 1) s += __shfl_xor_sync(0xffffffffu, s, o);
    float mean = s * (1.f / 256.f);

    float sq = 0.f;
#pragma unroll
    for (int i = 0; i < 8; i++) { float dv = v[i] - mean; sq += dv * dv; }
#pragma unroll
    for (int o = 16; o > 0; o >>= 1) sq += __shfl_xor_sync(0xffffffffu, sq, o);
    float rstd = rsqrtf(sq * (1.f / 256.f) + 1e-5f);

    const float4* g4 = (const float4*)(g) + lane * 2;
    const float4* b4 = (const float4*)(b) + lane * 2;
    float4 ga = g4[0], gb = g4[1], ba = b4[0], bb = b4[1];
    float gg[8] = {ga.x, ga.y, ga.z, ga.w, gb.x, gb.y, gb.z, gb.w};
    float bbv[8] = {ba.x, ba.y, ba.z, ba.w, bb.x, bb.y, bb.z, bb.w};

    float o8[8];
    union { __nv_bfloat16 b[8]; uint4 u; } uh, ul;
#pragma unroll
    for (int i = 0; i < 8; i++) {
        o8[i] = (v[i] - mean) * rstd * gg[i] + bbv[i];
        uh.b[i] = __float2bfloat16(o8[i]);
        ul.b[i] = __float2bfloat16(o8[i] - __bfloat162float(uh.b[i]));
    }

    float4* outp = (float4*)(out + (size_t)row * 256) + lane * 2;
    outp[0] = make_float4(o8[0], o8[1], o8[2], o8[3]);
    outp[1] = make_float4(o8[4], o8[5], o8[6], o8[7]);
    *(uint4*)(ohi + (size_t)row * 256 + lane * 8) = uh.u;
    *(uint4*)(olo + (size_t)row * 256 + lane * 8) = ul.u;
}

// ---------------------------------------------------------------------------
// Host orchestration.
// ---------------------------------------------------------------------------
static const int SMEM128 = 2 * (32768 + 2 * 128 * 128);   // 131072
static const int SMEM64  = 2 * (32768 + 2 * 64 * 128);    // 98304

static void build_csr(const int* dst, int* cnt, int* rp, int* ei, int* bsum, int N, int E)
{
    cudaMemsetAsync(cnt, 0, (size_t)(N + 1) * sizeof(int), 0);
    count_edges<<<(E + 255) / 256, 256>>>(dst, cnt, E);
    int nb = (N + 1023) / 1024;
    scan_block<<<nb, 1024>>>(cnt, rp, bsum, N);
    scan_bsum<<<1, 32>>>(bsum, nb);
    scan_add<<<nb, 1024>>>(rp, bsum, N);
    copy_int<<<(N + 255) / 256, 256>>>(rp, cnt, N);
    fill_edges<<<(E + 255) / 256, 256>>>(dst, cnt, ei, E);
}

extern "C" void kernel_launch(void* const* d_in, const int* in_sizes, int n_in,
                              void* d_out, int out_size)
{
    const float* x_author = (const float*)d_in[0];
    const float* x_paper  = (const float*)d_in[1];
    const float* ew_wb    = (const float*)d_in[2];
    const float* ew_w     = (const float*)d_in[3];
    const float* ew_c     = (const float*)d_in[4];
    const float* adapt_W  = (const float*)d_in[5];
    const float* adapt_b  = (const float*)d_in[6];
    const float* kW       = (const float*)d_in[7];
    const float* kb       = (const float*)d_in[8];
    const float* qW       = (const float*)d_in[9];
    const float* qb       = (const float*)d_in[10];
    const float* mW       = (const float*)d_in[11];
    const float* mb       = (const float*)d_in[12];
    const float* aW       = (const float*)d_in[13];
    const float* ab       = (const float*)d_in[14];
    const float* w_pri    = (const float*)d_in[15];
    const float* w_att    = (const float*)d_in[16];
    const float* w_msg    = (const float*)d_in[17];
    const float* skip     = (const float*)d_in[18];
    const float* ln_g     = (const float*)d_in[19];
    const float* ln_b     = (const float*)d_in[20];
    const float* out_W    = (const float*)d_in[21];
    const float* out_b    = (const float*)d_in[22];
    const int* src_wb     = (const int*)d_in[23];
    const int* dst_wb     = (const int*)d_in[24];
    const int* src_w      = (const int*)d_in[25];
    const int* dst_w      = (const int*)d_in[26];
    const int* src_c      = (const int*)d_in[27];
    const int* dst_c      = (const int*)d_in[28];
    (void)in_sizes; (void)n_in; (void)out_size;

    cudaFuncSetAttribute(hmma_gemm<128, false, false, false>, cudaFuncAttributeMaxDynamicSharedMemorySize, SMEM128);
    cudaFuncSetAttribute(hmma_gemm<128, false, false, true>,  cudaFuncAttributeMaxDynamicSharedMemorySize, SMEM128);
    cudaFuncSetAttribute(hmma_gemm<128, true, true, false>,   cudaFuncAttributeMaxDynamicSharedMemorySize, SMEM128);
    cudaFuncSetAttribute(hmma_gemm<64, false, false, false>,  cudaFuncAttributeMaxDynamicSharedMemorySize, SMEM64);

    float *feats_a, *feats_p;
    __half *proj_a, *proj_p;
    float *agg_p, *tr_a, *tr_p, *Wkp, *bkp, *Wmp, *bmp, *bias_p, *bias_a;
    int *rp_wb, *rp_w, *rp_c, *ei_wb, *ei_w, *ei_c, *cnt, *bsum;
    __nv_bfloat16 *xa_hi, *xa_lo, *xp_hi, *xp_lo, *fa_hi, *fa_lo, *fp_hi, *fp_lo;
    __nv_bfloat16 *ga_hi, *ga_lo, *gp_hi, *gp_lo, *Whi, *Wlo;
#define SYM(var, sym) cudaGetSymbolAddress((void**)&var, sym)
    SYM(feats_a, g_feats_a); SYM(feats_p, g_feats_p);
    SYM(proj_a, g_proj_a); SYM(proj_p, g_proj_p);
    SYM(agg_p, g_agg_p);
    SYM(tr_a, g_tr_a); SYM(tr_p, g_tr_p);
    SYM(Wkp, g_Wk); SYM(bkp, g_bk); SYM(Wmp, g_Wm); SYM(bmp, g_bm);
    SYM(bias_p, g_bias_p); SYM(bias_a, g_bias_a);
    SYM(rp_wb, g_rp_wb); SYM(rp_w, g_rp_w); SYM(rp_c, g_rp_c);
    SYM(ei_wb, g_ei_wb); SYM(ei_w, g_ei_w); SYM(ei_c, g_ei_c);
    SYM(cnt, g_cnt); SYM(bsum, g_bsum);
    SYM(xa_hi, g_xa_hi); SYM(xa_lo, g_xa_lo); SYM(xp_hi, g_xp_hi); SYM(xp_lo, g_xp_lo);
    SYM(fa_hi, g_fa_hi); SYM(fa_lo, g_fa_lo); SYM(fp_hi, g_fp_hi); SYM(fp_lo, g_fp_lo);
    SYM(ga_hi, g_ga_hi); SYM(ga_lo, g_ga_lo); SYM(gp_hi, g_gp_hi); SYM(gp_lo, g_gp_lo);
    SYM(Whi, g_Whi); SYM(Wlo, g_Wlo);
#undef SYM

    float* fa[2] = {feats_a, feats_a + (size_t)NA * D};
    float* fp[2] = {feats_p, feats_p + (size_t)NP * D};

    const int GA = (NA + 127) / 128;   // 157
    const int GP = (NP + 127) / 128;   // 313

    // 0) weight prep + CSR build (graph static; once per launch)
    combine_weights<<<dim3(12, 257), 256>>>(kW, kb, mW, mb, w_att, w_msg, Wkp, bkp, Wmp, bmp);
    transpose_split<<<dim3(8, 8, NSLOT), dim3(32, 8)>>>(adapt_W, qW, Wkp, Wmp, aW, out_W, Whi, Wlo);
    pack_bias<<<(LL * 2048 + 255) / 256, 256>>>(qb, bkp, bmp, bias_p, bias_a);
    build_csr(dst_wb, cnt, rp_wb, ei_wb, bsum, NA, E_WB);
    build_csr(dst_w,  cnt, rp_w,  ei_w,  bsum, NP, E_W);
    build_csr(dst_c,  cnt, rp_c,  ei_c,  bsum, NP, E_C);

    // 1) split inputs, adapt + GELU (emits feats fp32 + hi/lo)
    split_hilo<<<(NA * D / 4 + 255) / 256, 256>>>(x_author, xa_hi, xa_lo, NA * D / 4);
    split_hilo<<<(NP * D / 4 + 255) / 256, 256>>>(x_paper, xp_hi, xp_lo, NP * D / 4);
    hmma_gemm<128, true, true, false><<<dim3(GA, 2), 512, SMEM128>>>(xa_hi, xa_lo, Whi, Wlo,
        adapt_b, fa[0], nullptr, fa_hi, fa_lo, NA, 256, 1.f);
    hmma_gemm<128, true, true, false><<<dim3(GP, 2), 512, SMEM128>>>(xp_hi, xp_lo, Whi + 65536, Wlo + 65536,
        adapt_b + 256, fp[0], nullptr, fp_hi, fp_lo, NP, 256, 1.f);

    for (int l = 0; l < LL; l++) {
        int cur = l & 1, nxt = 1 - cur;

        // batched projections -> fp16 proj buffers
        const size_t psl = (size_t)(2 + l * 8) * 65536;
        const size_t asl = (size_t)(2 + l * 8 + 5) * 65536;
        hmma_gemm<128, false, false, true><<<dim3(GP, PSTR / 128), 512, SMEM128>>>(fp_hi, fp_lo,
            Whi + psl, Wlo + psl, bias_p + l * PSTR, nullptr, proj_p, nullptr, nullptr, NP, PSTR, 1.f);
        hmma_gemm<128, false, false, true><<<dim3(GA, ASTR / 128), 512, SMEM128>>>(fa_hi, fa_lo,
            Whi + asl, Wlo + asl, bias_a + l * ASTR, nullptr, proj_a, nullptr, nullptr, NA, ASTR, 1.f);

        // CSR aggregation, warp per dst
        // WRITTEN_BY: dst author (sole relation) -> bf16 hi/lo directly
        csr_agg<false, true><<<(NA * 32 + 255) / 256, 256>>>(rp_wb, ei_wb, src_wb, ew_wb,
            w_pri + (l * 3 + 2) * 4, proj_a, ASTR, proj_p + 256, proj_p + 768, PSTR,
            nullptr, ga_hi, ga_lo, NA);
        // WRITES: dst paper, first relation -> fp32 agg
        csr_agg<false, false><<<(NP * 32 + 255) / 256, 256>>>(rp_w, ei_w, src_w, ew_w,
            w_pri + (l * 3 + 1) * 4, proj_p, PSTR, proj_a + 256, proj_a + 512, ASTR,
            agg_p, nullptr, nullptr, NP);
        // CITES: dst paper, accumulate from agg_p -> bf16 hi/lo directly
        csr_agg<true, true><<<(NP * 32 + 255) / 256, 256>>>(rp_c, ei_c, src_c, ew_c,
            w_pri + (l * 3 + 0) * 4, proj_p, PSTR, proj_p + 512, proj_p + 1024, PSTR,
            agg_p, gp_hi, gp_lo, NP);

        // a-projection (0.5 cross-relation mean via scale)
        const size_t aa = (size_t)(18 + l * 2 + 0) * 65536;
        const size_t ap = (size_t)(18 + l * 2 + 1) * 65536;
        hmma_gemm<128, false, false, false><<<dim3(GA, 2), 512, SMEM128>>>(ga_hi, ga_lo,
            Whi + aa, Wlo + aa, ab + (l * 2 + 0) * 256, tr_a, nullptr, nullptr, nullptr, NA, 256, 1.0f);
        hmma_gemm<128, false, false, false><<<dim3(GP, 2), 512, SMEM128>>>(gp_hi, gp_lo,
            Whi + ap, Wlo + ap, ab + (l * 2 + 1) * 256, tr_p, nullptr, nullptr, nullptr, NP, 256, 0.5f);

        // skip blend + LN (emits fp32 feats + hi/lo for next layer / out proj)
        ln_blend_kernel<<<(NA + 7) / 8, 256>>>(tr_a, fa[cur], ln_g + (l * 2 + 0) * 256,
            ln_b + (l * 2 + 0) * 256, skip, l * 3 + 0, fa[nxt], fa_hi, fa_lo, NA);
        ln_blend_kernel<<<(NP + 7) / 8, 256>>>(tr_p, fp[cur], ln_g + (l * 2 + 1) * 256,
            ln_b + (l * 2 + 1) * 256, skip, l * 3 + 1, fp[nxt], fp_hi, fp_lo, NP);
    }

    // output projection: paper feats (hi/lo from last LN) @ out_W + out_b
    hmma_gemm<64, false, false, false><<<dim3(GP, 1), 512, SMEM64>>>(fp_hi, fp_lo,
        Whi + (size_t)22 * 65536, Wlo + (size_t)22 * 65536,
        out_b, (float*)d_out, nullptr, nullptr, nullptr, NP, 64, 1.f);
}

// round 15
// speedup vs baseline: 1.6850x; 1.0074x over previous
#include <cuda_runtime.h>
#include <cuda_bf16.h>
#include <cuda_fp16.h>
#include <math.h>
#include <stdint.h>

// ---------------------------------------------------------------------------
// HGT forward. GEMMs: mma.sync bf16 hi/lo 3-term. Projections/edge data fp16.
// R15: paper-side WRITES+CITES merged into one csr kernel (agg_p eliminated).
// ---------------------------------------------------------------------------
#define NA     20000
#define NP     40000
#define D      256
#define DOUT   64
#define LL     2
#define E_WB   150000
#define E_W    150000
#define E_C    300000
#define NSLOT  23
#define PSTR   1280   // paper proj row: q | k_wb | k_c | m_wb | m_c
#define ASTR   768    // author proj row: q | k_w | m_w

// ------------------------- device scratch ----------------------------------
__device__ float g_feats_a[2][NA * D];
__device__ float g_feats_p[2][NP * D];
__device__ __half g_proj_a[NA * ASTR];
__device__ __half g_proj_p[NP * PSTR];
__device__ float g_tr_a[NA * D];
__device__ float g_tr_p[NP * D];
__device__ float g_Wk[LL * 3 * D * D];
__device__ float g_bk[LL * 3 * D];
__device__ float g_Wm[LL * 3 * D * D];
__device__ float g_bm[LL * 3 * D];
__device__ float g_bias_p[LL * PSTR];
__device__ float g_bias_a[LL * ASTR];
// CSR scratch
__device__ int g_rp_wb[NA + 1], g_rp_w[NP + 1], g_rp_c[NP + 1];
__device__ int g_ei_wb[E_WB], g_ei_w[E_W], g_ei_c[E_C];
__device__ int g_cnt[NP + 1];
__device__ int g_bsum[64];
// bf16 hi/lo operands
__device__ __nv_bfloat16 g_xa_hi[NA * D], g_xa_lo[NA * D];
__device__ __nv_bfloat16 g_xp_hi[NP * D], g_xp_lo[NP * D];
__device__ __nv_bfloat16 g_fa_hi[NA * D], g_fa_lo[NA * D];
__device__ __nv_bfloat16 g_fp_hi[NP * D], g_fp_lo[NP * D];
__device__ __nv_bfloat16 g_ga_hi[NA * D], g_ga_lo[NA * D];
__device__ __nv_bfloat16 g_gp_hi[NP * D], g_gp_lo[NP * D];
__device__ __nv_bfloat16 g_Whi[NSLOT * D * D], g_Wlo[NSLOT * D * D];

// ------------------------- small helpers -----------------------------------
__device__ __forceinline__ uint32_t smem_u32(const void* p) {
    uint32_t a;
    asm("{ .reg .u64 t; cvta.to.shared.u64 t, %1; cvt.u32.u64 %0, t; }" : "=r"(a) : "l"(p));
    return a;
}
#define SWZ(off) ((off) ^ (((off) >> 3) & 0x70))

#define CPASYNC16(dst, src) \
    asm volatile("cp.async.cg.shared.global [%0], [%1], 16;" :: "r"(dst), "l"(src) : "memory")

#define LDSM_X4(r0, r1, r2, r3, addr)                                         \
    asm volatile("ldmatrix.sync.aligned.m8n8.x4.shared.b16 {%0,%1,%2,%3}, [%4];" \
                 : "=r"(r0), "=r"(r1), "=r"(r2), "=r"(r3) : "r"(addr))

#define MMA16816(d, a, b0, b1)                                                \
    asm volatile("mma.sync.aligned.m16n8k16.row.col.f32.bf16.bf16.f32 "       \
                 "{%0,%1,%2,%3}, {%4,%5,%6,%7}, {%8,%9}, {%0,%1,%2,%3};"      \
                 : "+f"((d)[0]), "+f"((d)[1]), "+f"((d)[2]), "+f"((d)[3])     \
                 : "r"((a)[0]), "r"((a)[1]), "r"((a)[2]), "r"((a)[3]),        \
                   "r"(b0), "r"(b1))

__device__ __forceinline__ float gelu_exact(float x) {
    return 0.5f * x * (1.0f + erff(x * 0.70710678118654752f));
}

// ---------------------------------------------------------------------------
// combine per-head w_att/w_msg into dense K/M projection weights (fp32).
// ---------------------------------------------------------------------------
__global__ void combine_weights(const float* __restrict__ kW, const float* __restrict__ kb,
                                const float* __restrict__ mW, const float* __restrict__ mb,
                                const float* __restrict__ w_att, const float* __restrict__ w_msg,
                                float* __restrict__ Wk, float* __restrict__ bk,
                                float* __restrict__ Wm, float* __restrict__ bm)
{
    int mat = blockIdx.x;
    int l = mat / 6;
    int r6 = mat % 6;
    int e = r6 / 2;
    int which = r6 % 2;
    int d = blockIdx.y;        // 0..256 (256 == bias row)
    int j = threadIdx.x;
    int h = j >> 6;
    int jj = j & 63;
    int st = (e == 1) ? 0 : 1;

    const float* W   = which ? mW : kW;
    const float* B   = which ? mb : kb;
    const float* att = which ? w_msg : w_att;

    const float* wrow;
    if (d < 256) wrow = W + (((size_t)(l * 2 + st) * 256 + d) * 256);
    else         wrow = B + ((size_t)(l * 2 + st) * 256);
    const float* a = att + ((size_t)((l * 3 + e) * 4 + h)) * 64 * 64;

    float s = 0.f;
#pragma unroll 8
    for (int c = 0; c < 64; c++)
        s += wrow[h * 64 + c] * a[c * 64 + jj];

    float* out  = which ? Wm : Wk;
    float* outb = which ? bm : bk;
    if (d < 256) out[((size_t)(l * 3 + e) * 256 + d) * 256 + j] = s;
    else         outb[(size_t)(l * 3 + e) * 256 + j] = s;
}

// ---------------------------------------------------------------------------
// Transpose + split weights into bf16 hi/lo, K-major [n][k].
// ---------------------------------------------------------------------------
__global__ void transpose_split(const float* __restrict__ adapt_W, const float* __restrict__ qW,
                                const float* __restrict__ Wk, const float* __restrict__ Wm,
                                const float* __restrict__ aW, const float* __restrict__ outW,
                                __nv_bfloat16* __restrict__ Whi, __nv_bfloat16* __restrict__ Wlo)
{
    int slot = blockIdx.z;
    const float* src; int NC = 256;
    if (slot < 2)        src = adapt_W + (size_t)slot * 65536;
    else if (slot < 18) {
        int l = (slot - 2) / 8, o = (slot - 2) % 8;
        switch (o) {
            case 0: src = qW + (size_t)(l * 2 + 1) * 65536; break;
            case 1: src = Wk + (size_t)(l * 3 + 2) * 65536; break;
            case 2: src = Wk + (size_t)(l * 3 + 0) * 65536; break;
            case 3: src = Wm + (size_t)(l * 3 + 2) * 65536; break;
            case 4: src = Wm + (size_t)(l * 3 + 0) * 65536; break;
            case 5: src = qW + (size_t)(l * 2 + 0) * 65536; break;
            case 6: src = Wk + (size_t)(l * 3 + 1) * 65536; break;
            default: src = Wm + (size_t)(l * 3 + 1) * 65536; break;
        }
    }
    else if (slot < 22)  src = aW + (size_t)(slot - 18) * 65536;
    else               { src = outW; NC = 64; }

    int k0 = blockIdx.x * 32, n0 = blockIdx.y * 32;
    if (n0 >= NC) return;
    int tx = threadIdx.x, ty = threadIdx.y;

    __shared__ float t[32][33];
#pragma unroll
    for (int i = 0; i < 4; i++) {
        int k = k0 + ty + i * 8;
        t[ty + i * 8][tx] = src[(size_t)k * NC + n0 + tx];
    }
    __syncthreads();
#pragma unroll
    for (int i = 0; i < 4; i++) {
        int n = n0 + ty + i * 8, k = k0 + tx;
        float v = t[tx][ty + i * 8];
        __nv_bfloat16 h = __float2bfloat16(v);
        float r = v - __bfloat162float(h);
        size_t o = (size_t)slot * 65536 + (size_t)n * 256 + k;
        Whi[o] = h;
        Wlo[o] = __float2bfloat16(r);
    }
}

// ---------------------------------------------------------------------------
// Pack per-layer projection biases into the batched column layout.
// ---------------------------------------------------------------------------
__global__ void pack_bias(const float* __restrict__ qb, const float* __restrict__ bk,
                          const float* __restrict__ bm,
                          float* __restrict__ bp, float* __restrict__ ba)
{
    int idx = blockIdx.x * 256 + threadIdx.x;
    if (idx >= LL * 2048) return;
    int l = idx / 2048, r = idx % 2048;
    int seg = r >> 8, c = r & 255;
    float v;
    switch (seg) {
        case 0: v = qb[(l * 2 + 1) * 256 + c]; break;
        case 1: v = bk[(l * 3 + 2) * 256 + c]; break;
        case 2: v = bk[(l * 3 + 0) * 256 + c]; break;
        case 3: v = bm[(l * 3 + 2) * 256 + c]; break;
        case 4: v = bm[(l * 3 + 0) * 256 + c]; break;
        case 5: v = qb[(l * 2 + 0) * 256 + c]; break;
        case 6: v = bk[(l * 3 + 1) * 256 + c]; break;
        default: v = bm[(l * 3 + 1) * 256 + c]; break;
    }
    if (seg < 5) bp[l * PSTR + seg * 256 + c] = v;
    else         ba[l * ASTR + (seg - 5) * 256 + c] = v;
}

// ---------------------------------------------------------------------------
// fp32 -> bf16 hi/lo split (vectorized) — inputs only.
// ---------------------------------------------------------------------------
__global__ void split_hilo(const float* __restrict__ s, __nv_bfloat16* __restrict__ hi,
                           __nv_bfloat16* __restrict__ lo, int n4)
{
    int i = blockIdx.x * blockDim.x + threadIdx.x;
    if (i >= n4) return;
    float4 v = ((const float4*)s)[i];
    __nv_bfloat16 h[4], l[4];
    float vv[4] = {v.x, v.y, v.z, v.w};
#pragma unroll
    for (int j = 0; j < 4; j++) {
        h[j] = __float2bfloat16(vv[j]);
        l[j] = __float2bfloat16(vv[j] - __bfloat162float(h[j]));
    }
    ((uint2*)hi)[i] = *(uint2*)h;
    ((uint2*)lo)[i] = *(uint2*)l;
}

// ---------------------------------------------------------------------------
// CSR build: count -> two-level exclusive scan -> fill (dst-sorted edge ids).
// ---------------------------------------------------------------------------
__global__ void count_edges(const int* __restrict__ dst, int* __restrict__ cnt, int E)
{
    int i = blockIdx.x * blockDim.x + threadIdx.x;
    if (i < E) atomicAdd(&cnt[dst[i]], 1);
}
__global__ void scan_block(const int* __restrict__ cnt, int* __restrict__ rp,
                           int* __restrict__ bsum, int n)
{
    __shared__ int sh[1024];
    int i = blockIdx.x * 1024 + threadIdx.x;
    sh[threadIdx.x] = (i < n) ? cnt[i] : 0;
    __syncthreads();
#pragma unroll
    for (int off = 1; off < 1024; off <<= 1) {
        int t = (threadIdx.x >= off) ? sh[threadIdx.x - off] : 0;
        __syncthreads();
        sh[threadIdx.x] += t;
        __syncthreads();
    }
    if (i < n) rp[i + 1] = sh[threadIdx.x];
    if (threadIdx.x == 1023) bsum[blockIdx.x] = sh[1023];
}
__global__ void scan_bsum(int* __restrict__ bsum, int nb)
{
    if (threadIdx.x == 0) {
        int run = 0;
        for (int i = 0; i < nb; i++) { int v = bsum[i]; bsum[i] = run; run += v; }
    }
}
__global__ void scan_add(int* __restrict__ rp, const int* __restrict__ bsum, int n)
{
    int i = blockIdx.x * 1024 + threadIdx.x;
    if (i < n) rp[i + 1] += bsum[blockIdx.x];
    if (blockIdx.x == 0 && threadIdx.x == 0) rp[0] = 0;
}
__global__ void copy_int(const int* __restrict__ a, int* __restrict__ b, int n)
{
    int i = blockIdx.x * blockDim.x + threadIdx.x;
    if (i < n) b[i] = a[i];
}
__global__ void fill_edges(const int* __restrict__ dst, int* __restrict__ cur,
                           int* __restrict__ ei, int E)
{
    int i = blockIdx.x * blockDim.x + threadIdx.x;
    if (i < E) ei[atomicAdd(&cur[dst[i]], 1)] = i;
}

// ---------------------------------------------------------------------------
// HMMA GEMM: epi( scale*(A @ W^T) + bias ). 512 threads, tile 128 x BN,
// warp tile 32 x BN/4, K chunks of 64, 2-stage cp.async, SW128 + ldmatrix.
// OUTH: fp16 output into Ch. HILO: bf16 hi/lo aux outputs.
// ---------------------------------------------------------------------------
#define A_HI_OFF  0
#define A_LO_OFF  16384

template <int BN, bool GELU, bool HILO, bool OUTH>
__global__ void __launch_bounds__(512, 1)
hmma_gemm(const __nv_bfloat16* __restrict__ Ahi, const __nv_bfloat16* __restrict__ Alo,
          const __nv_bfloat16* __restrict__ Whi, const __nv_bfloat16* __restrict__ Wlo,
          const float* __restrict__ bias, float* __restrict__ C,
          __half* __restrict__ Ch,
          __nv_bfloat16* __restrict__ Chi, __nv_bfloat16* __restrict__ Clo,
          int M, int Ntot, float scale)
{
    constexpr int WN = BN / 4;
    constexpr int NT = WN / 16;
    constexpr int B_HI_OFF = 32768;
    constexpr int B_LO_OFF = 32768 + BN * 128;
    constexpr int STG = 32768 + 2 * BN * 128;
    constexpr int A_OPS = 2048;
    constexpr int TOT_OPS = A_OPS + BN * 16;

    extern __shared__ __align__(1024) char sm[];
    const uint32_t sb = smem_u32(sm);

    const int tid = threadIdx.x;
    const int lane = tid & 31, wid = tid >> 5;
    const int wm = wid & 3, wn = wid >> 2;
    const int m0 = blockIdx.x * 128, n0 = blockIdx.y * BN;

    auto load_chunk = [&](int kc, int stg) {
        uint32_t base = sb + stg * STG;
        int kb = kc * 64;
#pragma unroll
        for (int it = tid; it < TOT_OPS; it += 512) {
            bool isA = it < A_OPS;
            int i = isA ? (it & 1023) : ((it - A_OPS) % (BN * 8));
            bool isHi = isA ? (it < 1024) : ((it - A_OPS) < BN * 8);
            int r = i >> 3, s = i & 7;
            uint32_t o = SWZ((uint32_t)(r * 128 + s * 16));
            if (isA) {
                if (m0 + r < M) {
                    const __nv_bfloat16* gp = (isHi ? Ahi : Alo) + (size_t)(m0 + r) * 256 + kb + s * 8;
                    CPASYNC16(base + (isHi ? A_HI_OFF : A_LO_OFF) + o, gp);
                }
            } else {
                const __nv_bfloat16* gp = (isHi ? Whi : Wlo) + (size_t)(n0 + r) * 256 + kb + s * 8;
                CPASYNC16(base + (isHi ? B_HI_OFF : B_LO_OFF) + o, gp);
            }
        }
        asm volatile("cp.async.commit_group;" ::: "memory");
    };

    float d[2][2 * NT][4];
#pragma unroll
    for (int i = 0; i < 2; i++)
#pragma unroll
        for (int j = 0; j < 2 * NT; j++)
#pragma unroll
            for (int r = 0; r < 4; r++) d[i][j][r] = 0.f;

    const int g = lane >> 3, l7 = lane & 7;
    const int a_row_off = (g & 1) ? 8 : 0;
    const int a_byte_off = (g & 2) ? 16 : 0;
    const int b_row_off = (g & 2) ? 8 : 0;
    const int b_byte_off = (g & 1) ? 16 : 0;

    load_chunk(0, 0);

    for (int kc = 0; kc < 4; kc++) {
        if (kc < 3) load_chunk(kc + 1, (kc + 1) & 1);
        if (kc < 3) asm volatile("cp.async.wait_group 1;" ::: "memory");
        else        asm volatile("cp.async.wait_group 0;" ::: "memory");
        __syncthreads();

        uint32_t base = sb + (kc & 1) * STG;
#pragma unroll
        for (int kk = 0; kk < 4; kk++) {
            int kb2 = kk * 32;
            uint32_t a_hi[2][4], a_lo[2][4], b_hi[NT][4], b_lo[NT][4];
#pragma unroll
            for (int i = 0; i < 2; i++) {
                uint32_t o = SWZ((uint32_t)((wm * 32 + i * 16 + l7 + a_row_off) * 128 + kb2 + a_byte_off));
                LDSM_X4(a_hi[i][0], a_hi[i][1], a_hi[i][2], a_hi[i][3], base + A_HI_OFF + o);
                LDSM_X4(a_lo[i][0], a_lo[i][1], a_lo[i][2], a_lo[i][3], base + A_LO_OFF + o);
            }
#pragma unroll
            for (int jt = 0; jt < NT; jt++) {
                uint32_t o = SWZ((uint32_t)((wn * WN + jt * 16 + l7 + b_row_off) * 128 + kb2 + b_byte_off));
                LDSM_X4(b_hi[jt][0], b_hi[jt][1], b_hi[jt][2], b_hi[jt][3], base + B_HI_OFF + o);
                LDSM_X4(b_lo[jt][0], b_lo[jt][1], b_lo[jt][2], b_lo[jt][3], base + B_LO_OFF + o);
            }
#pragma unroll
            for (int i = 0; i < 2; i++)
#pragma unroll
                for (int jt = 0; jt < NT; jt++)
#pragma unroll
                    for (int half = 0; half < 2; half++) {
                        int j = jt * 2 + half, sel = half * 2;
                        MMA16816(d[i][j], a_hi[i], b_hi[jt][sel], b_hi[jt][sel + 1]);
                        MMA16816(d[i][j], a_hi[i], b_lo[jt][sel], b_lo[jt][sel + 1]);
                        MMA16816(d[i][j], a_lo[i], b_hi[jt][sel], b_hi[jt][sel + 1]);
                    }
        }
        __syncthreads();
    }

    const int r_base = m0 + wm * 32;
    const int c_base = n0 + wn * WN;
#pragma unroll
    for (int i = 0; i < 2; i++)
#pragma unroll
        for (int j = 0; j < 2 * NT; j++) {
            int col = c_base + j * 8 + (lane & 3) * 2;
            float2 b2 = *(const float2*)(bias + col);
#pragma unroll
            for (int half = 0; half < 2; half++) {
                int row = r_base + i * 16 + (lane >> 2) + half * 8;
                if (row >= M) continue;
                float vx = d[i][j][half * 2 + 0] * scale + b2.x;
                float vy = d[i][j][half * 2 + 1] * scale + b2.y;
                if (GELU) { vx = gelu_exact(vx); vy = gelu_exact(vy); }
                if (OUTH) {
                    union { __half b[2]; uint32_t u; } ub;
                    ub.b[0] = __float2half_rn(vx);
                    ub.b[1] = __float2half_rn(vy);
                    *(uint32_t*)(Ch + (size_t)row * Ntot + col) = ub.u;
                } else {
                    *(float2*)(C + (size_t)row * Ntot + col) = make_float2(vx, vy);
                }
                if (HILO) {
                    union { __nv_bfloat16 b[2]; uint32_t u; } uh, ul;
                    uh.b[0] = __float2bfloat16(vx);
                    uh.b[1] = __float2bfloat16(vy);
                    ul.b[0] = __float2bfloat16(vx - __bfloat162float(uh.b[0]));
                    ul.b[1] = __float2bfloat16(vy - __bfloat162float(uh.b[1]));
                    *(uint32_t*)(Chi + (size_t)row * Ntot + col) = uh.u;
                    *(uint32_t*)(Clo + (size_t)row * Ntot + col) = ul.u;
                }
            }
        }
}

// ---------------------------------------------------------------------------
// CSR aggregation, single relation (author side): warp per dst node, q row in
// registers, fp32 accumulate; emits bf16 hi/lo directly.
// ---------------------------------------------------------------------------
__global__ void csr_agg1(const int* __restrict__ rp, const int* __restrict__ ei,
                         const int* __restrict__ src, const float* __restrict__ ew,
                         const float* __restrict__ pri,
                         const __half* __restrict__ q, int qs,
                         const __half* __restrict__ khat, const __half* __restrict__ mhat, int kms,
                         __nv_bfloat16* __restrict__ ohi, __nv_bfloat16* __restrict__ olo,
                         int N)
{
    int node = (int)((blockIdx.x * (size_t)blockDim.x + threadIdx.x) >> 5);
    int lane = threadIdx.x & 31;
    if (node >= N) return;

    int beg = rp[node], end = rp[node + 1];
    float prih = pri[lane >> 3] * 0.125f;

    union { uint4 u; __half2 h2[4]; } qv;
    qv.u = *(const uint4*)(q + (size_t)node * qs + lane * 8);
    float qf[8];
#pragma unroll
    for (int i = 0; i < 4; i++) {
        float2 f = __half22float2(qv.h2[i]);
        qf[2 * i] = f.x; qf[2 * i + 1] = f.y;
    }

    float acc[8];
#pragma unroll
    for (int i = 0; i < 8; i++) acc[i] = 0.f;

    for (int j = beg; j < end; j++) {
        int eid = ei[j];
        int s = src[eid];
        union { uint4 u; __half2 h2[4]; } kv, mv;
        kv.u = *(const uint4*)(khat + (size_t)s * kms + lane * 8);
        mv.u = *(const uint4*)(mhat + (size_t)s * kms + lane * 8);

        float p = 0.f;
#pragma unroll
        for (int i = 0; i < 4; i++) {
            float2 kf = __half22float2(kv.h2[i]);
            p += qf[2 * i] * kf.x + qf[2 * i + 1] * kf.y;
        }
        p += __shfl_xor_sync(0xffffffffu, p, 1);
        p += __shfl_xor_sync(0xffffffffu, p, 2);
        p += __shfl_xor_sync(0xffffffffu, p, 4);

        float attn = ew[eid] / (1.f + __expf(-p * prih));
#pragma unroll
        for (int i = 0; i < 4; i++) {
            float2 mf = __half22float2(mv.h2[i]);
            acc[2 * i]     += mf.x * attn;
            acc[2 * i + 1] += mf.y * attn;
        }
    }

    union { __nv_bfloat16 b[8]; uint4 u; } uh, ul;
#pragma unroll
    for (int i = 0; i < 8; i++) {
        uh.b[i] = __float2bfloat16(acc[i]);
        ul.b[i] = __float2bfloat16(acc[i] - __bfloat162float(uh.b[i]));
    }
    *(uint4*)(ohi + (size_t)node * 256 + lane * 8) = uh.u;
    *(uint4*)(olo + (size_t)node * 256 + lane * 8) = ul.u;
}

// ---------------------------------------------------------------------------
// CSR aggregation, paper side: BOTH relations (WRITES from author proj, then
// CITES from paper proj) accumulated in one pass; q row and accumulator stay
// in registers across both edge lists. Emits bf16 hi/lo directly.
// ---------------------------------------------------------------------------
__global__ void csr_agg2(const int* __restrict__ rp1, const int* __restrict__ ei1,
                         const int* __restrict__ src1, const float* __restrict__ ew1,
                         const float* __restrict__ pri1,
                         const __half* __restrict__ k1, const __half* __restrict__ m1, int kms1,
                         const int* __restrict__ rp2, const int* __restrict__ ei2,
                         const int* __restrict__ src2, const float* __restrict__ ew2,
                         const float* __restrict__ pri2,
                         const __half* __restrict__ k2, const __half* __restrict__ m2, int kms2,
                         const __half* __restrict__ q, int qs,
                         __nv_bfloat16* __restrict__ ohi, __nv_bfloat16* __restrict__ olo,
                         int N)
{
    int node = (int)((blockIdx.x * (size_t)blockDim.x + threadIdx.x) >> 5);
    int lane = threadIdx.x & 31;
    if (node >= N) return;

    float prih1 = pri1[lane >> 3] * 0.125f;
    float prih2 = pri2[lane >> 3] * 0.125f;

    union { uint4 u; __half2 h2[4]; } qv;
    qv.u = *(const uint4*)(q + (size_t)node * qs + lane * 8);
    float qf[8];
#pragma unroll
    for (int i = 0; i < 4; i++) {
        float2 f = __half22float2(qv.h2[i]);
        qf[2 * i] = f.x; qf[2 * i + 1] = f.y;
    }

    float acc[8];
#pragma unroll
    for (int i = 0; i < 8; i++) acc[i] = 0.f;

    // relation 1: WRITES (k/m from author proj)
    int beg = rp1[node], end = rp1[node + 1];
    for (int j = beg; j < end; j++) {
        int eid = ei1[j];
        int s = src1[eid];
        union { uint4 u; __half2 h2[4]; } kv, mv;
        kv.u = *(const uint4*)(k1 + (size_t)s * kms1 + lane * 8);
        mv.u = *(const uint4*)(m1 + (size_t)s * kms1 + lane * 8);
        float p = 0.f;
#pragma unroll
        for (int i = 0; i < 4; i++) {
            float2 kf = __half22float2(kv.h2[i]);
            p += qf[2 * i] * kf.x + qf[2 * i + 1] * kf.y;
        }
        p += __shfl_xor_sync(0xffffffffu, p, 1);
        p += __shfl_xor_sync(0xffffffffu, p, 2);
        p += __shfl_xor_sync(0xffffffffu, p, 4);
        float attn = ew1[eid] / (1.f + __expf(-p * prih1));
#pragma unroll
        for (int i = 0; i < 4; i++) {
            float2 mf = __half22float2(mv.h2[i]);
            acc[2 * i]     += mf.x * attn;
            acc[2 * i + 1] += mf.y * attn;
        }
    }

    // relation 2: CITES (k/m from paper proj)
    beg = rp2[node]; end = rp2[node + 1];
    for (int j = beg; j < end; j++) {
        int eid = ei2[j];
        int s = src2[eid];
        union { uint4 u; __half2 h2[4]; } kv, mv;
        kv.u = *(const uint4*)(k2 + (size_t)s * kms2 + lane * 8);
        mv.u = *(const uint4*)(m2 + (size_t)s * kms2 + lane * 8);
        float p = 0.f;
#pragma unroll
        for (int i = 0; i < 4; i++) {
            float2 kf = __half22float2(kv.h2[i]);
            p += qf[2 * i] * kf.x + qf[2 * i + 1] * kf.y;
        }
        p += __shfl_xor_sync(0xffffffffu, p, 1);
        p += __shfl_xor_sync(0xffffffffu, p, 2);
        p += __shfl_xor_sync(0xffffffffu, p, 4);
        float attn = ew2[eid] / (1.f + __expf(-p * prih2));
#pragma unroll
        for (int i = 0; i < 4; i++) {
            float2 mf = __half22float2(mv.h2[i]);
            acc[2 * i]     += mf.x * attn;
            acc[2 * i + 1] += mf.y * attn;
        }
    }

    union { __nv_bfloat16 b[8]; uint4 u; } uh, ul;
#pragma unroll
    for (int i = 0; i < 8; i++) {
        uh.b[i] = __float2bfloat16(acc[i]);
        ul.b[i] = __float2bfloat16(acc[i] - __bfloat162float(uh.b[i]));
    }
    *(uint4*)(ohi + (size_t)node * 256 + lane * 8) = uh.u;
    *(uint4*)(olo + (size_t)node * 256 + lane * 8) = ul.u;
}

// ---------------------------------------------------------------------------
// Skip-blend + LayerNorm; also emits bf16 hi/lo of the output.
// ---------------------------------------------------------------------------
__global__ void ln_blend_kernel(const float* __restrict__ tr, const float* __restrict__ feats,
                                const float* __restrict__ g, const float* __restrict__ b,
                                const float* __restrict__ skip, int skip_idx,
                                float* __restrict__ out,
                                __nv_bfloat16* __restrict__ ohi, __nv_bfloat16* __restrict__ olo,
                                int N)
{
    int row = (int)((blockIdx.x * (size_t)blockDim.x + threadIdx.x) >> 5);
    int lane = threadIdx.x & 31;
    if (row >= N) return;

    float alpha = 1.f / (1.f + __expf(-skip[skip_idx]));
    float beta = 1.f - alpha;

    const float4* t4 = (const float4*)(tr    + (size_t)row * 256) + lane * 2;
    const float4* f4 = (const float4*)(feats + (size_t)row * 256) + lane * 2;
    float4 ta = t4[0], tb = t4[1], fa = f4[0], fb = f4[1];

    float v[8];
    v[0] = ta.x * alpha + fa.x * beta;  v[1] = ta.y * alpha + fa.y * beta;
    v[2] = ta.z * alpha + fa.z * beta;  v[3] = ta.w * alpha + fa.w * beta;
    v[4] = tb.x * alpha + fb.x * beta;  v[5] = tb.y * alpha + fb.y * beta;
    v[6] = tb.z * alpha + fb.z * beta;  v[7] = tb.w * alpha + fb.w * beta;

    float s = 0.f;
#pragma unroll
    for (int i = 0; i < 8; i++) s += v[i];
#pragma unroll
    for (int o = 16; o > 0; o >>= 1) s += __shfl_xor_sync(0xffffffffu, s, o);
    float mean = s * (1.f / 256.f);

    float sq = 0.f;
#pragma unroll
    for (int i = 0; i < 8; i++) { float dv = v[i] - mean; sq += dv * dv; }
#pragma unroll
    for (int o = 16; o > 0; o >>= 1) sq += __shfl_xor_sync(0xffffffffu, sq, o);
    float rstd = rsqrtf(sq * (1.f / 256.f) + 1e-5f);

    const float4* g4 = (const float4*)(g) + lane * 2;
    const float4* b4 = (const float4*)(b) + lane * 2;
    float4 ga = g4[0], gb = g4[1], ba = b4[0], bb = b4[1];
    float gg[8] = {ga.x, ga.y, ga.z, ga.w, gb.x, gb.y, gb.z, gb.w};
    float bbv[8] = {ba.x, ba.y, ba.z, ba.w, bb.x, bb.y, bb.z, bb.w};

    float o8[8];
    union { __nv_bfloat16 b[8]; uint4 u; } uh, ul;
#pragma unroll
    for (int i = 0; i < 8; i++) {
        o8[i] = (v[i] - mean) * rstd * gg[i] + bbv[i];
        uh.b[i] = __float2bfloat16(o8[i]);
        ul.b[i] = __float2bfloat16(o8[i] - __bfloat162float(uh.b[i]));
    }

    float4* outp = (float4*)(out + (size_t)row * 256) + lane * 2;
    outp[0] = make_float4(o8[0], o8[1], o8[2], o8[3]);
    outp[1] = make_float4(o8[4], o8[5], o8[6], o8[7]);
    *(uint4*)(ohi + (size_t)row * 256 + lane * 8) = uh.u;
    *(uint4*)(olo + (size_t)row * 256 + lane * 8) = ul.u;
}

// ---------------------------------------------------------------------------
// Host orchestration.
// ---------------------------------------------------------------------------
static const int SMEM128 = 2 * (32768 + 2 * 128 * 128);   // 131072
static const int SMEM64  = 2 * (32768 + 2 * 64 * 128);    // 98304

static void build_csr(const int* dst, int* cnt, int* rp, int* ei, int* bsum, int N, int E)
{
    cudaMemsetAsync(cnt, 0, (size_t)(N + 1) * sizeof(int), 0);
    count_edges<<<(E + 255) / 256, 256>>>(dst, cnt, E);
    int nb = (N + 1023) / 1024;
    scan_block<<<nb, 1024>>>(cnt, rp, bsum, N);
    scan_bsum<<<1, 32>>>(bsum, nb);
    scan_add<<<nb, 1024>>>(rp, bsum, N);
    copy_int<<<(N + 255) / 256, 256>>>(rp, cnt, N);
    fill_edges<<<(E + 255) / 256, 256>>>(dst, cnt, ei, E);
}

extern "C" void kernel_launch(void* const* d_in, const int* in_sizes, int n_in,
                              void* d_out, int out_size)
{
    const float* x_author = (const float*)d_in[0];
    const float* x_paper  = (const float*)d_in[1];
    const float* ew_wb    = (const float*)d_in[2];
    const float* ew_w     = (const float*)d_in[3];
    const float* ew_c     = (const float*)d_in[4];
    const float* adapt_W  = (const float*)d_in[5];
    const float* adapt_b  = (const float*)d_in[6];
    const float* kW       = (const float*)d_in[7];
    const float* kb       = (const float*)d_in[8];
    const float* qW       = (const float*)d_in[9];
    const float* qb       = (const float*)d_in[10];
    const float* mW       = (const float*)d_in[11];
    const float* mb       = (const float*)d_in[12];
    const float* aW       = (const float*)d_in[13];
    const float* ab       = (const float*)d_in[14];
    const float* w_pri    = (const float*)d_in[15];
    const float* w_att    = (const float*)d_in[16];
    const float* w_msg    = (const float*)d_in[17];
    const float* skip     = (const float*)d_in[18];
    const float* ln_g     = (const float*)d_in[19];
    const float* ln_b     = (const float*)d_in[20];
    const float* out_W    = (const float*)d_in[21];
    const float* out_b    = (const float*)d_in[22];
    const int* src_wb     = (const int*)d_in[23];
    const int* dst_wb     = (const int*)d_in[24];
    const int* src_w      = (const int*)d_in[25];
    const int* dst_w      = (const int*)d_in[26];
    const int* src_c      = (const int*)d_in[27];
    const int* dst_c      = (const int*)d_in[28];
    (void)in_sizes; (void)n_in; (void)out_size;

    cudaFuncSetAttribute(hmma_gemm<128, false, false, false>, cudaFuncAttributeMaxDynamicSharedMemorySize, SMEM128);
    cudaFuncSetAttribute(hmma_gemm<128, false, false, true>,  cudaFuncAttributeMaxDynamicSharedMemorySize, SMEM128);
    cudaFuncSetAttribute(hmma_gemm<128, true, true, false>,   cudaFuncAttributeMaxDynamicSharedMemorySize, SMEM128);
    cudaFuncSetAttribute(hmma_gemm<64, false, false, false>,  cudaFuncAttributeMaxDynamicSharedMemorySize, SMEM64);

    float *feats_a, *feats_p;
    __half *proj_a, *proj_p;
    float *tr_a, *tr_p, *Wkp, *bkp, *Wmp, *bmp, *bias_p, *bias_a;
    int *rp_wb, *rp_w, *rp_c, *ei_wb, *ei_w, *ei_c, *cnt, *bsum;
    __nv_bfloat16 *xa_hi, *xa_lo, *xp_hi, *xp_lo, *fa_hi, *fa_lo, *fp_hi, *fp_lo;
    __nv_bfloat16 *ga_hi, *ga_lo, *gp_hi, *gp_lo, *Whi, *Wlo;
#define SYM(var, sym) cudaGetSymbolAddress((void**)&var, sym)
    SYM(feats_a, g_feats_a); SYM(feats_p, g_feats_p);
    SYM(proj_a, g_proj_a); SYM(proj_p, g_proj_p);
    SYM(tr_a, g_tr_a); SYM(tr_p, g_tr_p);
    SYM(Wkp, g_Wk); SYM(bkp, g_bk); SYM(Wmp, g_Wm); SYM(bmp, g_bm);
    SYM(bias_p, g_bias_p); SYM(bias_a, g_bias_a);
    SYM(rp_wb, g_rp_wb); SYM(rp_w, g_rp_w); SYM(rp_c, g_rp_c);
    SYM(ei_wb, g_ei_wb); SYM(ei_w, g_ei_w); SYM(ei_c, g_ei_c);
    SYM(cnt, g_cnt); SYM(bsum, g_bsum);
    SYM(xa_hi, g_xa_hi); SYM(xa_lo, g_xa_lo); SYM(xp_hi, g_xp_hi); SYM(xp_lo, g_xp_lo);
    SYM(fa_hi, g_fa_hi); SYM(fa_lo, g_fa_lo); SYM(fp_hi, g_fp_hi); SYM(fp_lo, g_fp_lo);
    SYM(ga_hi, g_ga_hi); SYM(ga_lo, g_ga_lo); SYM(gp_hi, g_gp_hi); SYM(gp_lo, g_gp_lo);
    SYM(Whi, g_Whi); SYM(Wlo, g_Wlo);
#undef SYM

    float* fa[2] = {feats_a, feats_a + (size_t)NA * D};
    float* fp[2] = {feats_p, feats_p + (size_t)NP * D};

    const int GA = (NA + 127) / 128;   // 157
    const int GP = (NP + 127) / 128;   // 313

    // 0) weight prep + CSR build (graph static; once per launch)
    combine_weights<<<dim3(12, 257), 256>>>(kW, kb, mW, mb, w_att, w_msg, Wkp, bkp, Wmp, bmp);
    transpose_split<<<dim3(8, 8, NSLOT), dim3(32, 8)>>>(adapt_W, qW, Wkp, Wmp, aW, out_W, Whi, Wlo);
    pack_bias<<<(LL * 2048 + 255) / 256, 256>>>(qb, bkp, bmp, bias_p, bias_a);
    build_csr(dst_wb, cnt, rp_wb, ei_wb, bsum, NA, E_WB);
    build_csr(dst_w,  cnt, rp_w,  ei_w,  bsum, NP, E_W);
    build_csr(dst_c,  cnt, rp_c,  ei_c,  bsum, NP, E_C);

    // 1) split inputs, adapt + GELU (emits feats fp32 + hi/lo)
    split_hilo<<<(NA * D / 4 + 255) / 256, 256>>>(x_author, xa_hi, xa_lo, NA * D / 4);
    split_hilo<<<(NP * D / 4 + 255) / 256, 256>>>(x_paper, xp_hi, xp_lo, NP * D / 4);
    hmma_gemm<128, true, true, false><<<dim3(GA, 2), 512, SMEM128>>>(xa_hi, xa_lo, Whi, Wlo,
        adapt_b, fa[0], nullptr, fa_hi, fa_lo, NA, 256, 1.f);
    hmma_gemm<128, true, true, false><<<dim3(GP, 2), 512, SMEM128>>>(xp_hi, xp_lo, Whi + 65536, Wlo + 65536,
        adapt_b + 256, fp[0], nullptr, fp_hi, fp_lo, NP, 256, 1.f);

    for (int l = 0; l < LL; l++) {
        int cur = l & 1, nxt = 1 - cur;

        // batched projections -> fp16 proj buffers
        const size_t psl = (size_t)(2 + l * 8) * 65536;
        const size_t asl = (size_t)(2 + l * 8 + 5) * 65536;
        hmma_gemm<128, false, false, true><<<dim3(GP, PSTR / 128), 512, SMEM128>>>(fp_hi, fp_lo,
            Whi + psl, Wlo + psl, bias_p + l * PSTR, nullptr, proj_p, nullptr, nullptr, NP, PSTR, 1.f);
        hmma_gemm<128, false, false, true><<<dim3(GA, ASTR / 128), 512, SMEM128>>>(fa_hi, fa_lo,
            Whi + asl, Wlo + asl, bias_a + l * ASTR, nullptr, proj_a, nullptr, nullptr, NA, ASTR, 1.f);

        // CSR aggregation, warp per dst
        // WRITTEN_BY: dst author (sole relation) -> bf16 hi/lo directly
        csr_agg1<<<(NA * 32 + 255) / 256, 256>>>(rp_wb, ei_wb, src_wb, ew_wb,
            w_pri + (l * 3 + 2) * 4, proj_a, ASTR, proj_p + 256, proj_p + 768, PSTR,
            ga_hi, ga_lo, NA);
        // paper: WRITES (author k/m) then CITES (paper k/m) fused -> bf16 hi/lo
        csr_agg2<<<(NP * 32 + 255) / 256, 256>>>(
            rp_w, ei_w, src_w, ew_w, w_pri + (l * 3 + 1) * 4, proj_a + 256, proj_a + 512, ASTR,
            rp_c, ei_c, src_c, ew_c, w_pri + (l * 3 + 0) * 4, proj_p + 512, proj_p + 1024, PSTR,
            proj_p, PSTR, gp_hi, gp_lo, NP);

        // a-projection (0.5 cross-relation mean via scale)
        const size_t aa = (size_t)(18 + l * 2 + 0) * 65536;
        const size_t ap = (size_t)(18 + l * 2 + 1) * 65536;
        hmma_gemm<128, false, false, false><<<dim3(GA, 2), 512, SMEM128>>>(ga_hi, ga_lo,
            Whi + aa, Wlo + aa, ab + (l * 2 + 0) * 256, tr_a, nullptr, nullptr, nullptr, NA, 256, 1.0f);
        hmma_gemm<128, false, false, false><<<dim3(GP, 2), 512, SMEM128>>>(gp_hi, gp_lo,
            Whi + ap, Wlo + ap, ab + (l * 2 + 1) * 256, tr_p, nullptr, nullptr, nullptr, NP, 256, 0.5f);

        // skip blend + LN (emits fp32 feats + hi/lo for next layer / out proj)
        ln_blend_kernel<<<(NA + 7) / 8, 256>>>(tr_a, fa[cur], ln_g + (l * 2 + 0) * 256,
            ln_b + (l * 2 + 0) * 256, skip, l * 3 + 0, fa[nxt], fa_hi, fa_lo, NA);
        ln_blend_kernel<<<(NP + 7) / 8, 256>>>(tr_p, fp[cur], ln_g + (l * 2 + 1) * 256,
            ln_b + (l * 2 + 1) * 256, skip, l * 3 + 1, fp[nxt], fp_hi, fp_lo, NP);
    }

    // output projection: paper feats (hi/lo from last LN) @ out_W + out_b
    hmma_gemm<64, false, false, false><<<dim3(GP, 1), 512, SMEM64>>>(fp_hi, fp_lo,
        Whi + (size_t)22 * 65536, Wlo + (size_t)22 * 65536,
        out_b, (float*)d_out, nullptr, nullptr, nullptr, NP, 64, 1.f);
}

// round 16
// speedup vs baseline: 2.1554x; 1.2791x over previous
#include <cuda_runtime.h>
#include <cuda_bf16.h>
#include <cuda_fp16.h>
#include <math.h>
#include <stdint.h>

// ---------------------------------------------------------------------------
// HGT forward.
// R16: projections + out-proj on plain fp16 MMA (1 term, 3x fewer MMAs);
// adapt + a-proj remain bf16 hi/lo 3-term (accuracy-critical path).
// ---------------------------------------------------------------------------
#define NA     20000
#define NP     40000
#define D      256
#define DOUT   64
#define LL     2
#define E_WB   150000
#define E_W    150000
#define E_C    300000
#define NSLOT  23
#define PSTR   1280   // paper proj row: q | k_wb | k_c | m_wb | m_c
#define ASTR   768    // author proj row: q | k_w | m_w

// ------------------------- device scratch ----------------------------------
__device__ float g_feats_a[2][NA * D];
__device__ float g_feats_p[2][NP * D];
__device__ __half g_fa16[NA * D], g_fp16[NP * D];       // fp16 feats (proj A)
__device__ __half g_proj_a[NA * ASTR];
__device__ __half g_proj_p[NP * PSTR];
__device__ float g_tr_a[NA * D];
__device__ float g_tr_p[NP * D];
__device__ float g_Wk[LL * 3 * D * D];
__device__ float g_bk[LL * 3 * D];
__device__ float g_Wm[LL * 3 * D * D];
__device__ float g_bm[LL * 3 * D];
__device__ float g_bias_p[LL * PSTR];
__device__ float g_bias_a[LL * ASTR];
// CSR scratch
__device__ int g_rp_wb[NA + 1], g_rp_w[NP + 1], g_rp_c[NP + 1];
__device__ int g_ei_wb[E_WB], g_ei_w[E_W], g_ei_c[E_C];
__device__ int g_cnt[NP + 1];
__device__ int g_bsum[64];
// bf16 hi/lo operands (adapt inputs + agg)
__device__ __nv_bfloat16 g_xa_hi[NA * D], g_xa_lo[NA * D];
__device__ __nv_bfloat16 g_xp_hi[NP * D], g_xp_lo[NP * D];
__device__ __nv_bfloat16 g_ga_hi[NA * D], g_ga_lo[NA * D];
__device__ __nv_bfloat16 g_gp_hi[NP * D], g_gp_lo[NP * D];
__device__ __nv_bfloat16 g_Whi[NSLOT * D * D], g_Wlo[NSLOT * D * D];
__device__ __half g_W16[NSLOT * D * D];                 // fp16 weights (proj/out)

// ------------------------- small helpers -----------------------------------
__device__ __forceinline__ uint32_t smem_u32(const void* p) {
    uint32_t a;
    asm("{ .reg .u64 t; cvta.to.shared.u64 t, %1; cvt.u32.u64 %0, t; }" : "=r"(a) : "l"(p));
    return a;
}
#define SWZ(off) ((off) ^ (((off) >> 3) & 0x70))

#define CPASYNC16(dst, src) \
    asm volatile("cp.async.cg.shared.global [%0], [%1], 16;" :: "r"(dst), "l"(src) : "memory")

#define LDSM_X4(r0, r1, r2, r3, addr)                                         \
    asm volatile("ldmatrix.sync.aligned.m8n8.x4.shared.b16 {%0,%1,%2,%3}, [%4];" \
                 : "=r"(r0), "=r"(r1), "=r"(r2), "=r"(r3) : "r"(addr))

#define MMA_BF16(d, a, b0, b1)                                                \
    asm volatile("mma.sync.aligned.m16n8k16.row.col.f32.bf16.bf16.f32 "       \
                 "{%0,%1,%2,%3}, {%4,%5,%6,%7}, {%8,%9}, {%0,%1,%2,%3};"      \
                 : "+f"((d)[0]), "+f"((d)[1]), "+f"((d)[2]), "+f"((d)[3])     \
                 : "r"((a)[0]), "r"((a)[1]), "r"((a)[2]), "r"((a)[3]),        \
                   "r"(b0), "r"(b1))

#define MMA_FP16(d, a, b0, b1)                                                \
    asm volatile("mma.sync.aligned.m16n8k16.row.col.f32.f16.f16.f32 "         \
                 "{%0,%1,%2,%3}, {%4,%5,%6,%7}, {%8,%9}, {%0,%1,%2,%3};"      \
                 : "+f"((d)[0]), "+f"((d)[1]), "+f"((d)[2]), "+f"((d)[3])     \
                 : "r"((a)[0]), "r"((a)[1]), "r"((a)[2]), "r"((a)[3]),        \
                   "r"(b0), "r"(b1))

__device__ __forceinline__ float gelu_exact(float x) {
    return 0.5f * x * (1.0f + erff(x * 0.70710678118654752f));
}

// ---------------------------------------------------------------------------
// combine per-head w_att/w_msg into dense K/M projection weights (fp32).
// ---------------------------------------------------------------------------
__global__ void combine_weights(const float* __restrict__ kW, const float* __restrict__ kb,
                                const float* __restrict__ mW, const float* __restrict__ mb,
                                const float* __restrict__ w_att, const float* __restrict__ w_msg,
                                float* __restrict__ Wk, float* __restrict__ bk,
                                float* __restrict__ Wm, float* __restrict__ bm)
{
    int mat = blockIdx.x;
    int l = mat / 6;
    int r6 = mat % 6;
    int e = r6 / 2;
    int which = r6 % 2;
    int d = blockIdx.y;        // 0..256 (256 == bias row)
    int j = threadIdx.x;
    int h = j >> 6;
    int jj = j & 63;
    int st = (e == 1) ? 0 : 1;

    const float* W   = which ? mW : kW;
    const float* B   = which ? mb : kb;
    const float* att = which ? w_msg : w_att;

    const float* wrow;
    if (d < 256) wrow = W + (((size_t)(l * 2 + st) * 256 + d) * 256);
    else         wrow = B + ((size_t)(l * 2 + st) * 256);
    const float* a = att + ((size_t)((l * 3 + e) * 4 + h)) * 64 * 64;

    float s = 0.f;
#pragma unroll 8
    for (int c = 0; c < 64; c++)
        s += wrow[h * 64 + c] * a[c * 64 + jj];

    float* out  = which ? Wm : Wk;
    float* outb = which ? bm : bk;
    if (d < 256) out[((size_t)(l * 3 + e) * 256 + d) * 256 + j] = s;
    else         outb[(size_t)(l * 3 + e) * 256 + j] = s;
}

// ---------------------------------------------------------------------------
// Transpose + split weights: bf16 hi/lo (3-term path) + fp16 (1-term path).
// ---------------------------------------------------------------------------
__global__ void transpose_split(const float* __restrict__ adapt_W, const float* __restrict__ qW,
                                const float* __restrict__ Wk, const float* __restrict__ Wm,
                                const float* __restrict__ aW, const float* __restrict__ outW,
                                __nv_bfloat16* __restrict__ Whi, __nv_bfloat16* __restrict__ Wlo,
                                __half* __restrict__ W16)
{
    int slot = blockIdx.z;
    const float* src; int NC = 256;
    if (slot < 2)        src = adapt_W + (size_t)slot * 65536;
    else if (slot < 18) {
        int l = (slot - 2) / 8, o = (slot - 2) % 8;
        switch (o) {
            case 0: src = qW + (size_t)(l * 2 + 1) * 65536; break;
            case 1: src = Wk + (size_t)(l * 3 + 2) * 65536; break;
            case 2: src = Wk + (size_t)(l * 3 + 0) * 65536; break;
            case 3: src = Wm + (size_t)(l * 3 + 2) * 65536; break;
            case 4: src = Wm + (size_t)(l * 3 + 0) * 65536; break;
            case 5: src = qW + (size_t)(l * 2 + 0) * 65536; break;
            case 6: src = Wk + (size_t)(l * 3 + 1) * 65536; break;
            default: src = Wm + (size_t)(l * 3 + 1) * 65536; break;
        }
    }
    else if (slot < 22)  src = aW + (size_t)(slot - 18) * 65536;
    else               { src = outW; NC = 64; }

    int k0 = blockIdx.x * 32, n0 = blockIdx.y * 32;
    if (n0 >= NC) return;
    int tx = threadIdx.x, ty = threadIdx.y;

    __shared__ float t[32][33];
#pragma unroll
    for (int i = 0; i < 4; i++) {
        int k = k0 + ty + i * 8;
        t[ty + i * 8][tx] = src[(size_t)k * NC + n0 + tx];
    }
    __syncthreads();
#pragma unroll
    for (int i = 0; i < 4; i++) {
        int n = n0 + ty + i * 8, k = k0 + tx;
        float v = t[tx][ty + i * 8];
        __nv_bfloat16 h = __float2bfloat16(v);
        float r = v - __bfloat162float(h);
        size_t o = (size_t)slot * 65536 + (size_t)n * 256 + k;
        Whi[o] = h;
        Wlo[o] = __float2bfloat16(r);
        W16[o] = __float2half_rn(v);
    }
}

// ---------------------------------------------------------------------------
// Pack per-layer projection biases into the batched column layout.
// ---------------------------------------------------------------------------
__global__ void pack_bias(const float* __restrict__ qb, const float* __restrict__ bk,
                          const float* __restrict__ bm,
                          float* __restrict__ bp, float* __restrict__ ba)
{
    int idx = blockIdx.x * 256 + threadIdx.x;
    if (idx >= LL * 2048) return;
    int l = idx / 2048, r = idx % 2048;
    int seg = r >> 8, c = r & 255;
    float v;
    switch (seg) {
        case 0: v = qb[(l * 2 + 1) * 256 + c]; break;
        case 1: v = bk[(l * 3 + 2) * 256 + c]; break;
        case 2: v = bk[(l * 3 + 0) * 256 + c]; break;
        case 3: v = bm[(l * 3 + 2) * 256 + c]; break;
        case 4: v = bm[(l * 3 + 0) * 256 + c]; break;
        case 5: v = qb[(l * 2 + 0) * 256 + c]; break;
        case 6: v = bk[(l * 3 + 1) * 256 + c]; break;
        default: v = bm[(l * 3 + 1) * 256 + c]; break;
    }
    if (seg < 5) bp[l * PSTR + seg * 256 + c] = v;
    else         ba[l * ASTR + (seg - 5) * 256 + c] = v;
}

// ---------------------------------------------------------------------------
// fp32 -> bf16 hi/lo split (vectorized) — adapt inputs only.
// ---------------------------------------------------------------------------
__global__ void split_hilo(const float* __restrict__ s, __nv_bfloat16* __restrict__ hi,
                           __nv_bfloat16* __restrict__ lo, int n4)
{
    int i = blockIdx.x * blockDim.x + threadIdx.x;
    if (i >= n4) return;
    float4 v = ((const float4*)s)[i];
    __nv_bfloat16 h[4], l[4];
    float vv[4] = {v.x, v.y, v.z, v.w};
#pragma unroll
    for (int j = 0; j < 4; j++) {
        h[j] = __float2bfloat16(vv[j]);
        l[j] = __float2bfloat16(vv[j] - __bfloat162float(h[j]));
    }
    ((uint2*)hi)[i] = *(uint2*)h;
    ((uint2*)lo)[i] = *(uint2*)l;
}

// ---------------------------------------------------------------------------
// CSR build: count -> two-level exclusive scan -> fill.
// ---------------------------------------------------------------------------
__global__ void count_edges(const int* __restrict__ dst, int* __restrict__ cnt, int E)
{
    int i = blockIdx.x * blockDim.x + threadIdx.x;
    if (i < E) atomicAdd(&cnt[dst[i]], 1);
}
__global__ void scan_block(const int* __restrict__ cnt, int* __restrict__ rp,
                           int* __restrict__ bsum, int n)
{
    __shared__ int sh[1024];
    int i = blockIdx.x * 1024 + threadIdx.x;
    sh[threadIdx.x] = (i < n) ? cnt[i] : 0;
    __syncthreads();
#pragma unroll
    for (int off = 1; off < 1024; off <<= 1) {
        int t = (threadIdx.x >= off) ? sh[threadIdx.x - off] : 0;
        __syncthreads();
        sh[threadIdx.x] += t;
        __syncthreads();
    }
    if (i < n) rp[i + 1] = sh[threadIdx.x];
    if (threadIdx.x == 1023) bsum[blockIdx.x] = sh[1023];
}
__global__ void scan_bsum(int* __restrict__ bsum, int nb)
{
    if (threadIdx.x == 0) {
        int run = 0;
        for (int i = 0; i < nb; i++) { int v = bsum[i]; bsum[i] = run; run += v; }
    }
}
__global__ void scan_add(int* __restrict__ rp, const int* __restrict__ bsum, int n)
{
    int i = blockIdx.x * 1024 + threadIdx.x;
    if (i < n) rp[i + 1] += bsum[blockIdx.x];
    if (blockIdx.x == 0 && threadIdx.x == 0) rp[0] = 0;
}
__global__ void copy_int(const int* __restrict__ a, int* __restrict__ b, int n)
{
    int i = blockIdx.x * blockDim.x + threadIdx.x;
    if (i < n) b[i] = a[i];
}
__global__ void fill_edges(const int* __restrict__ dst, int* __restrict__ cur,
                           int* __restrict__ ei, int E)
{
    int i = blockIdx.x * blockDim.x + threadIdx.x;
    if (i < E) ei[atomicAdd(&cur[dst[i]], 1)] = i;
}

// ---------------------------------------------------------------------------
// bf16 hi/lo 3-term GEMM (adapt, a-proj). 512 threads, tile 128 x 128.
// GELU: apply erf-gelu. F16OUT: additionally emit fp16 copy (adapt feats).
// ---------------------------------------------------------------------------
#define A_HI_OFF  0
#define A_LO_OFF  16384

template <bool GELU, bool F16OUT>
__global__ void __launch_bounds__(512, 1)
hmma_bf16(const __nv_bfloat16* __restrict__ Ahi, const __nv_bfloat16* __restrict__ Alo,
          const __nv_bfloat16* __restrict__ Whi, const __nv_bfloat16* __restrict__ Wlo,
          const float* __restrict__ bias, float* __restrict__ C,
          __half* __restrict__ Ch,
          int M, int Ntot, float scale)
{
    constexpr int BN = 128, WN = 32, NT = 2;
    constexpr int B_HI_OFF = 32768;
    constexpr int B_LO_OFF = 32768 + BN * 128;
    constexpr int STG = 32768 + 2 * BN * 128;
    constexpr int A_OPS = 2048;
    constexpr int TOT_OPS = A_OPS + BN * 16;

    extern __shared__ __align__(1024) char sm[];
    const uint32_t sb = smem_u32(sm);

    const int tid = threadIdx.x;
    const int lane = tid & 31, wid = tid >> 5;
    const int wm = wid & 3, wn = wid >> 2;
    const int m0 = blockIdx.x * 128, n0 = blockIdx.y * BN;

    auto load_chunk = [&](int kc, int stg) {
        uint32_t base = sb + stg * STG;
        int kb = kc * 64;
#pragma unroll
        for (int it = tid; it < TOT_OPS; it += 512) {
            bool isA = it < A_OPS;
            int i = isA ? (it & 1023) : ((it - A_OPS) % (BN * 8));
            bool isHi = isA ? (it < 1024) : ((it - A_OPS) < BN * 8);
            int r = i >> 3, s = i & 7;
            uint32_t o = SWZ((uint32_t)(r * 128 + s * 16));
            if (isA) {
                if (m0 + r < M) {
                    const __nv_bfloat16* gp = (isHi ? Ahi : Alo) + (size_t)(m0 + r) * 256 + kb + s * 8;
                    CPASYNC16(base + (isHi ? A_HI_OFF : A_LO_OFF) + o, gp);
                }
            } else {
                const __nv_bfloat16* gp = (isHi ? Whi : Wlo) + (size_t)(n0 + r) * 256 + kb + s * 8;
                CPASYNC16(base + (isHi ? B_HI_OFF : B_LO_OFF) + o, gp);
            }
        }
        asm volatile("cp.async.commit_group;" ::: "memory");
    };

    float d[2][2 * NT][4];
#pragma unroll
    for (int i = 0; i < 2; i++)
#pragma unroll
        for (int j = 0; j < 2 * NT; j++)
#pragma unroll
            for (int r = 0; r < 4; r++) d[i][j][r] = 0.f;

    const int g = lane >> 3, l7 = lane & 7;
    const int a_row_off = (g & 1) ? 8 : 0;
    const int a_byte_off = (g & 2) ? 16 : 0;
    const int b_row_off = (g & 2) ? 8 : 0;
    const int b_byte_off = (g & 1) ? 16 : 0;

    load_chunk(0, 0);

    for (int kc = 0; kc < 4; kc++) {
        if (kc < 3) load_chunk(kc + 1, (kc + 1) & 1);
        if (kc < 3) asm volatile("cp.async.wait_group 1;" ::: "memory");
        else        asm volatile("cp.async.wait_group 0;" ::: "memory");
        __syncthreads();

        uint32_t base = sb + (kc & 1) * STG;
#pragma unroll
        for (int kk = 0; kk < 4; kk++) {
            int kb2 = kk * 32;
            uint32_t a_hi[2][4], a_lo[2][4], b_hi[NT][4], b_lo[NT][4];
#pragma unroll
            for (int i = 0; i < 2; i++) {
                uint32_t o = SWZ((uint32_t)((wm * 32 + i * 16 + l7 + a_row_off) * 128 + kb2 + a_byte_off));
                LDSM_X4(a_hi[i][0], a_hi[i][1], a_hi[i][2], a_hi[i][3], base + A_HI_OFF + o);
                LDSM_X4(a_lo[i][0], a_lo[i][1], a_lo[i][2], a_lo[i][3], base + A_LO_OFF + o);
            }
#pragma unroll
            for (int jt = 0; jt < NT; jt++) {
                uint32_t o = SWZ((uint32_t)((wn * WN + jt * 16 + l7 + b_row_off) * 128 + kb2 + b_byte_off));
                LDSM_X4(b_hi[jt][0], b_hi[jt][1], b_hi[jt][2], b_hi[jt][3], base + B_HI_OFF + o);
                LDSM_X4(b_lo[jt][0], b_lo[jt][1], b_lo[jt][2], b_lo[jt][3], base + B_LO_OFF + o);
            }
#pragma unroll
            for (int i = 0; i < 2; i++)
#pragma unroll
                for (int jt = 0; jt < NT; jt++)
#pragma unroll
                    for (int half = 0; half < 2; half++) {
                        int j = jt * 2 + half, sel = half * 2;
                        MMA_BF16(d[i][j], a_hi[i], b_hi[jt][sel], b_hi[jt][sel + 1]);
                        MMA_BF16(d[i][j], a_hi[i], b_lo[jt][sel], b_lo[jt][sel + 1]);
                        MMA_BF16(d[i][j], a_lo[i], b_hi[jt][sel], b_hi[jt][sel + 1]);
                    }
        }
        __syncthreads();
    }

    const int r_base = m0 + wm * 32;
    const int c_base = n0 + wn * WN;
#pragma unroll
    for (int i = 0; i < 2; i++)
#pragma unroll
        for (int j = 0; j < 2 * NT; j++) {
            int col = c_base + j * 8 + (lane & 3) * 2;
            float2 b2 = *(const float2*)(bias + col);
#pragma unroll
            for (int half = 0; half < 2; half++) {
                int row = r_base + i * 16 + (lane >> 2) + half * 8;
                if (row >= M) continue;
                float vx = d[i][j][half * 2 + 0] * scale + b2.x;
                float vy = d[i][j][half * 2 + 1] * scale + b2.y;
                if (GELU) { vx = gelu_exact(vx); vy = gelu_exact(vy); }
                *(float2*)(C + (size_t)row * Ntot + col) = make_float2(vx, vy);
                if (F16OUT) {
                    union { __half b[2]; uint32_t u; } ub;
                    ub.b[0] = __float2half_rn(vx);
                    ub.b[1] = __float2half_rn(vy);
                    *(uint32_t*)(Ch + (size_t)row * Ntot + col) = ub.u;
                }
            }
        }
}

// ---------------------------------------------------------------------------
// fp16 single-term GEMM (projections, out-proj). 512 threads, tile 128 x BN.
// OUTH: fp16 output (projections); else fp32 output (out-proj).
// ---------------------------------------------------------------------------
template <int BN, bool OUTH>
__global__ void __launch_bounds__(512, 1)
hmma16(const __half* __restrict__ A, const __half* __restrict__ W,
       const float* __restrict__ bias, float* __restrict__ C,
       __half* __restrict__ Ch, int M, int Ntot)
{
    constexpr int WN = BN / 4;
    constexpr int NT = WN / 16;
    constexpr int B_OFF = 16384;
    constexpr int STG = 16384 + BN * 128;
    constexpr int A_OPS = 1024;                 // 128 rows x 8 sixteens
    constexpr int TOT_OPS = A_OPS + BN * 8;

    extern __shared__ __align__(1024) char sm[];
    const uint32_t sb = smem_u32(sm);

    const int tid = threadIdx.x;
    const int lane = tid & 31, wid = tid >> 5;
    const int wm = wid & 3, wn = wid >> 2;
    const int m0 = blockIdx.x * 128, n0 = blockIdx.y * BN;

    auto load_chunk = [&](int kc, int stg) {
        uint32_t base = sb + stg * STG;
        int kb = kc * 64;
#pragma unroll
        for (int it = tid; it < TOT_OPS; it += 512) {
            bool isA = it < A_OPS;
            int i = isA ? it : (it - A_OPS);
            int r = i >> 3, s = i & 7;
            uint32_t o = SWZ((uint32_t)(r * 128 + s * 16));
            if (isA) {
                if (m0 + r < M)
                    CPASYNC16(base + o, A + (size_t)(m0 + r) * 256 + kb + s * 8);
            } else {
                CPASYNC16(base + B_OFF + o, W + (size_t)(n0 + r) * 256 + kb + s * 8);
            }
        }
        asm volatile("cp.async.commit_group;" ::: "memory");
    };

    float d[2][2 * NT][4];
#pragma unroll
    for (int i = 0; i < 2; i++)
#pragma unroll
        for (int j = 0; j < 2 * NT; j++)
#pragma unroll
            for (int r = 0; r < 4; r++) d[i][j][r] = 0.f;

    const int g = lane >> 3, l7 = lane & 7;
    const int a_row_off = (g & 1) ? 8 : 0;
    const int a_byte_off = (g & 2) ? 16 : 0;
    const int b_row_off = (g & 2) ? 8 : 0;
    const int b_byte_off = (g & 1) ? 16 : 0;

    load_chunk(0, 0);

    for (int kc = 0; kc < 4; kc++) {
        if (kc < 3) load_chunk(kc + 1, (kc + 1) & 1);
        if (kc < 3) asm volatile("cp.async.wait_group 1;" ::: "memory");
        else        asm volatile("cp.async.wait_group 0;" ::: "memory");
        __syncthreads();

        uint32_t base = sb + (kc & 1) * STG;
#pragma unroll
        for (int kk = 0; kk < 4; kk++) {
            int kb2 = kk * 32;
            uint32_t a[2][4], b[NT][4];
#pragma unroll
            for (int i = 0; i < 2; i++) {
                uint32_t o = SWZ((uint32_t)((wm * 32 + i * 16 + l7 + a_row_off) * 128 + kb2 + a_byte_off));
                LDSM_X4(a[i][0], a[i][1], a[i][2], a[i][3], base + o);
            }
#pragma unroll
            for (int jt = 0; jt < NT; jt++) {
                uint32_t o = SWZ((uint32_t)((wn * WN + jt * 16 + l7 + b_row_off) * 128 + kb2 + b_byte_off));
                LDSM_X4(b[jt][0], b[jt][1], b[jt][2], b[jt][3], base + B_OFF + o);
            }
#pragma unroll
            for (int i = 0; i < 2; i++)
#pragma unroll
                for (int jt = 0; jt < NT; jt++)
#pragma unroll
                    for (int half = 0; half < 2; half++) {
                        int j = jt * 2 + half, sel = half * 2;
                        MMA_FP16(d[i][j], a[i], b[jt][sel], b[jt][sel + 1]);
                    }
        }
        __syncthreads();
    }

    const int r_base = m0 + wm * 32;
    const int c_base = n0 + wn * WN;
#pragma unroll
    for (int i = 0; i < 2; i++)
#pragma unroll
        for (int j = 0; j < 2 * NT; j++) {
            int col = c_base + j * 8 + (lane & 3) * 2;
            float2 b2 = *(const float2*)(bias + col);
#pragma unroll
            for (int half = 0; half < 2; half++) {
                int row = r_base + i * 16 + (lane >> 2) + half * 8;
                if (row >= M) continue;
                float vx = d[i][j][half * 2 + 0] + b2.x;
                float vy = d[i][j][half * 2 + 1] + b2.y;
                if (OUTH) {
                    union { __half b[2]; uint32_t u; } ub;
                    ub.b[0] = __float2half_rn(vx);
                    ub.b[1] = __float2half_rn(vy);
                    *(uint32_t*)(Ch + (size_t)row * Ntot + col) = ub.u;
                } else {
                    *(float2*)(C + (size_t)row * Ntot + col) = make_float2(vx, vy);
                }
            }
        }
}

// ---------------------------------------------------------------------------
// CSR aggregation, author side (single relation): warp per dst node.
// ---------------------------------------------------------------------------
__global__ void csr_agg1(const int* __restrict__ rp, const int* __restrict__ ei,
                         const int* __restrict__ src, const float* __restrict__ ew,
                         const float* __restrict__ pri,
                         const __half* __restrict__ q, int qs,
                         const __half* __restrict__ khat, const __half* __restrict__ mhat, int kms,
                         __nv_bfloat16* __restrict__ ohi, __nv_bfloat16* __restrict__ olo,
                         int N)
{
    int node = (int)((blockIdx.x * (size_t)blockDim.x + threadIdx.x) >> 5);
    int lane = threadIdx.x & 31;
    if (node >= N) return;

    int beg = rp[node], end = rp[node + 1];
    float prih = pri[lane >> 3] * 0.125f;

    union { uint4 u; __half2 h2[4]; } qv;
    qv.u = *(const uint4*)(q + (size_t)node * qs + lane * 8);
    float qf[8];
#pragma unroll
    for (int i = 0; i < 4; i++) {
        float2 f = __half22float2(qv.h2[i]);
        qf[2 * i] = f.x; qf[2 * i + 1] = f.y;
    }

    float acc[8];
#pragma unroll
    for (int i = 0; i < 8; i++) acc[i] = 0.f;

    for (int j = beg; j < end; j++) {
        int eid = ei[j];
        int s = src[eid];
        union { uint4 u; __half2 h2[4]; } kv, mv;
        kv.u = *(const uint4*)(khat + (size_t)s * kms + lane * 8);
        mv.u = *(const uint4*)(mhat + (size_t)s * kms + lane * 8);

        float p = 0.f;
#pragma unroll
        for (int i = 0; i < 4; i++) {
            float2 kf = __half22float2(kv.h2[i]);
            p += qf[2 * i] * kf.x + qf[2 * i + 1] * kf.y;
        }
        p += __shfl_xor_sync(0xffffffffu, p, 1);
        p += __shfl_xor_sync(0xffffffffu, p, 2);
        p += __shfl_xor_sync(0xffffffffu, p, 4);

        float attn = ew[eid] / (1.f + __expf(-p * prih));
#pragma unroll
        for (int i = 0; i < 4; i++) {
            float2 mf = __half22float2(mv.h2[i]);
            acc[2 * i]     += mf.x * attn;
            acc[2 * i + 1] += mf.y * attn;
        }
    }

    union { __nv_bfloat16 b[8]; uint4 u; } uh, ul;
#pragma unroll
    for (int i = 0; i < 8; i++) {
        uh.b[i] = __float2bfloat16(acc[i]);
        ul.b[i] = __float2bfloat16(acc[i] - __bfloat162float(uh.b[i]));
    }
    *(uint4*)(ohi + (size_t)node * 256 + lane * 8) = uh.u;
    *(uint4*)(olo + (size_t)node * 256 + lane * 8) = ul.u;
}

// ---------------------------------------------------------------------------
// CSR aggregation, paper side: WRITES then CITES fused, q/acc in registers.
// ---------------------------------------------------------------------------
__global__ void csr_agg2(const int* __restrict__ rp1, const int* __restrict__ ei1,
                         const int* __restrict__ src1, const float* __restrict__ ew1,
                         const float* __restrict__ pri1,
                         const __half* __restrict__ k1, const __half* __restrict__ m1, int kms1,
                         const int* __restrict__ rp2, const int* __restrict__ ei2,
                         const int* __restrict__ src2, const float* __restrict__ ew2,
                         const float* __restrict__ pri2,
                         const __half* __restrict__ k2, const __half* __restrict__ m2, int kms2,
                         const __half* __restrict__ q, int qs,
                         __nv_bfloat16* __restrict__ ohi, __nv_bfloat16* __restrict__ olo,
                         int N)
{
    int node = (int)((blockIdx.x * (size_t)blockDim.x + threadIdx.x) >> 5);
    int lane = threadIdx.x & 31;
    if (node >= N) return;

    float prih1 = pri1[lane >> 3] * 0.125f;
    float prih2 = pri2[lane >> 3] * 0.125f;

    union { uint4 u; __half2 h2[4]; } qv;
    qv.u = *(const uint4*)(q + (size_t)node * qs + lane * 8);
    float qf[8];
#pragma unroll
    for (int i = 0; i < 4; i++) {
        float2 f = __half22float2(qv.h2[i]);
        qf[2 * i] = f.x; qf[2 * i + 1] = f.y;
    }

    float acc[8];
#pragma unroll
    for (int i = 0; i < 8; i++) acc[i] = 0.f;

    int beg = rp1[node], end = rp1[node + 1];
    for (int j = beg; j < end; j++) {
        int eid = ei1[j];
        int s = src1[eid];
        union { uint4 u; __half2 h2[4]; } kv, mv;
        kv.u = *(const uint4*)(k1 + (size_t)s * kms1 + lane * 8);
        mv.u = *(const uint4*)(m1 + (size_t)s * kms1 + lane * 8);
        float p = 0.f;
#pragma unroll
        for (int i = 0; i < 4; i++) {
            float2 kf = __half22float2(kv.h2[i]);
            p += qf[2 * i] * kf.x + qf[2 * i + 1] * kf.y;
        }
        p += __shfl_xor_sync(0xffffffffu, p, 1);
        p += __shfl_xor_sync(0xffffffffu, p, 2);
        p += __shfl_xor_sync(0xffffffffu, p, 4);
        float attn = ew1[eid] / (1.f + __expf(-p * prih1));
#pragma unroll
        for (int i = 0; i < 4; i++) {
            float2 mf = __half22float2(mv.h2[i]);
            acc[2 * i]     += mf.x * attn;
            acc[2 * i + 1] += mf.y * attn;
        }
    }

    beg = rp2[node]; end = rp2[node + 1];
    for (int j = beg; j < end; j++) {
        int eid = ei2[j];
        int s = src2[eid];
        union { uint4 u; __half2 h2[4]; } kv, mv;
        kv.u = *(const uint4*)(k2 + (size_t)s * kms2 + lane * 8);
        mv.u = *(const uint4*)(m2 + (size_t)s * kms2 + lane * 8);
        float p = 0.f;
#pragma unroll
        for (int i = 0; i < 4; i++) {
            float2 kf = __half22float2(kv.h2[i]);
            p += qf[2 * i] * kf.x + qf[2 * i + 1] * kf.y;
        }
        p += __shfl_xor_sync(0xffffffffu, p, 1);
        p += __shfl_xor_sync(0xffffffffu, p, 2);
        p += __shfl_xor_sync(0xffffffffu, p, 4);
        float attn = ew2[eid] / (1.f + __expf(-p * prih2));
#pragma unroll
        for (int i = 0; i < 4; i++) {
            float2 mf = __half22float2(mv.h2[i]);
            acc[2 * i]     += mf.x * attn;
            acc[2 * i + 1] += mf.y * attn;
        }
    }

    union { __nv_bfloat16 b[8]; uint4 u; } uh, ul;
#pragma unroll
    for (int i = 0; i < 8; i++) {
        uh.b[i] = __float2bfloat16(acc[i]);
        ul.b[i] = __float2bfloat16(acc[i] - __bfloat162float(uh.b[i]));
    }
    *(uint4*)(ohi + (size_t)node * 256 + lane * 8) = uh.u;
    *(uint4*)(olo + (size_t)node * 256 + lane * 8) = ul.u;
}

// ---------------------------------------------------------------------------
// Skip-blend + LayerNorm; emits fp32 feats + fp16 feats.
// ---------------------------------------------------------------------------
__global__ void ln_blend_kernel(const float* __restrict__ tr, const float* __restrict__ feats,
                                const float* __restrict__ g, const float* __restrict__ b,
                                const float* __restrict__ skip, int skip_idx,
                                float* __restrict__ out, __half* __restrict__ o16,
                                int N)
{
    int row = (int)((blockIdx.x * (size_t)blockDim.x + threadIdx.x) >> 5);
    int lane = threadIdx.x & 31;
    if (row >= N) return;

    float alpha = 1.f / (1.f + __expf(-skip[skip_idx]));
    float beta = 1.f - alpha;

    const float4* t4 = (const float4*)(tr    + (size_t)row * 256) + lane * 2;
    const float4* f4 = (const float4*)(feats + (size_t)row * 256) + lane * 2;
    float4 ta = t4[0], tb = t4[1], fa = f4[0], fb = f4[1];

    float v[8];
    v[0] = ta.x * alpha + fa.x * beta;  v[1] = ta.y * alpha + fa.y * beta;
    v[2] = ta.z * alpha + fa.z * beta;  v[3] = ta.w * alpha + fa.w * beta;
    v[4] = tb.x * alpha + fb.x * beta;  v[5] = tb.y * alpha + fb.y * beta;
    v[6] = tb.z * alpha + fb.z * beta;  v[7] = tb.w * alpha + fb.w * beta;

    float s = 0.f;
#pragma unroll
    for (int i = 0; i < 8; i++) s += v[i];
#pragma unroll
    for (int o = 16; o > 0; o >>= 1) s += __shfl_xor_sync(0xffffffffu, s, o);
    float mean = s * (1.f / 256.f);

    float sq = 0.f;
#pragma unroll
    for (int i = 0; i < 8; i++) { float dv = v[i] - mean; sq += dv * dv; }
#pragma unroll
    for (int o = 16; o > 0; o >>= 1) sq += __shfl_xor_sync(0xffffffffu, sq, o);
    float rstd = rsqrtf(sq * (1.f / 256.f) + 1e-5f);

    const float4* g4 = (const float4*)(g) + lane * 2;
    const float4* b4 = (const float4*)(b) + lane * 2;
    float4 ga = g4[0], gb = g4[1], ba = b4[0], bb = b4[1];
    float gg[8] = {ga.x, ga.y, ga.z, ga.w, gb.x, gb.y, gb.z, gb.w};
    float bbv[8] = {ba.x, ba.y, ba.z, ba.w, bb.x, bb.y, bb.z, bb.w};

    float o8[8];
    union { __half b[8]; uint4 u; } uh;
#pragma unroll
    for (int i = 0; i < 8; i++) {
        o8[i] = (v[i] - mean) * rstd * gg[i] + bbv[i];
        uh.b[i] = __float2half_rn(o8[i]);
    }

    float4* outp = (float4*)(out + (size_t)row * 256) + lane * 2;
    outp[0] = make_float4(o8[0], o8[1], o8[2], o8[3]);
    outp[1] = make_float4(o8[4], o8[5], o8[6], o8[7]);
    *(uint4*)(o16 + (size_t)row * 256 + lane * 8) = uh.u;
}

// ---------------------------------------------------------------------------
// Host orchestration.
// ---------------------------------------------------------------------------
static const int SMEM_BF = 2 * (32768 + 2 * 128 * 128);   // 131072
static const int SMEM16_128 = 2 * (16384 + 128 * 128);    // 65536
static const int SMEM16_64  = 2 * (16384 + 64 * 128);     // 49152

static void build_csr(const int* dst, int* cnt, int* rp, int* ei, int* bsum, int N, int E)
{
    cudaMemsetAsync(cnt, 0, (size_t)(N + 1) * sizeof(int), 0);
    count_edges<<<(E + 255) / 256, 256>>>(dst, cnt, E);
    int nb = (N + 1023) / 1024;
    scan_block<<<nb, 1024>>>(cnt, rp, bsum, N);
    scan_bsum<<<1, 32>>>(bsum, nb);
    scan_add<<<nb, 1024>>>(rp, bsum, N);
    copy_int<<<(N + 255) / 256, 256>>>(rp, cnt, N);
    fill_edges<<<(E + 255) / 256, 256>>>(dst, cnt, ei, E);
}

extern "C" void kernel_launch(void* const* d_in, const int* in_sizes, int n_in,
                              void* d_out, int out_size)
{
    const float* x_author = (const float*)d_in[0];
    const float* x_paper  = (const float*)d_in[1];
    const float* ew_wb    = (const float*)d_in[2];
    const float* ew_w     = (const float*)d_in[3];
    const float* ew_c     = (const float*)d_in[4];
    const float* adapt_W  = (const float*)d_in[5];
    const float* adapt_b  = (const float*)d_in[6];
    const float* kW       = (const float*)d_in[7];
    const float* kb       = (const float*)d_in[8];
    const float* qW       = (const float*)d_in[9];
    const float* qb       = (const float*)d_in[10];
    const float* mW       = (const float*)d_in[11];
    const float* mb       = (const float*)d_in[12];
    const float* aW       = (const float*)d_in[13];
    const float* ab       = (const float*)d_in[14];
    const float* w_pri    = (const float*)d_in[15];
    const float* w_att    = (const float*)d_in[16];
    const float* w_msg    = (const float*)d_in[17];
    const float* skip     = (const float*)d_in[18];
    const float* ln_g     = (const float*)d_in[19];
    const float* ln_b     = (const float*)d_in[20];
    const float* out_W    = (const float*)d_in[21];
    const float* out_b    = (const float*)d_in[22];
    const int* src_wb     = (const int*)d_in[23];
    const int* dst_wb     = (const int*)d_in[24];
    const int* src_w      = (const int*)d_in[25];
    const int* dst_w      = (const int*)d_in[26];
    const int* src_c      = (const int*)d_in[27];
    const int* dst_c      = (const int*)d_in[28];
    (void)in_sizes; (void)n_in; (void)out_size;

    cudaFuncSetAttribute(hmma_bf16<true, true>,   cudaFuncAttributeMaxDynamicSharedMemorySize, SMEM_BF);
    cudaFuncSetAttribute(hmma_bf16<false, false>, cudaFuncAttributeMaxDynamicSharedMemorySize, SMEM_BF);
    cudaFuncSetAttribute(hmma16<128, true>,  cudaFuncAttributeMaxDynamicSharedMemorySize, SMEM16_128);
    cudaFuncSetAttribute(hmma16<64, false>,  cudaFuncAttributeMaxDynamicSharedMemorySize, SMEM16_64);

    float *feats_a, *feats_p;
    __half *fa16, *fp16p, *proj_a, *proj_p, *W16;
    float *tr_a, *tr_p, *Wkp, *bkp, *Wmp, *bmp, *bias_p, *bias_a;
    int *rp_wb, *rp_w, *rp_c, *ei_wb, *ei_w, *ei_c, *cnt, *bsum;
    __nv_bfloat16 *xa_hi, *xa_lo, *xp_hi, *xp_lo;
    __nv_bfloat16 *ga_hi, *ga_lo, *gp_hi, *gp_lo, *Whi, *Wlo;
#define SYM(var, sym) cudaGetSymbolAddress((void**)&var, sym)
    SYM(feats_a, g_feats_a); SYM(feats_p, g_feats_p);
    SYM(fa16, g_fa16); SYM(fp16p, g_fp16);
    SYM(proj_a, g_proj_a); SYM(proj_p, g_proj_p);
    SYM(tr_a, g_tr_a); SYM(tr_p, g_tr_p);
    SYM(Wkp, g_Wk); SYM(bkp, g_bk); SYM(Wmp, g_Wm); SYM(bmp, g_bm);
    SYM(bias_p, g_bias_p); SYM(bias_a, g_bias_a);
    SYM(rp_wb, g_rp_wb); SYM(rp_w, g_rp_w); SYM(rp_c, g_rp_c);
    SYM(ei_wb, g_ei_wb); SYM(ei_w, g_ei_w); SYM(ei_c, g_ei_c);
    SYM(cnt, g_cnt); SYM(bsum, g_bsum);
    SYM(xa_hi, g_xa_hi); SYM(xa_lo, g_xa_lo); SYM(xp_hi, g_xp_hi); SYM(xp_lo, g_xp_lo);
    SYM(ga_hi, g_ga_hi); SYM(ga_lo, g_ga_lo); SYM(gp_hi, g_gp_hi); SYM(gp_lo, g_gp_lo);
    SYM(Whi, g_Whi); SYM(Wlo, g_Wlo); SYM(W16, g_W16);
#undef SYM

    float* fa[2] = {feats_a, feats_a + (size_t)NA * D};
    float* fp[2] = {feats_p, feats_p + (size_t)NP * D};

    const int GA = (NA + 127) / 128;   // 157
    const int GP = (NP + 127) / 128;   // 313

    // 0) weight prep + CSR build
    combine_weights<<<dim3(12, 257), 256>>>(kW, kb, mW, mb, w_att, w_msg, Wkp, bkp, Wmp, bmp);
    transpose_split<<<dim3(8, 8, NSLOT), dim3(32, 8)>>>(adapt_W, qW, Wkp, Wmp, aW, out_W, Whi, Wlo, W16);
    pack_bias<<<(LL * 2048 + 255) / 256, 256>>>(qb, bkp, bmp, bias_p, bias_a);
    build_csr(dst_wb, cnt, rp_wb, ei_wb, bsum, NA, E_WB);
    build_csr(dst_w,  cnt, rp_w,  ei_w,  bsum, NP, E_W);
    build_csr(dst_c,  cnt, rp_c,  ei_c,  bsum, NP, E_C);

    // 1) split inputs, adapt + GELU (bf16 3-term; emits fp32 + fp16 feats)
    split_hilo<<<(NA * D / 4 + 255) / 256, 256>>>(x_author, xa_hi, xa_lo, NA * D / 4);
    split_hilo<<<(NP * D / 4 + 255) / 256, 256>>>(x_paper, xp_hi, xp_lo, NP * D / 4);
    hmma_bf16<true, true><<<dim3(GA, 2), 512, SMEM_BF>>>(xa_hi, xa_lo, Whi, Wlo,
        adapt_b, fa[0], fa16, NA, 256, 1.f);
    hmma_bf16<true, true><<<dim3(GP, 2), 512, SMEM_BF>>>(xp_hi, xp_lo, Whi + 65536, Wlo + 65536,
        adapt_b + 256, fp[0], fp16p, NP, 256, 1.f);

    for (int l = 0; l < LL; l++) {
        int cur = l & 1, nxt = 1 - cur;

        // batched projections (fp16 1-term) -> fp16 proj buffers
        const size_t psl = (size_t)(2 + l * 8) * 65536;
        const size_t asl = (size_t)(2 + l * 8 + 5) * 65536;
        hmma16<128, true><<<dim3(GP, PSTR / 128), 512, SMEM16_128>>>(fp16p, W16 + psl,
            bias_p + l * PSTR, nullptr, proj_p, NP, PSTR);
        hmma16<128, true><<<dim3(GA, ASTR / 128), 512, SMEM16_128>>>(fa16, W16 + asl,
            bias_a + l * ASTR, nullptr, proj_a, NA, ASTR);

        // CSR aggregation, warp per dst -> bf16 hi/lo
        csr_agg1<<<(NA * 32 + 255) / 256, 256>>>(rp_wb, ei_wb, src_wb, ew_wb,
            w_pri + (l * 3 + 2) * 4, proj_a, ASTR, proj_p + 256, proj_p + 768, PSTR,
            ga_hi, ga_lo, NA);
        csr_agg2<<<(NP * 32 + 255) / 256, 256>>>(
            rp_w, ei_w, src_w, ew_w, w_pri + (l * 3 + 1) * 4, proj_a + 256, proj_a + 512, ASTR,
            rp_c, ei_c, src_c, ew_c, w_pri + (l * 3 + 0) * 4, proj_p + 512, proj_p + 1024, PSTR,
            proj_p, PSTR, gp_hi, gp_lo, NP);

        // a-projection (bf16 3-term; 0.5 paper mean via scale)
        const size_t aa = (size_t)(18 + l * 2 + 0) * 65536;
        const size_t ap = (size_t)(18 + l * 2 + 1) * 65536;
        hmma_bf16<false, false><<<dim3(GA, 2), 512, SMEM_BF>>>(ga_hi, ga_lo,
            Whi + aa, Wlo + aa, ab + (l * 2 + 0) * 256, tr_a, nullptr, NA, 256, 1.0f);
        hmma_bf16<false, false><<<dim3(GP, 2), 512, SMEM_BF>>>(gp_hi, gp_lo,
            Whi + ap, Wlo + ap, ab + (l * 2 + 1) * 256, tr_p, nullptr, NP, 256, 0.5f);

        // skip blend + LN (emits fp32 + fp16 feats)
        ln_blend_kernel<<<(NA + 7) / 8, 256>>>(tr_a, fa[cur], ln_g + (l * 2 + 0) * 256,
            ln_b + (l * 2 + 0) * 256, skip, l * 3 + 0, fa[nxt], fa16, NA);
        ln_blend_kernel<<<(NP + 7) / 8, 256>>>(tr_p, fp[cur], ln_g + (l * 2 + 1) * 256,
            ln_b + (l * 2 + 1) * 256, skip, l * 3 + 1, fp[nxt], fp16p, NP);
    }

    // output projection (fp16 1-term): fp16 paper feats @ out_W + out_b -> fp32
    hmma16<64, false><<<dim3(GP, 1), 512, SMEM16_64>>>(fp16p,
        W16 + (size_t)22 * 65536, out_b, (float*)d_out, nullptr, NP, 64);
}

// round 17
// speedup vs baseline: 2.2903x; 1.0626x over previous
#include <cuda_runtime.h>
#include <cuda_bf16.h>
#include <cuda_fp16.h>
#include <math.h>
#include <stdint.h>

// ---------------------------------------------------------------------------
// HGT forward.
// R17: software-pipelined CSR gather loops (prefetch next edge's load chain).
// GEMMs: adapt/a-proj bf16 hi/lo 3-term; projections/out-proj fp16 1-term.
// ---------------------------------------------------------------------------
#define NA     20000
#define NP     40000
#define D      256
#define DOUT   64
#define LL     2
#define E_WB   150000
#define E_W    150000
#define E_C    300000
#define NSLOT  23
#define PSTR   1280   // paper proj row: q | k_wb | k_c | m_wb | m_c
#define ASTR   768    // author proj row: q | k_w | m_w

// ------------------------- device scratch ----------------------------------
__device__ float g_feats_a[2][NA * D];
__device__ float g_feats_p[2][NP * D];
__device__ __half g_fa16[NA * D], g_fp16[NP * D];       // fp16 feats (proj A)
__device__ __half g_proj_a[NA * ASTR];
__device__ __half g_proj_p[NP * PSTR];
__device__ float g_tr_a[NA * D];
__device__ float g_tr_p[NP * D];
__device__ float g_Wk[LL * 3 * D * D];
__device__ float g_bk[LL * 3 * D];
__device__ float g_Wm[LL * 3 * D * D];
__device__ float g_bm[LL * 3 * D];
__device__ float g_bias_p[LL * PSTR];
__device__ float g_bias_a[LL * ASTR];
// CSR scratch
__device__ int g_rp_wb[NA + 1], g_rp_w[NP + 1], g_rp_c[NP + 1];
__device__ int g_ei_wb[E_WB], g_ei_w[E_W], g_ei_c[E_C];
__device__ int g_cnt[NP + 1];
__device__ int g_bsum[64];
// bf16 hi/lo operands (adapt inputs + agg)
__device__ __nv_bfloat16 g_xa_hi[NA * D], g_xa_lo[NA * D];
__device__ __nv_bfloat16 g_xp_hi[NP * D], g_xp_lo[NP * D];
__device__ __nv_bfloat16 g_ga_hi[NA * D], g_ga_lo[NA * D];
__device__ __nv_bfloat16 g_gp_hi[NP * D], g_gp_lo[NP * D];
__device__ __nv_bfloat16 g_Whi[NSLOT * D * D], g_Wlo[NSLOT * D * D];
__device__ __half g_W16[NSLOT * D * D];                 // fp16 weights (proj/out)

// ------------------------- small helpers -----------------------------------
__device__ __forceinline__ uint32_t smem_u32(const void* p) {
    uint32_t a;
    asm("{ .reg .u64 t; cvta.to.shared.u64 t, %1; cvt.u32.u64 %0, t; }" : "=r"(a) : "l"(p));
    return a;
}
#define SWZ(off) ((off) ^ (((off) >> 3) & 0x70))

#define CPASYNC16(dst, src) \
    asm volatile("cp.async.cg.shared.global [%0], [%1], 16;" :: "r"(dst), "l"(src) : "memory")

#define LDSM_X4(r0, r1, r2, r3, addr)                                         \
    asm volatile("ldmatrix.sync.aligned.m8n8.x4.shared.b16 {%0,%1,%2,%3}, [%4];" \
                 : "=r"(r0), "=r"(r1), "=r"(r2), "=r"(r3) : "r"(addr))

#define MMA_BF16(d, a, b0, b1)                                                \
    asm volatile("mma.sync.aligned.m16n8k16.row.col.f32.bf16.bf16.f32 "       \
                 "{%0,%1,%2,%3}, {%4,%5,%6,%7}, {%8,%9}, {%0,%1,%2,%3};"      \
                 : "+f"((d)[0]), "+f"((d)[1]), "+f"((d)[2]), "+f"((d)[3])     \
                 : "r"((a)[0]), "r"((a)[1]), "r"((a)[2]), "r"((a)[3]),        \
                   "r"(b0), "r"(b1))

#define MMA_FP16(d, a, b0, b1)                                                \
    asm volatile("mma.sync.aligned.m16n8k16.row.col.f32.f16.f16.f32 "         \
                 "{%0,%1,%2,%3}, {%4,%5,%6,%7}, {%8,%9}, {%0,%1,%2,%3};"      \
                 : "+f"((d)[0]), "+f"((d)[1]), "+f"((d)[2]), "+f"((d)[3])     \
                 : "r"((a)[0]), "r"((a)[1]), "r"((a)[2]), "r"((a)[3]),        \
                   "r"(b0), "r"(b1))

__device__ __forceinline__ float gelu_exact(float x) {
    return 0.5f * x * (1.0f + erff(x * 0.70710678118654752f));
}

// ---------------------------------------------------------------------------
// combine per-head w_att/w_msg into dense K/M projection weights (fp32).
// ---------------------------------------------------------------------------
__global__ void combine_weights(const float* __restrict__ kW, const float* __restrict__ kb,
                                const float* __restrict__ mW, const float* __restrict__ mb,
                                const float* __restrict__ w_att, const float* __restrict__ w_msg,
                                float* __restrict__ Wk, float* __restrict__ bk,
                                float* __restrict__ Wm, float* __restrict__ bm)
{
    int mat = blockIdx.x;
    int l = mat / 6;
    int r6 = mat % 6;
    int e = r6 / 2;
    int which = r6 % 2;
    int d = blockIdx.y;        // 0..256 (256 == bias row)
    int j = threadIdx.x;
    int h = j >> 6;
    int jj = j & 63;
    int st = (e == 1) ? 0 : 1;

    const float* W   = which ? mW : kW;
    const float* B   = which ? mb : kb;
    const float* att = which ? w_msg : w_att;

    const float* wrow;
    if (d < 256) wrow = W + (((size_t)(l * 2 + st) * 256 + d) * 256);
    else         wrow = B + ((size_t)(l * 2 + st) * 256);
    const float* a = att + ((size_t)((l * 3 + e) * 4 + h)) * 64 * 64;

    float s = 0.f;
#pragma unroll 8
    for (int c = 0; c < 64; c++)
        s += wrow[h * 64 + c] * a[c * 64 + jj];

    float* out  = which ? Wm : Wk;
    float* outb = which ? bm : bk;
    if (d < 256) out[((size_t)(l * 3 + e) * 256 + d) * 256 + j] = s;
    else         outb[(size_t)(l * 3 + e) * 256 + j] = s;
}

// ---------------------------------------------------------------------------
// Transpose + split weights: bf16 hi/lo (3-term path) + fp16 (1-term path).
// ---------------------------------------------------------------------------
__global__ void transpose_split(const float* __restrict__ adapt_W, const float* __restrict__ qW,
                                const float* __restrict__ Wk, const float* __restrict__ Wm,
                                const float* __restrict__ aW, const float* __restrict__ outW,
                                __nv_bfloat16* __restrict__ Whi, __nv_bfloat16* __restrict__ Wlo,
                                __half* __restrict__ W16)
{
    int slot = blockIdx.z;
    const float* src; int NC = 256;
    if (slot < 2)        src = adapt_W + (size_t)slot * 65536;
    else if (slot < 18) {
        int l = (slot - 2) / 8, o = (slot - 2) % 8;
        switch (o) {
            case 0: src = qW + (size_t)(l * 2 + 1) * 65536; break;
            case 1: src = Wk + (size_t)(l * 3 + 2) * 65536; break;
            case 2: src = Wk + (size_t)(l * 3 + 0) * 65536; break;
            case 3: src = Wm + (size_t)(l * 3 + 2) * 65536; break;
            case 4: src = Wm + (size_t)(l * 3 + 0) * 65536; break;
            case 5: src = qW + (size_t)(l * 2 + 0) * 65536; break;
            case 6: src = Wk + (size_t)(l * 3 + 1) * 65536; break;
            default: src = Wm + (size_t)(l * 3 + 1) * 65536; break;
        }
    }
    else if (slot < 22)  src = aW + (size_t)(slot - 18) * 65536;
    else               { src = outW; NC = 64; }

    int k0 = blockIdx.x * 32, n0 = blockIdx.y * 32;
    if (n0 >= NC) return;
    int tx = threadIdx.x, ty = threadIdx.y;

    __shared__ float t[32][33];
#pragma unroll
    for (int i = 0; i < 4; i++) {
        int k = k0 + ty + i * 8;
        t[ty + i * 8][tx] = src[(size_t)k * NC + n0 + tx];
    }
    __syncthreads();
#pragma unroll
    for (int i = 0; i < 4; i++) {
        int n = n0 + ty + i * 8, k = k0 + tx;
        float v = t[tx][ty + i * 8];
        __nv_bfloat16 h = __float2bfloat16(v);
        float r = v - __bfloat162float(h);
        size_t o = (size_t)slot * 65536 + (size_t)n * 256 + k;
        Whi[o] = h;
        Wlo[o] = __float2bfloat16(r);
        W16[o] = __float2half_rn(v);
    }
}

// ---------------------------------------------------------------------------
// Pack per-layer projection biases into the batched column layout.
// ---------------------------------------------------------------------------
__global__ void pack_bias(const float* __restrict__ qb, const float* __restrict__ bk,
                          const float* __restrict__ bm,
                          float* __restrict__ bp, float* __restrict__ ba)
{
    int idx = blockIdx.x * 256 + threadIdx.x;
    if (idx >= LL * 2048) return;
    int l = idx / 2048, r = idx % 2048;
    int seg = r >> 8, c = r & 255;
    float v;
    switch (seg) {
        case 0: v = qb[(l * 2 + 1) * 256 + c]; break;
        case 1: v = bk[(l * 3 + 2) * 256 + c]; break;
        case 2: v = bk[(l * 3 + 0) * 256 + c]; break;
        case 3: v = bm[(l * 3 + 2) * 256 + c]; break;
        case 4: v = bm[(l * 3 + 0) * 256 + c]; break;
        case 5: v = qb[(l * 2 + 0) * 256 + c]; break;
        case 6: v = bk[(l * 3 + 1) * 256 + c]; break;
        default: v = bm[(l * 3 + 1) * 256 + c]; break;
    }
    if (seg < 5) bp[l * PSTR + seg * 256 + c] = v;
    else         ba[l * ASTR + (seg - 5) * 256 + c] = v;
}

// ---------------------------------------------------------------------------
// fp32 -> bf16 hi/lo split (vectorized) — adapt inputs only.
// ---------------------------------------------------------------------------
__global__ void split_hilo(const float* __restrict__ s, __nv_bfloat16* __restrict__ hi,
                           __nv_bfloat16* __restrict__ lo, int n4)
{
    int i = blockIdx.x * blockDim.x + threadIdx.x;
    if (i >= n4) return;
    float4 v = ((const float4*)s)[i];
    __nv_bfloat16 h[4], l[4];
    float vv[4] = {v.x, v.y, v.z, v.w};
#pragma unroll
    for (int j = 0; j < 4; j++) {
        h[j] = __float2bfloat16(vv[j]);
        l[j] = __float2bfloat16(vv[j] - __bfloat162float(h[j]));
    }
    ((uint2*)hi)[i] = *(uint2*)h;
    ((uint2*)lo)[i] = *(uint2*)l;
}

// ---------------------------------------------------------------------------
// CSR build: count -> two-level exclusive scan -> fill.
// ---------------------------------------------------------------------------
__global__ void count_edges(const int* __restrict__ dst, int* __restrict__ cnt, int E)
{
    int i = blockIdx.x * blockDim.x + threadIdx.x;
    if (i < E) atomicAdd(&cnt[dst[i]], 1);
}
__global__ void scan_block(const int* __restrict__ cnt, int* __restrict__ rp,
                           int* __restrict__ bsum, int n)
{
    __shared__ int sh[1024];
    int i = blockIdx.x * 1024 + threadIdx.x;
    sh[threadIdx.x] = (i < n) ? cnt[i] : 0;
    __syncthreads();
#pragma unroll
    for (int off = 1; off < 1024; off <<= 1) {
        int t = (threadIdx.x >= off) ? sh[threadIdx.x - off] : 0;
        __syncthreads();
        sh[threadIdx.x] += t;
        __syncthreads();
    }
    if (i < n) rp[i + 1] = sh[threadIdx.x];
    if (threadIdx.x == 1023) bsum[blockIdx.x] = sh[1023];
}
__global__ void scan_bsum(int* __restrict__ bsum, int nb)
{
    if (threadIdx.x == 0) {
        int run = 0;
        for (int i = 0; i < nb; i++) { int v = bsum[i]; bsum[i] = run; run += v; }
    }
}
__global__ void scan_add(int* __restrict__ rp, const int* __restrict__ bsum, int n)
{
    int i = blockIdx.x * 1024 + threadIdx.x;
    if (i < n) rp[i + 1] += bsum[blockIdx.x];
    if (blockIdx.x == 0 && threadIdx.x == 0) rp[0] = 0;
}
__global__ void copy_int(const int* __restrict__ a, int* __restrict__ b, int n)
{
    int i = blockIdx.x * blockDim.x + threadIdx.x;
    if (i < n) b[i] = a[i];
}
__global__ void fill_edges(const int* __restrict__ dst, int* __restrict__ cur,
                           int* __restrict__ ei, int E)
{
    int i = blockIdx.x * blockDim.x + threadIdx.x;
    if (i < E) ei[atomicAdd(&cur[dst[i]], 1)] = i;
}

// ---------------------------------------------------------------------------
// bf16 hi/lo 3-term GEMM (adapt, a-proj). 512 threads, tile 128 x 128.
// ---------------------------------------------------------------------------
#define A_HI_OFF  0
#define A_LO_OFF  16384

template <bool GELU, bool F16OUT>
__global__ void __launch_bounds__(512, 1)
hmma_bf16(const __nv_bfloat16* __restrict__ Ahi, const __nv_bfloat16* __restrict__ Alo,
          const __nv_bfloat16* __restrict__ Whi, const __nv_bfloat16* __restrict__ Wlo,
          const float* __restrict__ bias, float* __restrict__ C,
          __half* __restrict__ Ch,
          int M, int Ntot, float scale)
{
    constexpr int BN = 128, WN = 32, NT = 2;
    constexpr int B_HI_OFF = 32768;
    constexpr int B_LO_OFF = 32768 + BN * 128;
    constexpr int STG = 32768 + 2 * BN * 128;
    constexpr int A_OPS = 2048;
    constexpr int TOT_OPS = A_OPS + BN * 16;

    extern __shared__ __align__(1024) char sm[];
    const uint32_t sb = smem_u32(sm);

    const int tid = threadIdx.x;
    const int lane = tid & 31, wid = tid >> 5;
    const int wm = wid & 3, wn = wid >> 2;
    const int m0 = blockIdx.x * 128, n0 = blockIdx.y * BN;

    auto load_chunk = [&](int kc, int stg) {
        uint32_t base = sb + stg * STG;
        int kb = kc * 64;
#pragma unroll
        for (int it = tid; it < TOT_OPS; it += 512) {
            bool isA = it < A_OPS;
            int i = isA ? (it & 1023) : ((it - A_OPS) % (BN * 8));
            bool isHi = isA ? (it < 1024) : ((it - A_OPS) < BN * 8);
            int r = i >> 3, s = i & 7;
            uint32_t o = SWZ((uint32_t)(r * 128 + s * 16));
            if (isA) {
                if (m0 + r < M) {
                    const __nv_bfloat16* gp = (isHi ? Ahi : Alo) + (size_t)(m0 + r) * 256 + kb + s * 8;
                    CPASYNC16(base + (isHi ? A_HI_OFF : A_LO_OFF) + o, gp);
                }
            } else {
                const __nv_bfloat16* gp = (isHi ? Whi : Wlo) + (size_t)(n0 + r) * 256 + kb + s * 8;
                CPASYNC16(base + (isHi ? B_HI_OFF : B_LO_OFF) + o, gp);
            }
        }
        asm volatile("cp.async.commit_group;" ::: "memory");
    };

    float d[2][2 * NT][4];
#pragma unroll
    for (int i = 0; i < 2; i++)
#pragma unroll
        for (int j = 0; j < 2 * NT; j++)
#pragma unroll
            for (int r = 0; r < 4; r++) d[i][j][r] = 0.f;

    const int g = lane >> 3, l7 = lane & 7;
    const int a_row_off = (g & 1) ? 8 : 0;
    const int a_byte_off = (g & 2) ? 16 : 0;
    const int b_row_off = (g & 2) ? 8 : 0;
    const int b_byte_off = (g & 1) ? 16 : 0;

    load_chunk(0, 0);

    for (int kc = 0; kc < 4; kc++) {
        if (kc < 3) load_chunk(kc + 1, (kc + 1) & 1);
        if (kc < 3) asm volatile("cp.async.wait_group 1;" ::: "memory");
        else        asm volatile("cp.async.wait_group 0;" ::: "memory");
        __syncthreads();

        uint32_t base = sb + (kc & 1) * STG;
#pragma unroll
        for (int kk = 0; kk < 4; kk++) {
            int kb2 = kk * 32;
            uint32_t a_hi[2][4], a_lo[2][4], b_hi[NT][4], b_lo[NT][4];
#pragma unroll
            for (int i = 0; i < 2; i++) {
                uint32_t o = SWZ((uint32_t)((wm * 32 + i * 16 + l7 + a_row_off) * 128 + kb2 + a_byte_off));
                LDSM_X4(a_hi[i][0], a_hi[i][1], a_hi[i][2], a_hi[i][3], base + A_HI_OFF + o);
                LDSM_X4(a_lo[i][0], a_lo[i][1], a_lo[i][2], a_lo[i][3], base + A_LO_OFF + o);
            }
#pragma unroll
            for (int jt = 0; jt < NT; jt++) {
                uint32_t o = SWZ((uint32_t)((wn * WN + jt * 16 + l7 + b_row_off) * 128 + kb2 + b_byte_off));
                LDSM_X4(b_hi[jt][0], b_hi[jt][1], b_hi[jt][2], b_hi[jt][3], base + B_HI_OFF + o);
                LDSM_X4(b_lo[jt][0], b_lo[jt][1], b_lo[jt][2], b_lo[jt][3], base + B_LO_OFF + o);
            }
#pragma unroll
            for (int i = 0; i < 2; i++)
#pragma unroll
                for (int jt = 0; jt < NT; jt++)
#pragma unroll
                    for (int half = 0; half < 2; half++) {
                        int j = jt * 2 + half, sel = half * 2;
                        MMA_BF16(d[i][j], a_hi[i], b_hi[jt][sel], b_hi[jt][sel + 1]);
                        MMA_BF16(d[i][j], a_hi[i], b_lo[jt][sel], b_lo[jt][sel + 1]);
                        MMA_BF16(d[i][j], a_lo[i], b_hi[jt][sel], b_hi[jt][sel + 1]);
                    }
        }
        __syncthreads();
    }

    const int r_base = m0 + wm * 32;
    const int c_base = n0 + wn * WN;
#pragma unroll
    for (int i = 0; i < 2; i++)
#pragma unroll
        for (int j = 0; j < 2 * NT; j++) {
            int col = c_base + j * 8 + (lane & 3) * 2;
            float2 b2 = *(const float2*)(bias + col);
#pragma unroll
            for (int half = 0; half < 2; half++) {
                int row = r_base + i * 16 + (lane >> 2) + half * 8;
                if (row >= M) continue;
                float vx = d[i][j][half * 2 + 0] * scale + b2.x;
                float vy = d[i][j][half * 2 + 1] * scale + b2.y;
                if (GELU) { vx = gelu_exact(vx); vy = gelu_exact(vy); }
                *(float2*)(C + (size_t)row * Ntot + col) = make_float2(vx, vy);
                if (F16OUT) {
                    union { __half b[2]; uint32_t u; } ub;
                    ub.b[0] = __float2half_rn(vx);
                    ub.b[1] = __float2half_rn(vy);
                    *(uint32_t*)(Ch + (size_t)row * Ntot + col) = ub.u;
                }
            }
        }
}

// ---------------------------------------------------------------------------
// fp16 single-term GEMM (projections, out-proj). 512 threads, tile 128 x BN.
// ---------------------------------------------------------------------------
template <int BN, bool OUTH>
__global__ void __launch_bounds__(512, 1)
hmma16(const __half* __restrict__ A, const __half* __restrict__ W,
       const float* __restrict__ bias, float* __restrict__ C,
       __half* __restrict__ Ch, int M, int Ntot)
{
    constexpr int WN = BN / 4;
    constexpr int NT = WN / 16;
    constexpr int B_OFF = 16384;
    constexpr int STG = 16384 + BN * 128;
    constexpr int A_OPS = 1024;
    constexpr int TOT_OPS = A_OPS + BN * 8;

    extern __shared__ __align__(1024) char sm[];
    const uint32_t sb = smem_u32(sm);

    const int tid = threadIdx.x;
    const int lane = tid & 31, wid = tid >> 5;
    const int wm = wid & 3, wn = wid >> 2;
    const int m0 = blockIdx.x * 128, n0 = blockIdx.y * BN;

    auto load_chunk = [&](int kc, int stg) {
        uint32_t base = sb + stg * STG;
        int kb = kc * 64;
#pragma unroll
        for (int it = tid; it < TOT_OPS; it += 512) {
            bool isA = it < A_OPS;
            int i = isA ? it : (it - A_OPS);
            int r = i >> 3, s = i & 7;
            uint32_t o = SWZ((uint32_t)(r * 128 + s * 16));
            if (isA) {
                if (m0 + r < M)
                    CPASYNC16(base + o, A + (size_t)(m0 + r) * 256 + kb + s * 8);
            } else {
                CPASYNC16(base + B_OFF + o, W + (size_t)(n0 + r) * 256 + kb + s * 8);
            }
        }
        asm volatile("cp.async.commit_group;" ::: "memory");
    };

    float d[2][2 * NT][4];
#pragma unroll
    for (int i = 0; i < 2; i++)
#pragma unroll
        for (int j = 0; j < 2 * NT; j++)
#pragma unroll
            for (int r = 0; r < 4; r++) d[i][j][r] = 0.f;

    const int g = lane >> 3, l7 = lane & 7;
    const int a_row_off = (g & 1) ? 8 : 0;
    const int a_byte_off = (g & 2) ? 16 : 0;
    const int b_row_off = (g & 2) ? 8 : 0;
    const int b_byte_off = (g & 1) ? 16 : 0;

    load_chunk(0, 0);

    for (int kc = 0; kc < 4; kc++) {
        if (kc < 3) load_chunk(kc + 1, (kc + 1) & 1);
        if (kc < 3) asm volatile("cp.async.wait_group 1;" ::: "memory");
        else        asm volatile("cp.async.wait_group 0;" ::: "memory");
        __syncthreads();

        uint32_t base = sb + (kc & 1) * STG;
#pragma unroll
        for (int kk = 0; kk < 4; kk++) {
            int kb2 = kk * 32;
            uint32_t a[2][4], b[NT][4];
#pragma unroll
            for (int i = 0; i < 2; i++) {
                uint32_t o = SWZ((uint32_t)((wm * 32 + i * 16 + l7 + a_row_off) * 128 + kb2 + a_byte_off));
                LDSM_X4(a[i][0], a[i][1], a[i][2], a[i][3], base + o);
            }
#pragma unroll
            for (int jt = 0; jt < NT; jt++) {
                uint32_t o = SWZ((uint32_t)((wn * WN + jt * 16 + l7 + b_row_off) * 128 + kb2 + b_byte_off));
                LDSM_X4(b[jt][0], b[jt][1], b[jt][2], b[jt][3], base + B_OFF + o);
            }
#pragma unroll
            for (int i = 0; i < 2; i++)
#pragma unroll
                for (int jt = 0; jt < NT; jt++)
#pragma unroll
                    for (int half = 0; half < 2; half++) {
                        int j = jt * 2 + half, sel = half * 2;
                        MMA_FP16(d[i][j], a[i], b[jt][sel], b[jt][sel + 1]);
                    }
        }
        __syncthreads();
    }

    const int r_base = m0 + wm * 32;
    const int c_base = n0 + wn * WN;
#pragma unroll
    for (int i = 0; i < 2; i++)
#pragma unroll
        for (int j = 0; j < 2 * NT; j++) {
            int col = c_base + j * 8 + (lane & 3) * 2;
            float2 b2 = *(const float2*)(bias + col);
#pragma unroll
            for (int half = 0; half < 2; half++) {
                int row = r_base + i * 16 + (lane >> 2) + half * 8;
                if (row >= M) continue;
                float vx = d[i][j][half * 2 + 0] + b2.x;
                float vy = d[i][j][half * 2 + 1] + b2.y;
                if (OUTH) {
                    union { __half b[2]; uint32_t u; } ub;
                    ub.b[0] = __float2half_rn(vx);
                    ub.b[1] = __float2half_rn(vy);
                    *(uint32_t*)(Ch + (size_t)row * Ntot + col) = ub.u;
                } else {
                    *(float2*)(C + (size_t)row * Ntot + col) = make_float2(vx, vy);
                }
            }
        }
}

// ---------------------------------------------------------------------------
// Pipelined per-edge body: compute with current regs while next loads fly.
// ---------------------------------------------------------------------------
struct EdgeRegs {
    uint4 kv, mv;
    float ew;
};

__device__ __forceinline__ void edge_prefetch(const int* __restrict__ ei,
                                              const int* __restrict__ src,
                                              const float* __restrict__ ew,
                                              const __half* __restrict__ kbase,
                                              const __half* __restrict__ mbase,
                                              int kms, int j, int lane, EdgeRegs& r)
{
    int eid = ei[j];
    int s = src[eid];
    r.kv = *(const uint4*)(kbase + (size_t)s * kms + lane * 8);
    r.mv = *(const uint4*)(mbase + (size_t)s * kms + lane * 8);
    r.ew = ew[eid];
}

__device__ __forceinline__ void edge_compute(const EdgeRegs& r, const float* qf,
                                             float prih, float* acc)
{
    union { uint4 u; __half2 h2[4]; } kv, mv;
    kv.u = r.kv; mv.u = r.mv;
    float p = 0.f;
#pragma unroll
    for (int i = 0; i < 4; i++) {
        float2 kf = __half22float2(kv.h2[i]);
        p += qf[2 * i] * kf.x + qf[2 * i + 1] * kf.y;
    }
    p += __shfl_xor_sync(0xffffffffu, p, 1);
    p += __shfl_xor_sync(0xffffffffu, p, 2);
    p += __shfl_xor_sync(0xffffffffu, p, 4);
    float attn = r.ew / (1.f + __expf(-p * prih));
#pragma unroll
    for (int i = 0; i < 4; i++) {
        float2 mf = __half22float2(mv.h2[i]);
        acc[2 * i]     += mf.x * attn;
        acc[2 * i + 1] += mf.y * attn;
    }
}

// ---------------------------------------------------------------------------
// CSR aggregation, author side (single relation): warp per dst, pipelined.
// ---------------------------------------------------------------------------
__global__ void csr_agg1(const int* __restrict__ rp, const int* __restrict__ ei,
                         const int* __restrict__ src, const float* __restrict__ ew,
                         const float* __restrict__ pri,
                         const __half* __restrict__ q, int qs,
                         const __half* __restrict__ khat, const __half* __restrict__ mhat, int kms,
                         __nv_bfloat16* __restrict__ ohi, __nv_bfloat16* __restrict__ olo,
                         int N)
{
    int node = (int)((blockIdx.x * (size_t)blockDim.x + threadIdx.x) >> 5);
    int lane = threadIdx.x & 31;
    if (node >= N) return;

    int beg = rp[node], end = rp[node + 1];
    float prih = pri[lane >> 3] * 0.125f;

    union { uint4 u; __half2 h2[4]; } qv;
    qv.u = *(const uint4*)(q + (size_t)node * qs + lane * 8);
    float qf[8];
#pragma unroll
    for (int i = 0; i < 4; i++) {
        float2 f = __half22float2(qv.h2[i]);
        qf[2 * i] = f.x; qf[2 * i + 1] = f.y;
    }

    float acc[8];
#pragma unroll
    for (int i = 0; i < 8; i++) acc[i] = 0.f;

    EdgeRegs cur, nxt;
    if (beg < end) edge_prefetch(ei, src, ew, khat, mhat, kms, beg, lane, cur);
    for (int j = beg; j < end; j++) {
        if (j + 1 < end) edge_prefetch(ei, src, ew, khat, mhat, kms, j + 1, lane, nxt);
        edge_compute(cur, qf, prih, acc);
        cur = nxt;
    }

    union { __nv_bfloat16 b[8]; uint4 u; } uh, ul;
#pragma unroll
    for (int i = 0; i < 8; i++) {
        uh.b[i] = __float2bfloat16(acc[i]);
        ul.b[i] = __float2bfloat16(acc[i] - __bfloat162float(uh.b[i]));
    }
    *(uint4*)(ohi + (size_t)node * 256 + lane * 8) = uh.u;
    *(uint4*)(olo + (size_t)node * 256 + lane * 8) = ul.u;
}

// ---------------------------------------------------------------------------
// CSR aggregation, paper side: WRITES then CITES fused, both loops pipelined.
// ---------------------------------------------------------------------------
__global__ void csr_agg2(const int* __restrict__ rp1, const int* __restrict__ ei1,
                         const int* __restrict__ src1, const float* __restrict__ ew1,
                         const float* __restrict__ pri1,
                         const __half* __restrict__ k1, const __half* __restrict__ m1, int kms1,
                         const int* __restrict__ rp2, const int* __restrict__ ei2,
                         const int* __restrict__ src2, const float* __restrict__ ew2,
                         const float* __restrict__ pri2,
                         const __half* __restrict__ k2, const __half* __restrict__ m2, int kms2,
                         const __half* __restrict__ q, int qs,
                         __nv_bfloat16* __restrict__ ohi, __nv_bfloat16* __restrict__ olo,
                         int N)
{
    int node = (int)((blockIdx.x * (size_t)blockDim.x + threadIdx.x) >> 5);
    int lane = threadIdx.x & 31;
    if (node >= N) return;

    float prih1 = pri1[lane >> 3] * 0.125f;
    float prih2 = pri2[lane >> 3] * 0.125f;

    union { uint4 u; __half2 h2[4]; } qv;
    qv.u = *(const uint4*)(q + (size_t)node * qs + lane * 8);
    float qf[8];
#pragma unroll
    for (int i = 0; i < 4; i++) {
        float2 f = __half22float2(qv.h2[i]);
        qf[2 * i] = f.x; qf[2 * i + 1] = f.y;
    }

    float acc[8];
#pragma unroll
    for (int i = 0; i < 8; i++) acc[i] = 0.f;

    int beg1 = rp1[node], end1 = rp1[node + 1];
    int beg2 = rp2[node], end2 = rp2[node + 1];

    EdgeRegs cur, nxt;
    // relation 1 (WRITES); prefetch crosses into relation 2's first edge
    if (beg1 < end1) edge_prefetch(ei1, src1, ew1, k1, m1, kms1, beg1, lane, cur);
    else if (beg2 < end2) edge_prefetch(ei2, src2, ew2, k2, m2, kms2, beg2, lane, cur);
    for (int j = beg1; j < end1; j++) {
        if (j + 1 < end1)      edge_prefetch(ei1, src1, ew1, k1, m1, kms1, j + 1, lane, nxt);
        else if (beg2 < end2)  edge_prefetch(ei2, src2, ew2, k2, m2, kms2, beg2, lane, nxt);
        edge_compute(cur, qf, prih1, acc);
        cur = nxt;
    }
    // relation 2 (CITES)
    for (int j = beg2; j < end2; j++) {
        if (j + 1 < end2) edge_prefetch(ei2, src2, ew2, k2, m2, kms2, j + 1, lane, nxt);
        edge_compute(cur, qf, prih2, acc);
        cur = nxt;
    }

    union { __nv_bfloat16 b[8]; uint4 u; } uh, ul;
#pragma unroll
    for (int i = 0; i < 8; i++) {
        uh.b[i] = __float2bfloat16(acc[i]);
        ul.b[i] = __float2bfloat16(acc[i] - __bfloat162float(uh.b[i]));
    }
    *(uint4*)(ohi + (size_t)node * 256 + lane * 8) = uh.u;
    *(uint4*)(olo + (size_t)node * 256 + lane * 8) = ul.u;
}

// ---------------------------------------------------------------------------
// Skip-blend + LayerNorm; emits fp32 feats + fp16 feats.
// ---------------------------------------------------------------------------
__global__ void ln_blend_kernel(const float* __restrict__ tr, const float* __restrict__ feats,
                                const float* __restrict__ g, const float* __restrict__ b,
                                const float* __restrict__ skip, int skip_idx,
                                float* __restrict__ out, __half* __restrict__ o16,
                                int N)
{
    int row = (int)((blockIdx.x * (size_t)blockDim.x + threadIdx.x) >> 5);
    int lane = threadIdx.x & 31;
    if (row >= N) return;

    float alpha = 1.f / (1.f + __expf(-skip[skip_idx]));
    float beta = 1.f - alpha;

    const float4* t4 = (const float4*)(tr    + (size_t)row * 256) + lane * 2;
    const float4* f4 = (const float4*)(feats + (size_t)row * 256) + lane * 2;
    float4 ta = t4[0], tb = t4[1], fa = f4[0], fb = f4[1];

    float v[8];
    v[0] = ta.x * alpha + fa.x * beta;  v[1] = ta.y * alpha + fa.y * beta;
    v[2] = ta.z * alpha + fa.z * beta;  v[3] = ta.w * alpha + fa.w * beta;
    v[4] = tb.x * alpha + fb.x * beta;  v[5] = tb.y * alpha + fb.y * beta;
    v[6] = tb.z * alpha + fb.z * beta;  v[7] = tb.w * alpha + fb.w * beta;

    float s = 0.f;
#pragma unroll
    for (int i = 0; i < 8; i++) s += v[i];
#pragma unroll
    for (int o = 16; o > 0; o >>= 1) s += __shfl_xor_sync(0xffffffffu, s, o);
    float mean = s * (1.f / 256.f);

    float sq = 0.f;
#pragma unroll
    for (int i = 0; i < 8; i++) { float dv = v[i] - mean; sq += dv * dv; }
#pragma unroll
    for (int o = 16; o > 0; o >>= 1) sq += __shfl_xor_sync(0xffffffffu, sq, o);
    float rstd = rsqrtf(sq * (1.f / 256.f) + 1e-5f);

    const float4* g4 = (const float4*)(g) + lane * 2;
    const float4* b4 = (const float4*)(b) + lane * 2;
    float4 ga = g4[0], gb = g4[1], ba = b4[0], bb = b4[1];
    float gg[8] = {ga.x, ga.y, ga.z, ga.w, gb.x, gb.y, gb.z, gb.w};
    float bbv[8] = {ba.x, ba.y, ba.z, ba.w, bb.x, bb.y, bb.z, bb.w};

    float o8[8];
    union { __half b[8]; uint4 u; } uh;
#pragma unroll
    for (int i = 0; i < 8; i++) {
        o8[i] = (v[i] - mean) * rstd * gg[i] + bbv[i];
        uh.b[i] = __float2half_rn(o8[i]);
    }

    float4* outp = (float4*)(out + (size_t)row * 256) + lane * 2;
    outp[0] = make_float4(o8[0], o8[1], o8[2], o8[3]);
    outp[1] = make_float4(o8[4], o8[5], o8[6], o8[7]);
    *(uint4*)(o16 + (size_t)row * 256 + lane * 8) = uh.u;
}

// ---------------------------------------------------------------------------
// Host orchestration.
// ---------------------------------------------------------------------------
static const int SMEM_BF = 2 * (32768 + 2 * 128 * 128);   // 131072
static const int SMEM16_128 = 2 * (16384 + 128 * 128);    // 65536
static const int SMEM16_64  = 2 * (16384 + 64 * 128);     // 49152

static void build_csr(const int* dst, int* cnt, int* rp, int* ei, int* bsum, int N, int E)
{
    cudaMemsetAsync(cnt, 0, (size_t)(N + 1) * sizeof(int), 0);
    count_edges<<<(E + 255) / 256, 256>>>(dst, cnt, E);
    int nb = (N + 1023) / 1024;
    scan_block<<<nb, 1024>>>(cnt, rp, bsum, N);
    scan_bsum<<<1, 32>>>(bsum, nb);
    scan_add<<<nb, 1024>>>(rp, bsum, N);
    copy_int<<<(N + 255) / 256, 256>>>(rp, cnt, N);
    fill_edges<<<(E + 255) / 256, 256>>>(dst, cnt, ei, E);
}

extern "C" void kernel_launch(void* const* d_in, const int* in_sizes, int n_in,
                              void* d_out, int out_size)
{
    const float* x_author = (const float*)d_in[0];
    const float* x_paper  = (const float*)d_in[1];
    const float* ew_wb    = (const float*)d_in[2];
    const float* ew_w     = (const float*)d_in[3];
    const float* ew_c     = (const float*)d_in[4];
    const float* adapt_W  = (const float*)d_in[5];
    const float* adapt_b  = (const float*)d_in[6];
    const float* kW       = (const float*)d_in[7];
    const float* kb       = (const float*)d_in[8];
    const float* qW       = (const float*)d_in[9];
    const float* qb       = (const float*)d_in[10];
    const float* mW       = (const float*)d_in[11];
    const float* mb       = (const float*)d_in[12];
    const float* aW       = (const float*)d_in[13];
    const float* ab       = (const float*)d_in[14];
    const float* w_pri    = (const float*)d_in[15];
    const float* w_att    = (const float*)d_in[16];
    const float* w_msg    = (const float*)d_in[17];
    const float* skip     = (const float*)d_in[18];
    const float* ln_g     = (const float*)d_in[19];
    const float* ln_b     = (const float*)d_in[20];
    const float* out_W    = (const float*)d_in[21];
    const float* out_b    = (const float*)d_in[22];
    const int* src_wb     = (const int*)d_in[23];
    const int* dst_wb     = (const int*)d_in[24];
    const int* src_w      = (const int*)d_in[25];
    const int* dst_w      = (const int*)d_in[26];
    const int* src_c      = (const int*)d_in[27];
    const int* dst_c      = (const int*)d_in[28];
    (void)in_sizes; (void)n_in; (void)out_size;

    cudaFuncSetAttribute(hmma_bf16<true, true>,   cudaFuncAttributeMaxDynamicSharedMemorySize, SMEM_BF);
    cudaFuncSetAttribute(hmma_bf16<false, false>, cudaFuncAttributeMaxDynamicSharedMemorySize, SMEM_BF);
    cudaFuncSetAttribute(hmma16<128, true>,  cudaFuncAttributeMaxDynamicSharedMemorySize, SMEM16_128);
    cudaFuncSetAttribute(hmma16<64, false>,  cudaFuncAttributeMaxDynamicSharedMemorySize, SMEM16_64);

    float *feats_a, *feats_p;
    __half *fa16, *fp16p, *proj_a, *proj_p, *W16;
    float *tr_a, *tr_p, *Wkp, *bkp, *Wmp, *bmp, *bias_p, *bias_a;
    int *rp_wb, *rp_w, *rp_c, *ei_wb, *ei_w, *ei_c, *cnt, *bsum;
    __nv_bfloat16 *xa_hi, *xa_lo, *xp_hi, *xp_lo;
    __nv_bfloat16 *ga_hi, *ga_lo, *gp_hi, *gp_lo, *Whi, *Wlo;
#define SYM(var, sym) cudaGetSymbolAddress((void**)&var, sym)
    SYM(feats_a, g_feats_a); SYM(feats_p, g_feats_p);
    SYM(fa16, g_fa16); SYM(fp16p, g_fp16);
    SYM(proj_a, g_proj_a); SYM(proj_p, g_proj_p);
    SYM(tr_a, g_tr_a); SYM(tr_p, g_tr_p);
    SYM(Wkp, g_Wk); SYM(bkp, g_bk); SYM(Wmp, g_Wm); SYM(bmp, g_bm);
    SYM(bias_p, g_bias_p); SYM(bias_a, g_bias_a);
    SYM(rp_wb, g_rp_wb); SYM(rp_w, g_rp_w); SYM(rp_c, g_rp_c);
    SYM(ei_wb, g_ei_wb); SYM(ei_w, g_ei_w); SYM(ei_c, g_ei_c);
    SYM(cnt, g_cnt); SYM(bsum, g_bsum);
    SYM(xa_hi, g_xa_hi); SYM(xa_lo, g_xa_lo); SYM(xp_hi, g_xp_hi); SYM(xp_lo, g_xp_lo);
    SYM(ga_hi, g_ga_hi); SYM(ga_lo, g_ga_lo); SYM(gp_hi, g_gp_hi); SYM(gp_lo, g_gp_lo);
    SYM(Whi, g_Whi); SYM(Wlo, g_Wlo); SYM(W16, g_W16);
#undef SYM

    float* fa[2] = {feats_a, feats_a + (size_t)NA * D};
    float* fp[2] = {feats_p, feats_p + (size_t)NP * D};

    const int GA = (NA + 127) / 128;   // 157
    const int GP = (NP + 127) / 128;   // 313

    // 0) weight prep + CSR build
    combine_weights<<<dim3(12, 257), 256>>>(kW, kb, mW, mb, w_att, w_msg, Wkp, bkp, Wmp, bmp);
    transpose_split<<<dim3(8, 8, NSLOT), dim3(32, 8)>>>(adapt_W, qW, Wkp, Wmp, aW, out_W, Whi, Wlo, W16);
    pack_bias<<<(LL * 2048 + 255) / 256, 256>>>(qb, bkp, bmp, bias_p, bias_a);
    build_csr(dst_wb, cnt, rp_wb, ei_wb, bsum, NA, E_WB);
    build_csr(dst_w,  cnt, rp_w,  ei_w,  bsum, NP, E_W);
    build_csr(dst_c,  cnt, rp_c,  ei_c,  bsum, NP, E_C);

    // 1) split inputs, adapt + GELU (bf16 3-term; emits fp32 + fp16 feats)
    split_hilo<<<(NA * D / 4 + 255) / 256, 256>>>(x_author, xa_hi, xa_lo, NA * D / 4);
    split_hilo<<<(NP * D / 4 + 255) / 256, 256>>>(x_paper, xp_hi, xp_lo, NP * D / 4);
    hmma_bf16<true, true><<<dim3(GA, 2), 512, SMEM_BF>>>(xa_hi, xa_lo, Whi, Wlo,
        adapt_b, fa[0], fa16, NA, 256, 1.f);
    hmma_bf16<true, true><<<dim3(GP, 2), 512, SMEM_BF>>>(xp_hi, xp_lo, Whi + 65536, Wlo + 65536,
        adapt_b + 256, fp[0], fp16p, NP, 256, 1.f);

    for (int l = 0; l < LL; l++) {
        int cur = l & 1, nxt = 1 - cur;

        // batched projections (fp16 1-term) -> fp16 proj buffers
        const size_t psl = (size_t)(2 + l * 8) * 65536;
        const size_t asl = (size_t)(2 + l * 8 + 5) * 65536;
        hmma16<128, true><<<dim3(GP, PSTR / 128), 512, SMEM16_128>>>(fp16p, W16 + psl,
            bias_p + l * PSTR, nullptr, proj_p, NP, PSTR);
        hmma16<128, true><<<dim3(GA, ASTR / 128), 512, SMEM16_128>>>(fa16, W16 + asl,
            bias_a + l * ASTR, nullptr, proj_a, NA, ASTR);

        // CSR aggregation (pipelined), warp per dst -> bf16 hi/lo
        csr_agg1<<<(NA * 32 + 255) / 256, 256>>>(rp_wb, ei_wb, src_wb, ew_wb,
            w_pri + (l * 3 + 2) * 4, proj_a, ASTR, proj_p + 256, proj_p + 768, PSTR,
            ga_hi, ga_lo, NA);
        csr_agg2<<<(NP * 32 + 255) / 256, 256>>>(
            rp_w, ei_w, src_w, ew_w, w_pri + (l * 3 + 1) * 4, proj_a + 256, proj_a + 512, ASTR,
            rp_c, ei_c, src_c, ew_c, w_pri + (l * 3 + 0) * 4, proj_p + 512, proj_p + 1024, PSTR,
            proj_p, PSTR, gp_hi, gp_lo, NP);

        // a-projection (bf16 3-term; 0.5 paper mean via scale)
        const size_t aa = (size_t)(18 + l * 2 + 0) * 65536;
        const size_t ap = (size_t)(18 + l * 2 + 1) * 65536;
        hmma_bf16<false, false><<<dim3(GA, 2), 512, SMEM_BF>>>(ga_hi, ga_lo,
            Whi + aa, Wlo + aa, ab + (l * 2 + 0) * 256, tr_a, nullptr, NA, 256, 1.0f);
        hmma_bf16<false, false><<<dim3(GP, 2), 512, SMEM_BF>>>(gp_hi, gp_lo,
            Whi + ap, Wlo + ap, ab + (l * 2 + 1) * 256, tr_p, nullptr, NP, 256, 0.5f);

        // skip blend + LN (emits fp32 + fp16 feats)
        ln_blend_kernel<<<(NA + 7) / 8, 256>>>(tr_a, fa[cur], ln_g + (l * 2 + 0) * 256,
            ln_b + (l * 2 + 0) * 256, skip, l * 3 + 0, fa[nxt], fa16, NA);
        ln_blend_kernel<<<(NP + 7) / 8, 256>>>(tr_p, fp[cur], ln_g + (l * 2 + 1) * 256,
            ln_b + (l * 2 + 1) * 256, skip, l * 3 + 1, fp[nxt], fp16p, NP);
    }

    // output projection (fp16 1-term): fp16 paper feats @ out_W + out_b -> fp32
    hmma16<64, false><<<dim3(GP, 1), 512, SMEM16_64>>>(fp16p,
        W16 + (size_t)22 * 65536, out_b, (float*)d_out, nullptr, NP, 64);
}